// round 10
// baseline (speedup 1.0000x reference)
#include <cuda_runtime.h>
#include <cuda_bf16.h>
#include <cstdint>

#define D    256
#define MAXK 2048
#define MAXN 65536

#define COMMIT_COST 0.25f
#define DIV_GAMMA   0.1f
#define EPS_F       1e-8f

typedef unsigned long long ull;
#define UMAX64 0xFFFFFFFFFFFFFFFFULL

// ---------------- device scratch ----------------
__device__ float g_esq[MAXK];
__device__ float g_rninv[MAXK];
__device__ float g_xsq[MAXN];
__device__ float g_sx[MAXN];
__device__ float g_se[MAXK];
__device__ int   g_idx[MAXN];
__device__ int   g_idx2[MAXN];
__device__ float g_counts[MAXK];
__device__ float g_acc[4];

// int8 hi/lo splits (x = sx*(h + l/128))
__device__ unsigned g_xh8[MAXN * D / 4];
__device__ unsigned g_xl8[MAXN * D / 4];
__device__ unsigned g_eh8[MAXK * D / 4];
__device__ unsigned g_el8[MAXK * D / 4];

// bf16 hi/lo splits of e (for k_sim only)
__device__ uint4 g_ehi[MAXK * D / 8];
__device__ uint4 g_elo[MAXK * D / 8];

// ---------------- helpers ----------------
__device__ __forceinline__ uint32_t smem_u32(const void* p) {
    uint32_t a;
    asm("{ .reg .u64 t; cvta.to.shared.u64 t, %1; cvt.u32.u64 %0, t; }" : "=r"(a) : "l"(p));
    return a;
}
__device__ __forceinline__ void ldsm_x4(uint32_t& d0, uint32_t& d1, uint32_t& d2, uint32_t& d3,
                                        uint32_t addr) {
    asm volatile("ldmatrix.sync.aligned.m8n8.x4.shared.b16 {%0,%1,%2,%3}, [%4];"
        : "=r"(d0), "=r"(d1), "=r"(d2), "=r"(d3) : "r"(addr));
}
__device__ __forceinline__ void mma_bf16(float* c, const uint32_t* a, const uint32_t* b) {
    asm volatile(
        "mma.sync.aligned.m16n8k16.row.col.f32.bf16.bf16.f32 "
        "{%0,%1,%2,%3}, {%4,%5,%6,%7}, {%8,%9}, {%0,%1,%2,%3};"
        : "+f"(c[0]), "+f"(c[1]), "+f"(c[2]), "+f"(c[3])
        : "r"(a[0]), "r"(a[1]), "r"(a[2]), "r"(a[3]), "r"(b[0]), "r"(b[1]));
}
__device__ __forceinline__ void mma_s8(int* c, const uint32_t* a, const uint32_t* b) {
    asm volatile(
        "mma.sync.aligned.m16n8k32.row.col.s32.s8.s8.s32 "
        "{%0,%1,%2,%3}, {%4,%5,%6,%7}, {%8,%9}, {%0,%1,%2,%3};"
        : "+r"(c[0]), "+r"(c[1]), "+r"(c[2]), "+r"(c[3])
        : "r"(a[0]), "r"(a[1]), "r"(a[2]), "r"(a[3]), "r"(b[0]), "r"(b[1]));
}
__device__ __forceinline__ void cp16(uint32_t dst, const void* src) {
    asm volatile("{ .reg .u64 g; cvta.to.global.u64 g, %1; "
                 "cp.async.cg.shared.global [%0], [g], 16; }"
                 :: "r"(dst), "l"(src) : "memory");
}
#define CP_COMMIT() asm volatile("cp.async.commit_group;" ::: "memory")
#define CP_WAIT0()  asm volatile("cp.async.wait_group 0;" ::: "memory")

__device__ __forceinline__ uint32_t fold_off(int row, int g) {
    return (uint32_t)((row >> 1) * 128 + (row & 1) * 64 + ((g ^ ((row >> 1) & 3)) << 4));
}
// top-2 update
__device__ __forceinline__ void upd2(ull& b1, ull& b2, ull c) {
    if (c < b1) { b2 = b1; b1 = c; }
    else if (c < b2) { b2 = c; }
}

// ---------------- k_init ----------------
__global__ void k_init(int K) {
    int i = blockIdx.x * blockDim.x + threadIdx.x;
    if (i < K) g_counts[i] = 0.f;
    if (i < 4) g_acc[i] = 0.f;
}

// ---------------- int8 quantization helpers ----------------
__device__ __forceinline__ void quant1(float x, float inv, int& h, int& l) {
    float v = x * inv;
    float hf = rintf(v);
    float lf = rintf((v - hf) * 128.0f);
    h = (int)hf; l = (int)lf;
}
__device__ __forceinline__ unsigned pack4(int b0, int b1, int b2, int b3) {
    return (unsigned)(b0 & 0xFF) | ((unsigned)(b1 & 0xFF) << 8) |
           ((unsigned)(b2 & 0xFF) << 16) | ((unsigned)(b3 & 0xFF) << 24);
}
__device__ __forceinline__ void quant4(float4 v, float inv, unsigned& hp, unsigned& lp) {
    int h0,h1,h2,h3,l0,l1,l2,l3;
    quant1(v.x, inv, h0, l0); quant1(v.y, inv, h1, l1);
    quant1(v.z, inv, h2, l2); quant1(v.w, inv, h3, l3);
    hp = pack4(h0,h1,h2,h3); lp = pack4(l0,l1,l2,l3);
}

// ---------------- k_prep_x ----------------
__global__ void k_prep_x(const float* __restrict__ x, int N) {
    int w    = (blockIdx.x * blockDim.x + threadIdx.x) >> 5;
    int lane = threadIdx.x & 31;
    if (w >= N) return;
    const float4* xr = reinterpret_cast<const float4*>(x + (size_t)w * D);
    float4 a = xr[lane], b = xr[32 + lane];
    float s = __fadd_rn(
        __fadd_rn(__fadd_rn(__fmul_rn(a.x,a.x), __fmul_rn(a.y,a.y)),
                  __fadd_rn(__fmul_rn(a.z,a.z), __fmul_rn(a.w,a.w))),
        __fadd_rn(__fadd_rn(__fmul_rn(b.x,b.x), __fmul_rn(b.y,b.y)),
                  __fadd_rn(__fmul_rn(b.z,b.z), __fmul_rn(b.w,b.w))));
    float mx = fmaxf(fmaxf(fmaxf(fabsf(a.x),fabsf(a.y)), fmaxf(fabsf(a.z),fabsf(a.w))),
                     fmaxf(fmaxf(fabsf(b.x),fabsf(b.y)), fmaxf(fabsf(b.z),fabsf(b.w))));
#pragma unroll
    for (int off = 16; off > 0; off >>= 1) {
        s += __shfl_xor_sync(0xffffffffu, s, off);
        mx = fmaxf(mx, __shfl_xor_sync(0xffffffffu, mx, off));
    }
    mx = fmaxf(mx, 1e-20f);
    float inv = 127.0f / mx;
    unsigned hpa, lpa, hpb, lpb;
    quant4(a, inv, hpa, lpa);
    quant4(b, inv, hpb, lpb);
    g_xh8[w * 64 + lane]      = hpa;
    g_xh8[w * 64 + 32 + lane] = hpb;
    g_xl8[w * 64 + lane]      = lpa;
    g_xl8[w * 64 + 32 + lane] = lpb;
    if (lane == 0) {
        g_xsq[w] = s;
        g_sx[w]  = mx * (1.0f / 127.0f);
    }
}

// ---------------- k_prep_e ----------------
__global__ void k_prep_e(const float* __restrict__ e, int K) {
    int w    = (blockIdx.x * blockDim.x + threadIdx.x) >> 5;
    int lane = threadIdx.x & 31;
    if (w >= K) return;
    const float4* er = reinterpret_cast<const float4*>(e + (size_t)w * D);
    float4 a = er[lane], b = er[32 + lane];
    float s = __fadd_rn(
        __fadd_rn(__fadd_rn(__fmul_rn(a.x,a.x), __fmul_rn(a.y,a.y)),
                  __fadd_rn(__fmul_rn(a.z,a.z), __fmul_rn(a.w,a.w))),
        __fadd_rn(__fadd_rn(__fmul_rn(b.x,b.x), __fmul_rn(b.y,b.y)),
                  __fadd_rn(__fmul_rn(b.z,b.z), __fmul_rn(b.w,b.w))));
    float mx = fmaxf(fmaxf(fmaxf(fabsf(a.x),fabsf(a.y)), fmaxf(fabsf(a.z),fabsf(a.w))),
                     fmaxf(fmaxf(fabsf(b.x),fabsf(b.y)), fmaxf(fabsf(b.z),fabsf(b.w))));
#pragma unroll
    for (int off = 16; off > 0; off >>= 1) {
        s += __shfl_xor_sync(0xffffffffu, s, off);
        mx = fmaxf(mx, __shfl_xor_sync(0xffffffffu, mx, off));
    }
    mx = fmaxf(mx, 1e-20f);
    float inv = 127.0f / mx;
    unsigned hpa, lpa, hpb, lpb;
    quant4(a, inv, hpa, lpa);
    quant4(b, inv, hpb, lpb);
    g_eh8[w * 64 + lane]      = hpa;
    g_eh8[w * 64 + 32 + lane] = hpb;
    g_el8[w * 64 + lane]      = lpa;
    g_el8[w * 64 + 32 + lane] = lpb;
    if (lane == 0) {
        g_esq[w] = s;
        g_se[w]  = mx * (1.0f / 127.0f);
        float rn = sqrtf(s);
        g_rninv[w] = 1.0f / fmaxf(rn, 1e-12f);
        atomicAdd(&g_acc[2], rn);
    }
}

// ---------------- k_split_e (bf16 for k_sim) ----------------
__device__ __forceinline__ void split8(const float* f, uint4& hh, uint4& ll) {
    unsigned h[8], l[8];
#pragma unroll
    for (int j = 0; j < 8; j++) {
        __nv_bfloat16 hb = __float2bfloat16(f[j]);
        float hf = __bfloat162float(hb);
        __nv_bfloat16 lb = __float2bfloat16(f[j] - hf);
        h[j] = __bfloat16_as_ushort(hb);
        l[j] = __bfloat16_as_ushort(lb);
    }
    hh = make_uint4(h[0] | (h[1] << 16), h[2] | (h[3] << 16),
                    h[4] | (h[5] << 16), h[6] | (h[7] << 16));
    ll = make_uint4(l[0] | (l[1] << 16), l[2] | (l[3] << 16),
                    l[4] | (l[5] << 16), l[6] | (l[7] << 16));
}
__global__ void k_split_e(const float4* __restrict__ src, int n8) {
    int i = blockIdx.x * blockDim.x + threadIdx.x;
    if (i >= n8) return;
    float4 v0 = src[2 * i], v1 = src[2 * i + 1];
    float f[8] = {v0.x, v0.y, v0.z, v0.w, v1.x, v1.y, v1.z, v1.w};
    uint4 hh, ll; split8(f, hh, ll);
    g_ehi[i] = hh; g_elo[i] = ll;
}

// ================= k_argmin_i8: 64x128 CTA, 32x32 warp tiles, int8x3 + top-2 =================
#define STG3     24576
#define S3_AH    0
#define S3_AL    4096
#define S3_BH    8192
#define S3_BL    16384
#define OFF_B3   (2 * STG3)
#define SMEM_A3  (2 * STG3 + 2048)

__device__ __forceinline__ void stage_load3(uint32_t sb, int abase, int bbase, int tid) {
    const uint4* xh4 = reinterpret_cast<const uint4*>(g_xh8);
    const uint4* xl4 = reinterpret_cast<const uint4*>(g_xl8);
    const uint4* eh4 = reinterpret_cast<const uint4*>(g_eh8);
    const uint4* el4 = reinterpret_cast<const uint4*>(g_el8);
    {
        int row = tid >> 2, g = tid & 3;
        uint32_t so = fold_off(row, g);
        int fa = abase + row * 16 + g;
        cp16(sb + S3_AH + so, xh4 + fa);
        cp16(sb + S3_AL + so, xl4 + fa);
    }
#pragma unroll
    for (int rep = 0; rep < 2; rep++) {
        int id  = tid + rep * 256;
        int row = id >> 2, g = id & 3;
        uint32_t so = fold_off(row, g);
        int fb = bbase + row * 16 + g;
        cp16(sb + S3_BH + so, eh4 + fb);
        cp16(sb + S3_BL + so, el4 + fb);
    }
}

__global__ void __launch_bounds__(256, 2)
k_argmin_i8(int N, int K) {
    extern __shared__ char dsm[];
    uint32_t smb = smem_u32(dsm);
    int tid  = threadIdx.x;
    int lane = tid & 31;
    int wid  = tid >> 5;
    int wm   = wid >> 2;
    int wn   = wid & 3;
    int m0   = blockIdx.x * 64;

    int aoff[2], akey[2];
#pragma unroll
    for (int ma = 0; ma < 2; ma++) {
        int row = wm * 32 + ma * 16 + ((lane >> 3) & 1) * 8 + (lane & 7);
        aoff[ma] = (row >> 1) * 128 + (row & 1) * 64;
        akey[ma] = (row >> 1) & 3;
    }
    int boff[2], bkey[2];
#pragma unroll
    for (int pr = 0; pr < 2; pr++) {
        int row = wn * 32 + pr * 16 + ((lane >> 4) & 1) * 8 + (lane & 7);
        boff[pr] = (row >> 1) * 128 + (row & 1) * 64;
        bkey[pr] = (row >> 1) & 3;
    }
    int asub = lane >> 4;
    int bsub = (lane >> 3) & 1;

    ull tb1[4], tb2[4];
#pragma unroll
    for (int i = 0; i < 4; i++) { tb1[i] = UMAX64; tb2[i] = UMAX64; }

    int C = (K / 128) * 4;   // chunks of k64

    stage_load3(smb, m0 * 16, 0, tid);
    CP_COMMIT();

    int hh[2][4][4], cr[2][4][4];
#pragma unroll
    for (int ma = 0; ma < 2; ma++)
#pragma unroll
        for (int na = 0; na < 4; na++)
#pragma unroll
            for (int q = 0; q < 4; q++) { hh[ma][na][q] = 0; cr[ma][na][q] = 0; }

#pragma unroll 1
    for (int c = 0; c < C; c++) {
        int nt = c >> 2, dc = c & 3;
        uint32_t sb = smb + (c & 1) * STG3;

        CP_WAIT0();
        __syncthreads();

        if (c + 1 < C) {
            int nt1 = (c + 1) >> 2, dc1 = (c + 1) & 3;
            stage_load3(smb + ((c + 1) & 1) * STG3,
                        m0 * 16 + dc1 * 4, nt1 * 128 * 16 + dc1 * 4, tid);
            CP_COMMIT();
        } else {
            CP_COMMIT();
        }

#pragma unroll
        for (int slice = 0; slice < 2; slice++) {
            int ga = slice * 2 + asub;
            int gb = slice * 2 + bsub;
            uint32_t ah[2][4], al[2][4], bb[4][2];
#pragma unroll
            for (int ma = 0; ma < 2; ma++)
                ldsm_x4(ah[ma][0], ah[ma][1], ah[ma][2], ah[ma][3],
                        sb + S3_AH + aoff[ma] + (((ga ^ akey[ma]) & 3) << 4));
#pragma unroll
            for (int pr = 0; pr < 2; pr++) {
                uint32_t d0, d1, d2, d3;
                ldsm_x4(d0, d1, d2, d3,
                        sb + S3_BH + boff[pr] + (((gb ^ bkey[pr]) & 3) << 4));
                bb[2*pr][0] = d0; bb[2*pr][1] = d1;
                bb[2*pr+1][0] = d2; bb[2*pr+1][1] = d3;
            }
#pragma unroll
            for (int ma = 0; ma < 2; ma++)
#pragma unroll
                for (int na = 0; na < 4; na++)
                    mma_s8(hh[ma][na], ah[ma], bb[na]);
#pragma unroll
            for (int ma = 0; ma < 2; ma++)
                ldsm_x4(al[ma][0], al[ma][1], al[ma][2], al[ma][3],
                        sb + S3_AL + aoff[ma] + (((ga ^ akey[ma]) & 3) << 4));
#pragma unroll
            for (int ma = 0; ma < 2; ma++)
#pragma unroll
                for (int na = 0; na < 4; na++)
                    mma_s8(cr[ma][na], al[ma], bb[na]);
#pragma unroll
            for (int pr = 0; pr < 2; pr++) {
                uint32_t d0, d1, d2, d3;
                ldsm_x4(d0, d1, d2, d3,
                        sb + S3_BL + boff[pr] + (((gb ^ bkey[pr]) & 3) << 4));
                bb[2*pr][0] = d0; bb[2*pr][1] = d1;
                bb[2*pr+1][0] = d2; bb[2*pr+1][1] = d3;
            }
#pragma unroll
            for (int ma = 0; ma < 2; ma++)
#pragma unroll
                for (int na = 0; na < 4; na++)
                    mma_s8(cr[ma][na], ah[ma], bb[na]);
        }

        if (dc == 3) {
#pragma unroll
            for (int ma = 0; ma < 2; ma++) {
                int m_r = m0 + wm * 32 + ma * 16 + (lane >> 2);
                float xq0 = g_xsq[m_r],     sx0 = g_sx[m_r];
                float xq1 = g_xsq[m_r + 8], sx1 = g_sx[m_r + 8];
#pragma unroll
                for (int na = 0; na < 4; na++) {
                    int n0c = nt * 128 + wn * 32 + na * 8 + 2 * (lane & 3);
                    float se0 = g_se[n0c], se1 = g_se[n0c + 1];
                    float e0 = g_esq[n0c], e1 = g_esq[n0c + 1];
                    float S00 = (float)hh[ma][na][0] + (float)cr[ma][na][0] * 0.0078125f;
                    float S01 = (float)hh[ma][na][1] + (float)cr[ma][na][1] * 0.0078125f;
                    float S10 = (float)hh[ma][na][2] + (float)cr[ma][na][2] * 0.0078125f;
                    float S11 = (float)hh[ma][na][3] + (float)cr[ma][na][3] * 0.0078125f;
                    float d00 = __fsub_rn(__fadd_rn(xq0, e0), 2.0f * (sx0 * se0 * S00));
                    float d01 = __fsub_rn(__fadd_rn(xq0, e1), 2.0f * (sx0 * se1 * S01));
                    float d10 = __fsub_rn(__fadd_rn(xq1, e0), 2.0f * (sx1 * se0 * S10));
                    float d11 = __fsub_rn(__fadd_rn(xq1, e1), 2.0f * (sx1 * se1 * S11));
                    upd2(tb1[ma * 2],     tb2[ma * 2],
                         ((ull)__float_as_uint(d00) << 32) | (unsigned)n0c);
                    upd2(tb1[ma * 2],     tb2[ma * 2],
                         ((ull)__float_as_uint(d01) << 32) | (unsigned)(n0c + 1));
                    upd2(tb1[ma * 2 + 1], tb2[ma * 2 + 1],
                         ((ull)__float_as_uint(d10) << 32) | (unsigned)n0c);
                    upd2(tb1[ma * 2 + 1], tb2[ma * 2 + 1],
                         ((ull)__float_as_uint(d11) << 32) | (unsigned)(n0c + 1));
#pragma unroll
                    for (int q = 0; q < 4; q++) { hh[ma][na][q] = 0; cr[ma][na][q] = 0; }
                }
            }
        }
    }

    // cross-thread top-2 combine
    ull* best  = reinterpret_cast<ull*>(dsm + OFF_B3);
    ull* best2 = best + 64;
    __syncthreads();
    if (tid < 64) { best[tid] = UMAX64; best2[tid] = UMAX64; }
    __syncthreads();
#pragma unroll
    for (int ma = 0; ma < 2; ma++) {
        int mloc = wm * 32 + ma * 16 + (lane >> 2);
        atomicMin(&best[mloc],     tb1[ma * 2]);
        atomicMin(&best[mloc + 8], tb1[ma * 2 + 1]);
    }
    __syncthreads();
#pragma unroll
    for (int ma = 0; ma < 2; ma++) {
        int mloc = wm * 32 + ma * 16 + (lane >> 2);
        ull g0 = best[mloc];
        ull g1 = best[mloc + 8];
        atomicMin(&best2[mloc],     (tb1[ma * 2]     == g0) ? tb2[ma * 2]     : tb1[ma * 2]);
        atomicMin(&best2[mloc + 8], (tb1[ma * 2 + 1] == g1) ? tb2[ma * 2 + 1] : tb1[ma * 2 + 1]);
    }
    __syncthreads();
    if (tid < 64) {
        g_idx [m0 + tid] = (int)(best [tid] & 0xFFFFFFFFu);
        g_idx2[m0 + tid] = (int)(best2[tid] & 0xFFFFFFFFu);
    }
}

// ---------------- k_refine: exact fp32 rescore of the int8 top-2 ----------------
__global__ void __launch_bounds__(256)
k_refine(const float* __restrict__ x, const float* __restrict__ e, int N) {
    int w    = (blockIdx.x * blockDim.x + threadIdx.x) >> 5;
    int lane = threadIdx.x & 31;
    if (w >= N) return;
    int i1 = g_idx[w], i2 = g_idx2[w];
    const float4* xr = reinterpret_cast<const float4*>(x + (size_t)w * D);
    const float4* p1 = reinterpret_cast<const float4*>(e + (size_t)i1 * D);
    const float4* p2 = reinterpret_cast<const float4*>(e + (size_t)i2 * D);
    float4 a = xr[lane], b = xr[32 + lane];
    float4 u = p1[lane], v = p1[32 + lane];
    float4 r = p2[lane], t = p2[32 + lane];
    float d1 = a.x*u.x + a.y*u.y + a.z*u.z + a.w*u.w
             + b.x*v.x + b.y*v.y + b.z*v.z + b.w*v.w;
    float d2 = a.x*r.x + a.y*r.y + a.z*r.z + a.w*r.w
             + b.x*t.x + b.y*t.y + b.z*t.z + b.w*t.w;
#pragma unroll
    for (int off = 16; off > 0; off >>= 1) {
        d1 += __shfl_xor_sync(0xffffffffu, d1, off);
        d2 += __shfl_xor_sync(0xffffffffu, d2, off);
    }
    if (lane == 0) {
        float xq = g_xsq[w];
        float dist1 = __fsub_rn(__fadd_rn(xq, g_esq[i1]), 2.0f * d1);
        float dist2 = __fsub_rn(__fadd_rn(xq, g_esq[i2]), 2.0f * d2);
        ull c1 = ((ull)__float_as_uint(dist1) << 32) | (unsigned)i1;
        ull c2 = ((ull)__float_as_uint(dist2) << 32) | (unsigned)i2;
        g_idx[w] = (int)(((c1 < c2) ? c1 : c2) & 0xFFFFFFFFu);
    }
}

// ================= k_sim (bf16x3, round-7 proven) =================
#define STG_SZ   32768
#define S_AHI    0
#define S_ALO    8192
#define S_BHI    16384
#define S_BLO    24576
#define OFF_AUX  65536
#define SMEM_SIM (65536 + 2048)

__device__ __forceinline__ void stage_load_sim(uint32_t sb,
                                               int abase_g, int bbase_g, int tid) {
#pragma unroll
    for (int rep = 0; rep < 2; rep++) {
        int id  = tid + rep * 256;
        int row = id >> 2, g = id & 3;
        uint32_t so = fold_off(row, g);
        int fa = abase_g + row * 32 + g;
        int fb = bbase_g + row * 32 + g;
        cp16(sb + S_AHI + so, g_ehi + fa);
        cp16(sb + S_ALO + so, g_elo + fa);
        cp16(sb + S_BHI + so, g_ehi + fb);
        cp16(sb + S_BLO + so, g_elo + fb);
    }
}

struct Frag {
    int aoff[4], akey[4], boff[2], bkey[2];
    int asub, bsub;
};
__device__ __forceinline__ void frag_init(Frag& f, int lane, int wm, int wn) {
    f.asub = lane >> 4;
    f.bsub = (lane >> 3) & 1;
#pragma unroll
    for (int ma = 0; ma < 4; ma++) {
        int row = wm * 64 + ma * 16 + ((lane >> 3) & 1) * 8 + (lane & 7);
        f.aoff[ma] = (row >> 1) * 128 + (row & 1) * 64;
        f.akey[ma] = (row >> 1) & 3;
    }
#pragma unroll
    for (int pr = 0; pr < 2; pr++) {
        int row = wn * 32 + pr * 16 + ((lane >> 4) & 1) * 8 + (lane & 7);
        f.boff[pr] = (row >> 1) * 128 + (row & 1) * 64;
        f.bkey[pr] = (row >> 1) & 3;
    }
}

__device__ __forceinline__ void chunk_compute_sim(uint32_t sb, const Frag& f,
                                                  float acc[4][4][4]) {
#pragma unroll
    for (int ks = 0; ks < 2; ks++) {
        int ga = ks * 2 + f.asub;
        int gb = ks * 2 + f.bsub;
        uint32_t ah[4][4], al[4][4], bh[4][2], bl[4][2];
#pragma unroll
        for (int ma = 0; ma < 4; ma++)
            ldsm_x4(ah[ma][0], ah[ma][1], ah[ma][2], ah[ma][3],
                    sb + S_AHI + f.aoff[ma] + (((ga ^ f.akey[ma]) & 3) << 4));
#pragma unroll
        for (int pr = 0; pr < 2; pr++) {
            uint32_t d0, d1, d2, d3;
            ldsm_x4(d0, d1, d2, d3,
                    sb + S_BHI + f.boff[pr] + (((gb ^ f.bkey[pr]) & 3) << 4));
            bh[2*pr][0] = d0; bh[2*pr][1] = d1;
            bh[2*pr+1][0] = d2; bh[2*pr+1][1] = d3;
        }
#pragma unroll
        for (int ma = 0; ma < 4; ma++)
#pragma unroll
            for (int na = 0; na < 4; na++)
                mma_bf16(acc[ma][na], ah[ma], bh[na]);
#pragma unroll
        for (int pr = 0; pr < 2; pr++) {
            uint32_t d0, d1, d2, d3;
            ldsm_x4(d0, d1, d2, d3,
                    sb + S_BLO + f.boff[pr] + (((gb ^ f.bkey[pr]) & 3) << 4));
            bl[2*pr][0] = d0; bl[2*pr][1] = d1;
            bl[2*pr+1][0] = d2; bl[2*pr+1][1] = d3;
        }
#pragma unroll
        for (int ma = 0; ma < 4; ma++)
#pragma unroll
            for (int na = 0; na < 4; na++)
                mma_bf16(acc[ma][na], ah[ma], bl[na]);
#pragma unroll
        for (int ma = 0; ma < 4; ma++)
            ldsm_x4(al[ma][0], al[ma][1], al[ma][2], al[ma][3],
                    sb + S_ALO + f.aoff[ma] + (((ga ^ f.akey[ma]) & 3) << 4));
#pragma unroll
        for (int ma = 0; ma < 4; ma++)
#pragma unroll
            for (int na = 0; na < 4; na++)
                mma_bf16(acc[ma][na], al[ma], bh[na]);
    }
}

__global__ void __launch_bounds__(256, 2)
k_sim_mma(int K) {
    extern __shared__ char dsm[];
    uint32_t smb = smem_u32(dsm);
    int tid  = threadIdx.x;
    int lane = tid & 31;
    int wid  = tid >> 5;
    int wm   = wid >> 2;
    int wn   = wid & 3;

    int nt_blocks = K / 128;
    int b = blockIdx.x, by = 0;
    while (b >= nt_blocks - by) { b -= nt_blocks - by; by++; }
    int bx = by + b;
    int m0 = by * 128, n0 = bx * 128;
    float wgt = (by == bx) ? 1.0f : 2.0f;

    Frag f; frag_init(f, lane, wm, wn);

    float acc[4][4][4];
#pragma unroll
    for (int ma = 0; ma < 4; ma++)
#pragma unroll
        for (int na = 0; na < 4; na++)
#pragma unroll
            for (int c = 0; c < 4; c++) acc[ma][na][c] = 0.f;

    stage_load_sim(smb, m0 * 32, n0 * 32, tid);
    CP_COMMIT();

#pragma unroll 1
    for (int dc = 0; dc < 8; dc++) {
        uint32_t sb = smb + (dc & 1) * STG_SZ;
        CP_WAIT0();
        __syncthreads();
        if (dc + 1 < 8) {
            stage_load_sim(smb + ((dc + 1) & 1) * STG_SZ,
                           m0 * 32 + (dc + 1) * 4, n0 * 32 + (dc + 1) * 4, tid);
            CP_COMMIT();
        } else {
            CP_COMMIT();
        }
        chunk_compute_sim(sb, f, acc);
    }

    float s = 0.f;
#pragma unroll
    for (int ma = 0; ma < 4; ma++) {
        int m_r0 = m0 + wm * 64 + ma * 16 + (lane >> 2);
        float r0 = g_rninv[m_r0], r1 = g_rninv[m_r0 + 8];
#pragma unroll
        for (int na = 0; na < 4; na++) {
            int n0c = n0 + wn * 32 + na * 8 + 2 * (lane & 3);
            float q0 = g_rninv[n0c], q1 = g_rninv[n0c + 1];
            float s00 = fabsf(acc[ma][na][0] * r0 * q0);
            float s01 = fabsf(acc[ma][na][1] * r0 * q1);
            float s10 = fabsf(acc[ma][na][2] * r1 * q0);
            float s11 = fabsf(acc[ma][na][3] * r1 * q1);
            if (m_r0     == n0c)     s00 = 0.f;
            if (m_r0     == n0c + 1) s01 = 0.f;
            if (m_r0 + 8 == n0c)     s10 = 0.f;
            if (m_r0 + 8 == n0c + 1) s11 = 0.f;
            s += (s00 + s01) + (s10 + s11);
        }
    }
    s *= wgt;

    float* red = reinterpret_cast<float*>(dsm + OFF_AUX);
    __syncthreads();
    red[tid] = s; __syncthreads();
    for (int st = 128; st > 0; st >>= 1) { if (tid < st) red[tid] += red[tid + st]; __syncthreads(); }
    if (tid == 0) atomicAdd(&g_acc[1], red[0]);
}

// ---------------- k_gather ----------------
__global__ void __launch_bounds__(256)
k_gather(const float* __restrict__ x, const float* __restrict__ e,
         float* __restrict__ outq, float* __restrict__ outidx, int N) {
    __shared__ float red[256];
    int tid = threadIdx.x;
    int t   = blockIdx.x * 16 + (tid >> 4);
    int seg = tid & 15;
    int k = g_idx[t];
    const float4* er = reinterpret_cast<const float4*>(e + (size_t)k * D);
    const float4* xr = reinterpret_cast<const float4*>(x + (size_t)t * D);
    float4* qr = reinterpret_cast<float4*>(outq + (size_t)t * D);
    float s = 0.f;
#pragma unroll
    for (int j = 0; j < 4; j++) {
        int c = seg + j * 16;
        float4 q = er[c], xv = xr[c];
        qr[c] = q;
        float dx = q.x - xv.x, dy = q.y - xv.y, dz = q.z - xv.z, dw = q.w - xv.w;
        s += (dx * dx + dy * dy) + (dz * dz + dw * dw);
    }
    red[tid] = s; __syncthreads();
    for (int st = 128; st > 0; st >>= 1) { if (tid < st) red[tid] += red[tid + st]; __syncthreads(); }
    if (tid == 0) atomicAdd(&g_acc[0], red[0]);
    if (seg == 0) {
        outidx[t] = (float)k;
        atomicAdd(&g_counts[k], 1.0f);
    }
}

// ---------------- k_final ----------------
__global__ void k_final(float* __restrict__ out_loss, float* __restrict__ out_perp, int N, int K) {
    __shared__ float sA[256], sB[256], sC[256];
    int tid = threadIdx.x;

    float tot = 0.f;
    for (int k = tid; k < K; k += 256) tot += g_counts[k];
    sA[tid] = tot; __syncthreads();
    for (int st = 128; st > 0; st >>= 1) { if (tid < st) sA[tid] += sA[tid + st]; __syncthreads(); }
    float total = sA[0];
    __syncthreads();

    float tuni = 1.0f / (float)K;
    float kl = 0.f, pl = 0.f;
    for (int k = tid; k < K; k += 256) {
        float p = g_counts[k] / total;
        kl += (p + EPS_F) * logf((p + EPS_F) / (tuni + EPS_F));
        if (p > 0.f) pl += p * logf(p);
    }
    sB[tid] = kl; sC[tid] = pl; __syncthreads();
    for (int st = 128; st > 0; st >>= 1) {
        if (tid < st) { sB[tid] += sB[tid + st]; sC[tid] += sC[tid + st]; }
        __syncthreads();
    }
    if (tid == 0) {
        float klv = fminf(sB[0], 100.0f);
        float mse = g_acc[0] / ((float)N * (float)D);
        float vq  = mse + COMMIT_COST * mse;
        float l2  = fminf(g_acc[2] / (float)K, 10.0f);
        float orth = fminf(g_acc[1] / ((float)K * (float)K), 10.0f);
        float reg = l2 + orth;
        float loss = fminf(vq + DIV_GAMMA * klv + 0.01f * reg, 100.0f);
        *out_loss = loss;
        *out_perp = expf(-sC[0]);
    }
}

// ---------------- launch ----------------
extern "C" void kernel_launch(void* const* d_in, const int* in_sizes, int n_in,
                              void* d_out, int out_size) {
    const float* x = (const float*)d_in[0];
    const float* e = (const float*)d_in[1];
    float* out = (float*)d_out;

    int N = in_sizes[0] / D;   // 65536
    int K = in_sizes[1] / D;   // 2048
    if (N > MAXN) N = MAXN;
    if (K > MAXK) K = MAXK;

    float* out_q    = out;
    float* out_loss = out + (size_t)N * D;
    float* out_perp = out_loss + 1;
    float* out_idx  = out_perp + 1;

    cudaFuncSetAttribute(k_argmin_i8, cudaFuncAttributeMaxDynamicSharedMemorySize, SMEM_A3);
    cudaFuncSetAttribute(k_sim_mma,   cudaFuncAttributeMaxDynamicSharedMemorySize, SMEM_SIM);

    int ne8 = K * (D / 8);
    int ntb = K / 128;
    int tri = ntb * (ntb + 1) / 2;

    k_init     <<<(K + 255) / 256, 256>>>(K);
    k_prep_e   <<<(K + 7) / 8, 256>>>(e, K);
    k_split_e  <<<(ne8 + 255) / 256, 256>>>((const float4*)e, ne8);
    k_prep_x   <<<(N + 7) / 8, 256>>>(x, N);
    k_argmin_i8<<<N / 64, 256, SMEM_A3>>>(N, K);
    k_refine   <<<(N + 7) / 8, 256>>>(x, e, N);
    k_gather   <<<N / 16, 256>>>(x, e, out_q, out_idx, N);
    k_sim_mma  <<<tri, 256, SMEM_SIM>>>(K);
    k_final    <<<1, 256>>>(out_loss, out_perp, N, K);
}

// round 11
// speedup vs baseline: 2.6084x; 2.6084x over previous
#include <cuda_runtime.h>
#include <cuda_bf16.h>
#include <cstdint>

#define D    256
#define MAXK 2048
#define MAXN 65536

#define COMMIT_COST 0.25f
#define DIV_GAMMA   0.1f
#define EPS_F       1e-8f

typedef unsigned long long ull;
#define UMAX64 0xFFFFFFFFFFFFFFFFULL

// ---------------- device scratch ----------------
__device__ float g_esq[MAXK];
__device__ float g_rninv[MAXK];
__device__ float g_xsq[MAXN];
__device__ int   g_idx[MAXN];
__device__ int   g_cand[4 * MAXN];
__device__ float g_counts[MAXK];
__device__ float g_acc[4];

// bf16 hi/lo splits (16B granules of 8 bf16)
__device__ uint4 g_xhi[MAXN * D / 8];
__device__ uint4 g_xlo[MAXN * D / 8];
__device__ uint4 g_ehi[MAXK * D / 8];
__device__ uint4 g_elo[MAXK * D / 8];

// ---------------- helpers ----------------
__device__ __forceinline__ uint32_t smem_u32(const void* p) {
    uint32_t a;
    asm("{ .reg .u64 t; cvta.to.shared.u64 t, %1; cvt.u32.u64 %0, t; }" : "=r"(a) : "l"(p));
    return a;
}
__device__ __forceinline__ void ldsm_x4(uint32_t& d0, uint32_t& d1, uint32_t& d2, uint32_t& d3,
                                        uint32_t addr) {
    asm volatile("ldmatrix.sync.aligned.m8n8.x4.shared.b16 {%0,%1,%2,%3}, [%4];"
        : "=r"(d0), "=r"(d1), "=r"(d2), "=r"(d3) : "r"(addr));
}
__device__ __forceinline__ void mma_bf16(float* c, const uint32_t* a, const uint32_t* b) {
    asm volatile(
        "mma.sync.aligned.m16n8k16.row.col.f32.bf16.bf16.f32 "
        "{%0,%1,%2,%3}, {%4,%5,%6,%7}, {%8,%9}, {%0,%1,%2,%3};"
        : "+f"(c[0]), "+f"(c[1]), "+f"(c[2]), "+f"(c[3])
        : "r"(a[0]), "r"(a[1]), "r"(a[2]), "r"(a[3]), "r"(b[0]), "r"(b[1]));
}
__device__ __forceinline__ void cp16(uint32_t dst, const void* src) {
    asm volatile("{ .reg .u64 g; cvta.to.global.u64 g, %1; "
                 "cp.async.cg.shared.global [%0], [g], 16; }"
                 :: "r"(dst), "l"(src) : "memory");
}
#define CP_COMMIT() asm volatile("cp.async.commit_group;" ::: "memory")
#define CP_WAIT0()  asm volatile("cp.async.wait_group 0;" ::: "memory")

__device__ __forceinline__ uint32_t fold_off(int row, int g) {
    return (uint32_t)((row >> 1) * 128 + (row & 1) * 64 + ((g ^ ((row >> 1) & 3)) << 4));
}
__device__ __forceinline__ void upd2(ull& b1, ull& b2, ull c) {
    if (c < b1) { b2 = b1; b1 = c; }
    else if (c < b2) { b2 = c; }
}

// ---------------- k_init ----------------
__global__ void k_init(int K) {
    int i = blockIdx.x * blockDim.x + threadIdx.x;
    if (i < K) g_counts[i] = 0.f;
    if (i < 4) g_acc[i] = 0.f;
}

// ---------------- k_prep (e): esq, rninv, rn-sum ----------------
__global__ void k_prep(const float* __restrict__ e, int K) {
    int w    = (blockIdx.x * blockDim.x + threadIdx.x) >> 5;
    int lane = threadIdx.x & 31;
    if (w >= K) return;
    const float4* er = reinterpret_cast<const float4*>(e + (size_t)w * D);
    float4 a = er[lane], b = er[32 + lane];
    float s = __fadd_rn(
        __fadd_rn(__fadd_rn(__fmul_rn(a.x,a.x), __fmul_rn(a.y,a.y)),
                  __fadd_rn(__fmul_rn(a.z,a.z), __fmul_rn(a.w,a.w))),
        __fadd_rn(__fadd_rn(__fmul_rn(b.x,b.x), __fmul_rn(b.y,b.y)),
                  __fadd_rn(__fmul_rn(b.z,b.z), __fmul_rn(b.w,b.w))));
#pragma unroll
    for (int off = 16; off > 0; off >>= 1) s += __shfl_xor_sync(0xffffffffu, s, off);
    if (lane == 0) {
        g_esq[w] = s;
        float rn = sqrtf(s);
        g_rninv[w] = 1.0f / fmaxf(rn, 1e-12f);
        atomicAdd(&g_acc[2], rn);
    }
}

// ---------------- k_xsq ----------------
__global__ void k_xsq(const float* __restrict__ x, int N) {
    int w    = (blockIdx.x * blockDim.x + threadIdx.x) >> 5;
    int lane = threadIdx.x & 31;
    if (w >= N) return;
    const float4* xr = reinterpret_cast<const float4*>(x + (size_t)w * D);
    float4 a = xr[lane], b = xr[32 + lane];
    float s = __fadd_rn(
        __fadd_rn(__fadd_rn(__fmul_rn(a.x,a.x), __fmul_rn(a.y,a.y)),
                  __fadd_rn(__fmul_rn(a.z,a.z), __fmul_rn(a.w,a.w))),
        __fadd_rn(__fadd_rn(__fmul_rn(b.x,b.x), __fmul_rn(b.y,b.y)),
                  __fadd_rn(__fmul_rn(b.z,b.z), __fmul_rn(b.w,b.w))));
#pragma unroll
    for (int off = 16; off > 0; off >>= 1) s += __shfl_xor_sync(0xffffffffu, s, off);
    if (lane == 0) g_xsq[w] = s;
}

// ---------------- k_split: bf16 hi/lo ----------------
__device__ __forceinline__ void split8(const float* f, uint4& hh, uint4& ll) {
    unsigned h[8], l[8];
#pragma unroll
    for (int j = 0; j < 8; j++) {
        __nv_bfloat16 hb = __float2bfloat16(f[j]);
        float hf = __bfloat162float(hb);
        __nv_bfloat16 lb = __float2bfloat16(f[j] - hf);
        h[j] = __bfloat16_as_ushort(hb);
        l[j] = __bfloat16_as_ushort(lb);
    }
    hh = make_uint4(h[0] | (h[1] << 16), h[2] | (h[3] << 16),
                    h[4] | (h[5] << 16), h[6] | (h[7] << 16));
    ll = make_uint4(l[0] | (l[1] << 16), l[2] | (l[3] << 16),
                    l[4] | (l[5] << 16), l[6] | (l[7] << 16));
}
__global__ void k_split_x(const float4* __restrict__ src, int n8) {
    int i = blockIdx.x * blockDim.x + threadIdx.x;
    if (i >= n8) return;
    float4 v0 = src[2 * i], v1 = src[2 * i + 1];
    float f[8] = {v0.x, v0.y, v0.z, v0.w, v1.x, v1.y, v1.z, v1.w};
    uint4 hh, ll; split8(f, hh, ll);
    g_xhi[i] = hh; g_xlo[i] = ll;
}
__global__ void k_split_e(const float4* __restrict__ src, int n8) {
    int i = blockIdx.x * blockDim.x + threadIdx.x;
    if (i >= n8) return;
    float4 v0 = src[2 * i], v1 = src[2 * i + 1];
    float f[8] = {v0.x, v0.y, v0.z, v0.w, v1.x, v1.y, v1.z, v1.w};
    uint4 hh, ll; split8(f, hh, ll);
    g_ehi[i] = hh; g_elo[i] = ll;
}

// ================= k_argmin: bf16x2 (exact x·eh), top-2/thread, global top-4 =================
// stage (24KB): AHI[8K] ALO[8K] BHI[8K]; 2 stages; aux @49152
#define STG2     24576
#define S2_AHI   0
#define S2_ALO   8192
#define S2_BHI   16384
#define OFF_AUX2 49152
#define SMEM_ARG (49152 + 2048)

__device__ __forceinline__ void stage_load2(uint32_t sb, int abase_g, int bbase_g, int tid) {
#pragma unroll
    for (int rep = 0; rep < 2; rep++) {
        int id  = tid + rep * 256;
        int row = id >> 2, g = id & 3;
        uint32_t so = fold_off(row, g);
        int fa = abase_g + row * 32 + g;
        int fb = bbase_g + row * 32 + g;
        cp16(sb + S2_AHI + so, g_xhi + fa);
        cp16(sb + S2_ALO + so, g_xlo + fa);
        cp16(sb + S2_BHI + so, g_ehi + fb);
    }
}

struct Frag {
    int aoff[4], akey[4], boff[2], bkey[2];
    int asub, bsub;
};
__device__ __forceinline__ void frag_init(Frag& f, int lane, int wm, int wn) {
    f.asub = lane >> 4;
    f.bsub = (lane >> 3) & 1;
#pragma unroll
    for (int ma = 0; ma < 4; ma++) {
        int row = wm * 64 + ma * 16 + ((lane >> 3) & 1) * 8 + (lane & 7);
        f.aoff[ma] = (row >> 1) * 128 + (row & 1) * 64;
        f.akey[ma] = (row >> 1) & 3;
    }
#pragma unroll
    for (int pr = 0; pr < 2; pr++) {
        int row = wn * 32 + pr * 16 + ((lane >> 4) & 1) * 8 + (lane & 7);
        f.boff[pr] = (row >> 1) * 128 + (row & 1) * 64;
        f.bkey[pr] = (row >> 1) & 3;
    }
}

// one 128x128x32 chunk: acc += xh*eh + xl*eh   (= exact x·eh)
__device__ __forceinline__ void chunk_compute(uint32_t sb, const Frag& f,
                                              float acc[4][4][4]) {
#pragma unroll
    for (int ks = 0; ks < 2; ks++) {
        int ga = ks * 2 + f.asub;
        int gb = ks * 2 + f.bsub;
        uint32_t ah[4][4], al[4][4], bh[4][2];
#pragma unroll
        for (int ma = 0; ma < 4; ma++)
            ldsm_x4(ah[ma][0], ah[ma][1], ah[ma][2], ah[ma][3],
                    sb + S2_AHI + f.aoff[ma] + (((ga ^ f.akey[ma]) & 3) << 4));
#pragma unroll
        for (int pr = 0; pr < 2; pr++) {
            uint32_t d0, d1, d2, d3;
            ldsm_x4(d0, d1, d2, d3,
                    sb + S2_BHI + f.boff[pr] + (((gb ^ f.bkey[pr]) & 3) << 4));
            bh[2*pr][0] = d0; bh[2*pr][1] = d1;
            bh[2*pr+1][0] = d2; bh[2*pr+1][1] = d3;
        }
#pragma unroll
        for (int ma = 0; ma < 4; ma++)
#pragma unroll
            for (int na = 0; na < 4; na++)
                mma_bf16(acc[ma][na], ah[ma], bh[na]);
#pragma unroll
        for (int ma = 0; ma < 4; ma++)
            ldsm_x4(al[ma][0], al[ma][1], al[ma][2], al[ma][3],
                    sb + S2_ALO + f.aoff[ma] + (((ga ^ f.akey[ma]) & 3) << 4));
#pragma unroll
        for (int ma = 0; ma < 4; ma++)
#pragma unroll
            for (int na = 0; na < 4; na++)
                mma_bf16(acc[ma][na], al[ma], bh[na]);
    }
}

__global__ void __launch_bounds__(256, 2)
k_argmin_b2(int N, int K) {
    extern __shared__ char dsm[];
    uint32_t smb = smem_u32(dsm);
    int tid  = threadIdx.x;
    int lane = tid & 31;
    int wid  = tid >> 5;
    int wm   = wid >> 2;
    int wn   = wid & 3;
    int m0   = blockIdx.x * 128;

    Frag f; frag_init(f, lane, wm, wn);

    ull tb1[8], tb2[8];
#pragma unroll
    for (int i = 0; i < 8; i++) { tb1[i] = UMAX64; tb2[i] = UMAX64; }

    int NT = K / 128;
    int C  = NT * 8;

    stage_load2(smb, m0 * 32, 0, tid);
    CP_COMMIT();

    float acc[4][4][4];
#pragma unroll
    for (int ma = 0; ma < 4; ma++)
#pragma unroll
        for (int na = 0; na < 4; na++)
#pragma unroll
            for (int c = 0; c < 4; c++) acc[ma][na][c] = 0.f;

#pragma unroll 1
    for (int c = 0; c < C; c++) {
        int nt = c >> 3, dc = c & 7;
        uint32_t sb = smb + (c & 1) * STG2;

        CP_WAIT0();
        __syncthreads();

        if (c + 1 < C) {
            int nt1 = (c + 1) >> 3, dc1 = (c + 1) & 7;
            stage_load2(smb + ((c + 1) & 1) * STG2,
                        m0 * 32 + dc1 * 4, nt1 * 128 * 32 + dc1 * 4, tid);
            CP_COMMIT();
        } else {
            CP_COMMIT();
        }

        chunk_compute(sb, f, acc);

        if (dc == 7) {
#pragma unroll
            for (int ma = 0; ma < 4; ma++) {
                int m_r = m0 + wm * 64 + ma * 16 + (lane >> 2);
                float xq0 = g_xsq[m_r];
                float xq1 = g_xsq[m_r + 8];
#pragma unroll
                for (int na = 0; na < 4; na++) {
                    int n0c = nt * 128 + wn * 32 + na * 8 + 2 * (lane & 3);
                    float e0 = g_esq[n0c], e1 = g_esq[n0c + 1];
                    float d00 = __fsub_rn(__fadd_rn(xq0, e0), 2.0f * acc[ma][na][0]);
                    float d01 = __fsub_rn(__fadd_rn(xq0, e1), 2.0f * acc[ma][na][1]);
                    float d10 = __fsub_rn(__fadd_rn(xq1, e0), 2.0f * acc[ma][na][2]);
                    float d11 = __fsub_rn(__fadd_rn(xq1, e1), 2.0f * acc[ma][na][3]);
                    upd2(tb1[ma * 2],     tb2[ma * 2],
                         ((ull)__float_as_uint(d00) << 32) | (unsigned)n0c);
                    upd2(tb1[ma * 2],     tb2[ma * 2],
                         ((ull)__float_as_uint(d01) << 32) | (unsigned)(n0c + 1));
                    upd2(tb1[ma * 2 + 1], tb2[ma * 2 + 1],
                         ((ull)__float_as_uint(d10) << 32) | (unsigned)n0c);
                    upd2(tb1[ma * 2 + 1], tb2[ma * 2 + 1],
                         ((ull)__float_as_uint(d11) << 32) | (unsigned)(n0c + 1));
                    acc[ma][na][0] = 0.f; acc[ma][na][1] = 0.f;
                    acc[ma][na][2] = 0.f; acc[ma][na][3] = 0.f;
                }
            }
        }
    }

    // global top-4 merge: 4 rounds of atomicMin with exclusion (values are distinct)
    ull* best = reinterpret_cast<ull*>(dsm + OFF_AUX2);
    ull wlast[8];
#pragma unroll
    for (int i = 0; i < 8; i++) wlast[i] = 0ULL;   // distances > 0 => packed > 0

#pragma unroll 1
    for (int r = 0; r < 4; r++) {
        __syncthreads();
        if (tid < 128) best[tid] = UMAX64;
        __syncthreads();
#pragma unroll
        for (int i = 0; i < 8; i++) {
            int ma = i >> 1;
            int mloc = wm * 64 + ma * 16 + (lane >> 2) + (i & 1) * 8;
            ull cand = (tb1[i] > wlast[i]) ? tb1[i]
                     : ((tb2[i] > wlast[i]) ? tb2[i] : UMAX64);
            if (cand != UMAX64) atomicMin(&best[mloc], cand);
        }
        __syncthreads();
#pragma unroll
        for (int i = 0; i < 8; i++) {
            int ma = i >> 1;
            int mloc = wm * 64 + ma * 16 + (lane >> 2) + (i & 1) * 8;
            wlast[i] = best[mloc];
        }
        if (tid < 128) g_cand[r * MAXN + m0 + tid] = (int)(best[tid] & 0xFFFFFFFFu);
    }
}

// ---------------- k_refine: exact fp32 rescore of the 4 candidates ----------------
__global__ void __launch_bounds__(256)
k_refine(const float* __restrict__ x, const float* __restrict__ e, int N) {
    int w    = (blockIdx.x * blockDim.x + threadIdx.x) >> 5;
    int lane = threadIdx.x & 31;
    if (w >= N) return;
    int c0 = g_cand[0 * MAXN + w];
    int c1 = g_cand[1 * MAXN + w];
    int c2 = g_cand[2 * MAXN + w];
    int c3 = g_cand[3 * MAXN + w];
    const float4* xr = reinterpret_cast<const float4*>(x + (size_t)w * D);
    float4 a = xr[lane], b = xr[32 + lane];
    float d[4];
    int cc[4] = {c0, c1, c2, c3};
#pragma unroll
    for (int r = 0; r < 4; r++) {
        const float4* er = reinterpret_cast<const float4*>(e + (size_t)cc[r] * D);
        float4 u = er[lane], v = er[32 + lane];
        d[r] = a.x*u.x + a.y*u.y + a.z*u.z + a.w*u.w
             + b.x*v.x + b.y*v.y + b.z*v.z + b.w*v.w;
    }
#pragma unroll
    for (int off = 16; off > 0; off >>= 1) {
#pragma unroll
        for (int r = 0; r < 4; r++) d[r] += __shfl_xor_sync(0xffffffffu, d[r], off);
    }
    if (lane == 0) {
        float xq = g_xsq[w];
        ull bestc = UMAX64;
#pragma unroll
        for (int r = 0; r < 4; r++) {
            float dist = __fsub_rn(__fadd_rn(xq, g_esq[cc[r]]), 2.0f * d[r]);
            ull c = ((ull)__float_as_uint(dist) << 32) | (unsigned)cc[r];
            if (c < bestc) bestc = c;
        }
        g_idx[w] = (int)(bestc & 0xFFFFFFFFu);
    }
}

// ================= k_sim (bf16x3, round-7 proven) =================
#define STG_SZ   32768
#define S_AHI    0
#define S_ALO    8192
#define S_BHI    16384
#define S_BLO    24576
#define OFF_AUX  65536
#define SMEM_SIM (65536 + 2048)

__device__ __forceinline__ void stage_load_sim(uint32_t sb,
                                               int abase_g, int bbase_g, int tid) {
#pragma unroll
    for (int rep = 0; rep < 2; rep++) {
        int id  = tid + rep * 256;
        int row = id >> 2, g = id & 3;
        uint32_t so = fold_off(row, g);
        int fa = abase_g + row * 32 + g;
        int fb = bbase_g + row * 32 + g;
        cp16(sb + S_AHI + so, g_ehi + fa);
        cp16(sb + S_ALO + so, g_elo + fa);
        cp16(sb + S_BHI + so, g_ehi + fb);
        cp16(sb + S_BLO + so, g_elo + fb);
    }
}

__device__ __forceinline__ void chunk_compute_sim(uint32_t sb, const Frag& f,
                                                  float acc[4][4][4]) {
#pragma unroll
    for (int ks = 0; ks < 2; ks++) {
        int ga = ks * 2 + f.asub;
        int gb = ks * 2 + f.bsub;
        uint32_t ah[4][4], al[4][4], bh[4][2], bl[4][2];
#pragma unroll
        for (int ma = 0; ma < 4; ma++)
            ldsm_x4(ah[ma][0], ah[ma][1], ah[ma][2], ah[ma][3],
                    sb + S_AHI + f.aoff[ma] + (((ga ^ f.akey[ma]) & 3) << 4));
#pragma unroll
        for (int pr = 0; pr < 2; pr++) {
            uint32_t d0, d1, d2, d3;
            ldsm_x4(d0, d1, d2, d3,
                    sb + S_BHI + f.boff[pr] + (((gb ^ f.bkey[pr]) & 3) << 4));
            bh[2*pr][0] = d0; bh[2*pr][1] = d1;
            bh[2*pr+1][0] = d2; bh[2*pr+1][1] = d3;
        }
#pragma unroll
        for (int ma = 0; ma < 4; ma++)
#pragma unroll
            for (int na = 0; na < 4; na++)
                mma_bf16(acc[ma][na], ah[ma], bh[na]);
#pragma unroll
        for (int pr = 0; pr < 2; pr++) {
            uint32_t d0, d1, d2, d3;
            ldsm_x4(d0, d1, d2, d3,
                    sb + S_BLO + f.boff[pr] + (((gb ^ f.bkey[pr]) & 3) << 4));
            bl[2*pr][0] = d0; bl[2*pr][1] = d1;
            bl[2*pr+1][0] = d2; bl[2*pr+1][1] = d3;
        }
#pragma unroll
        for (int ma = 0; ma < 4; ma++)
#pragma unroll
            for (int na = 0; na < 4; na++)
                mma_bf16(acc[ma][na], ah[ma], bl[na]);
#pragma unroll
        for (int ma = 0; ma < 4; ma++)
            ldsm_x4(al[ma][0], al[ma][1], al[ma][2], al[ma][3],
                    sb + S_ALO + f.aoff[ma] + (((ga ^ f.akey[ma]) & 3) << 4));
#pragma unroll
        for (int ma = 0; ma < 4; ma++)
#pragma unroll
            for (int na = 0; na < 4; na++)
                mma_bf16(acc[ma][na], al[ma], bh[na]);
    }
}

__global__ void __launch_bounds__(256, 2)
k_sim_mma(int K) {
    extern __shared__ char dsm[];
    uint32_t smb = smem_u32(dsm);
    int tid  = threadIdx.x;
    int lane = tid & 31;
    int wid  = tid >> 5;
    int wm   = wid >> 2;
    int wn   = wid & 3;

    int nt_blocks = K / 128;
    int b = blockIdx.x, by = 0;
    while (b >= nt_blocks - by) { b -= nt_blocks - by; by++; }
    int bx = by + b;
    int m0 = by * 128, n0 = bx * 128;
    float wgt = (by == bx) ? 1.0f : 2.0f;

    Frag f; frag_init(f, lane, wm, wn);

    float acc[4][4][4];
#pragma unroll
    for (int ma = 0; ma < 4; ma++)
#pragma unroll
        for (int na = 0; na < 4; na++)
#pragma unroll
            for (int c = 0; c < 4; c++) acc[ma][na][c] = 0.f;

    stage_load_sim(smb, m0 * 32, n0 * 32, tid);
    CP_COMMIT();

#pragma unroll 1
    for (int dc = 0; dc < 8; dc++) {
        uint32_t sb = smb + (dc & 1) * STG_SZ;
        CP_WAIT0();
        __syncthreads();
        if (dc + 1 < 8) {
            stage_load_sim(smb + ((dc + 1) & 1) * STG_SZ,
                           m0 * 32 + (dc + 1) * 4, n0 * 32 + (dc + 1) * 4, tid);
            CP_COMMIT();
        } else {
            CP_COMMIT();
        }
        chunk_compute_sim(sb, f, acc);
    }

    float s = 0.f;
#pragma unroll
    for (int ma = 0; ma < 4; ma++) {
        int m_r0 = m0 + wm * 64 + ma * 16 + (lane >> 2);
        float r0 = g_rninv[m_r0], r1 = g_rninv[m_r0 + 8];
#pragma unroll
        for (int na = 0; na < 4; na++) {
            int n0c = n0 + wn * 32 + na * 8 + 2 * (lane & 3);
            float q0 = g_rninv[n0c], q1 = g_rninv[n0c + 1];
            float s00 = fabsf(acc[ma][na][0] * r0 * q0);
            float s01 = fabsf(acc[ma][na][1] * r0 * q1);
            float s10 = fabsf(acc[ma][na][2] * r1 * q0);
            float s11 = fabsf(acc[ma][na][3] * r1 * q1);
            if (m_r0     == n0c)     s00 = 0.f;
            if (m_r0     == n0c + 1) s01 = 0.f;
            if (m_r0 + 8 == n0c)     s10 = 0.f;
            if (m_r0 + 8 == n0c + 1) s11 = 0.f;
            s += (s00 + s01) + (s10 + s11);
        }
    }
    s *= wgt;

    float* red = reinterpret_cast<float*>(dsm + OFF_AUX);
    __syncthreads();
    red[tid] = s; __syncthreads();
    for (int st = 128; st > 0; st >>= 1) { if (tid < st) red[tid] += red[tid + st]; __syncthreads(); }
    if (tid == 0) atomicAdd(&g_acc[1], red[0]);
}

// ---------------- k_gather ----------------
__global__ void __launch_bounds__(256)
k_gather(const float* __restrict__ x, const float* __restrict__ e,
         float* __restrict__ outq, float* __restrict__ outidx, int N) {
    __shared__ float red[256];
    int tid = threadIdx.x;
    int t   = blockIdx.x * 16 + (tid >> 4);
    int seg = tid & 15;
    int k = g_idx[t];
    const float4* er = reinterpret_cast<const float4*>(e + (size_t)k * D);
    const float4* xr = reinterpret_cast<const float4*>(x + (size_t)t * D);
    float4* qr = reinterpret_cast<float4*>(outq + (size_t)t * D);
    float s = 0.f;
#pragma unroll
    for (int j = 0; j < 4; j++) {
        int c = seg + j * 16;
        float4 q = er[c], xv = xr[c];
        qr[c] = q;
        float dx = q.x - xv.x, dy = q.y - xv.y, dz = q.z - xv.z, dw = q.w - xv.w;
        s += (dx * dx + dy * dy) + (dz * dz + dw * dw);
    }
    red[tid] = s; __syncthreads();
    for (int st = 128; st > 0; st >>= 1) { if (tid < st) red[tid] += red[tid + st]; __syncthreads(); }
    if (tid == 0) atomicAdd(&g_acc[0], red[0]);
    if (seg == 0) {
        outidx[t] = (float)k;
        atomicAdd(&g_counts[k], 1.0f);
    }
}

// ---------------- k_final ----------------
__global__ void k_final(float* __restrict__ out_loss, float* __restrict__ out_perp, int N, int K) {
    __shared__ float sA[256], sB[256], sC[256];
    int tid = threadIdx.x;

    float tot = 0.f;
    for (int k = tid; k < K; k += 256) tot += g_counts[k];
    sA[tid] = tot; __syncthreads();
    for (int st = 128; st > 0; st >>= 1) { if (tid < st) sA[tid] += sA[tid + st]; __syncthreads(); }
    float total = sA[0];
    __syncthreads();

    float tuni = 1.0f / (float)K;
    float kl = 0.f, pl = 0.f;
    for (int k = tid; k < K; k += 256) {
        float p = g_counts[k] / total;
        kl += (p + EPS_F) * logf((p + EPS_F) / (tuni + EPS_F));
        if (p > 0.f) pl += p * logf(p);
    }
    sB[tid] = kl; sC[tid] = pl; __syncthreads();
    for (int st = 128; st > 0; st >>= 1) {
        if (tid < st) { sB[tid] += sB[tid + st]; sC[tid] += sC[tid + st]; }
        __syncthreads();
    }
    if (tid == 0) {
        float klv = fminf(sB[0], 100.0f);
        float mse = g_acc[0] / ((float)N * (float)D);
        float vq  = mse + COMMIT_COST * mse;
        float l2  = fminf(g_acc[2] / (float)K, 10.0f);
        float orth = fminf(g_acc[1] / ((float)K * (float)K), 10.0f);
        float reg = l2 + orth;
        float loss = fminf(vq + DIV_GAMMA * klv + 0.01f * reg, 100.0f);
        *out_loss = loss;
        *out_perp = expf(-sC[0]);
    }
}

// ---------------- launch ----------------
extern "C" void kernel_launch(void* const* d_in, const int* in_sizes, int n_in,
                              void* d_out, int out_size) {
    const float* x = (const float*)d_in[0];
    const float* e = (const float*)d_in[1];
    float* out = (float*)d_out;

    int N = in_sizes[0] / D;   // 65536
    int K = in_sizes[1] / D;   // 2048
    if (N > MAXN) N = MAXN;
    if (K > MAXK) K = MAXK;

    float* out_q    = out;
    float* out_loss = out + (size_t)N * D;
    float* out_perp = out_loss + 1;
    float* out_idx  = out_perp + 1;

    cudaFuncSetAttribute(k_argmin_b2, cudaFuncAttributeMaxDynamicSharedMemorySize, SMEM_ARG);
    cudaFuncSetAttribute(k_sim_mma,   cudaFuncAttributeMaxDynamicSharedMemorySize, SMEM_SIM);

    int nx8 = N * (D / 8);
    int ne8 = K * (D / 8);
    int ntb = K / 128;
    int tri = ntb * (ntb + 1) / 2;

    k_init     <<<(K + 255) / 256, 256>>>(K);
    k_prep     <<<(K + 7) / 8, 256>>>(e, K);
    k_xsq      <<<(N + 7) / 8, 256>>>(x, N);
    k_split_x  <<<(nx8 + 255) / 256, 256>>>((const float4*)x, nx8);
    k_split_e  <<<(ne8 + 255) / 256, 256>>>((const float4*)e, ne8);
    k_argmin_b2<<<N / 128, 256, SMEM_ARG>>>(N, K);
    k_refine   <<<(N + 7) / 8, 256>>>(x, e, N);
    k_gather   <<<N / 16, 256>>>(x, e, out_q, out_idx, N);
    k_sim_mma  <<<tri, 256, SMEM_SIM>>>(K);
    k_final    <<<1, 256>>>(out_loss, out_perp, N, K);
}

// round 12
// speedup vs baseline: 3.5617x; 1.3655x over previous
#include <cuda_runtime.h>
#include <cuda_bf16.h>
#include <cstdint>

#define D    256
#define MAXK 2048
#define MAXN 65536

#define COMMIT_COST 0.25f
#define DIV_GAMMA   0.1f
#define EPS_F       1e-8f

typedef unsigned long long ull;
#define UMAX64 0xFFFFFFFFFFFFFFFFULL

// ---------------- device scratch ----------------
__device__ float g_esq[MAXK];
__device__ float g_rninv[MAXK];
__device__ float g_xsq[MAXN];
__device__ int   g_idx[MAXN];
__device__ int   g_cand[4 * MAXN];
__device__ float g_counts[MAXK];
__device__ float g_acc[4];

// bf16 splits (16B granules of 8 bf16). x: hi only. e: hi + lo (lo for k_sim).
__device__ uint4 g_xhi[MAXN * D / 8];
__device__ uint4 g_ehi[MAXK * D / 8];
__device__ uint4 g_elo[MAXK * D / 8];

// ---------------- helpers ----------------
__device__ __forceinline__ uint32_t smem_u32(const void* p) {
    uint32_t a;
    asm("{ .reg .u64 t; cvta.to.shared.u64 t, %1; cvt.u32.u64 %0, t; }" : "=r"(a) : "l"(p));
    return a;
}
__device__ __forceinline__ void ldsm_x4(uint32_t& d0, uint32_t& d1, uint32_t& d2, uint32_t& d3,
                                        uint32_t addr) {
    asm volatile("ldmatrix.sync.aligned.m8n8.x4.shared.b16 {%0,%1,%2,%3}, [%4];"
        : "=r"(d0), "=r"(d1), "=r"(d2), "=r"(d3) : "r"(addr));
}
__device__ __forceinline__ void mma_bf16(float* c, const uint32_t* a, const uint32_t* b) {
    asm volatile(
        "mma.sync.aligned.m16n8k16.row.col.f32.bf16.bf16.f32 "
        "{%0,%1,%2,%3}, {%4,%5,%6,%7}, {%8,%9}, {%0,%1,%2,%3};"
        : "+f"(c[0]), "+f"(c[1]), "+f"(c[2]), "+f"(c[3])
        : "r"(a[0]), "r"(a[1]), "r"(a[2]), "r"(a[3]), "r"(b[0]), "r"(b[1]));
}
__device__ __forceinline__ void cp16(uint32_t dst, const void* src) {
    asm volatile("{ .reg .u64 g; cvta.to.global.u64 g, %1; "
                 "cp.async.cg.shared.global [%0], [g], 16; }"
                 :: "r"(dst), "l"(src) : "memory");
}
#define CP_COMMIT() asm volatile("cp.async.commit_group;" ::: "memory")
#define CP_WAIT0()  asm volatile("cp.async.wait_group 0;" ::: "memory")

__device__ __forceinline__ uint32_t fold_off(int row, int g) {
    return (uint32_t)((row >> 1) * 128 + (row & 1) * 64 + ((g ^ ((row >> 1) & 3)) << 4));
}
__device__ __forceinline__ void upd2(ull& b1, ull& b2, ull c) {
    if (c < b1) { b2 = b1; b1 = c; }
    else if (c < b2) { b2 = c; }
}

// ---------------- k_init ----------------
__global__ void k_init(int K) {
    int i = blockIdx.x * blockDim.x + threadIdx.x;
    if (i < K) g_counts[i] = 0.f;
    if (i < 4) g_acc[i] = 0.f;
}

// ---------------- k_prep (e): esq, rninv, rn-sum ----------------
__global__ void k_prep(const float* __restrict__ e, int K) {
    int w    = (blockIdx.x * blockDim.x + threadIdx.x) >> 5;
    int lane = threadIdx.x & 31;
    if (w >= K) return;
    const float4* er = reinterpret_cast<const float4*>(e + (size_t)w * D);
    float4 a = er[lane], b = er[32 + lane];
    float s = __fadd_rn(
        __fadd_rn(__fadd_rn(__fmul_rn(a.x,a.x), __fmul_rn(a.y,a.y)),
                  __fadd_rn(__fmul_rn(a.z,a.z), __fmul_rn(a.w,a.w))),
        __fadd_rn(__fadd_rn(__fmul_rn(b.x,b.x), __fmul_rn(b.y,b.y)),
                  __fadd_rn(__fmul_rn(b.z,b.z), __fmul_rn(b.w,b.w))));
#pragma unroll
    for (int off = 16; off > 0; off >>= 1) s += __shfl_xor_sync(0xffffffffu, s, off);
    if (lane == 0) {
        g_esq[w] = s;
        float rn = sqrtf(s);
        g_rninv[w] = 1.0f / fmaxf(rn, 1e-12f);
        atomicAdd(&g_acc[2], rn);
    }
}

// ---------------- k_xsq ----------------
__global__ void k_xsq(const float* __restrict__ x, int N) {
    int w    = (blockIdx.x * blockDim.x + threadIdx.x) >> 5;
    int lane = threadIdx.x & 31;
    if (w >= N) return;
    const float4* xr = reinterpret_cast<const float4*>(x + (size_t)w * D);
    float4 a = xr[lane], b = xr[32 + lane];
    float s = __fadd_rn(
        __fadd_rn(__fadd_rn(__fmul_rn(a.x,a.x), __fmul_rn(a.y,a.y)),
                  __fadd_rn(__fmul_rn(a.z,a.z), __fmul_rn(a.w,a.w))),
        __fadd_rn(__fadd_rn(__fmul_rn(b.x,b.x), __fmul_rn(b.y,b.y)),
                  __fadd_rn(__fmul_rn(b.z,b.z), __fmul_rn(b.w,b.w))));
#pragma unroll
    for (int off = 16; off > 0; off >>= 1) s += __shfl_xor_sync(0xffffffffu, s, off);
    if (lane == 0) g_xsq[w] = s;
}

// ---------------- k_split: bf16 hi (x) / hi+lo (e) ----------------
__device__ __forceinline__ void split8(const float* f, uint4& hh, uint4& ll) {
    unsigned h[8], l[8];
#pragma unroll
    for (int j = 0; j < 8; j++) {
        __nv_bfloat16 hb = __float2bfloat16(f[j]);
        float hf = __bfloat162float(hb);
        __nv_bfloat16 lb = __float2bfloat16(f[j] - hf);
        h[j] = __bfloat16_as_ushort(hb);
        l[j] = __bfloat16_as_ushort(lb);
    }
    hh = make_uint4(h[0] | (h[1] << 16), h[2] | (h[3] << 16),
                    h[4] | (h[5] << 16), h[6] | (h[7] << 16));
    ll = make_uint4(l[0] | (l[1] << 16), l[2] | (l[3] << 16),
                    l[4] | (l[5] << 16), l[6] | (l[7] << 16));
}
__global__ void k_split_x(const float4* __restrict__ src, int n8) {
    int i = blockIdx.x * blockDim.x + threadIdx.x;
    if (i >= n8) return;
    float4 v0 = src[2 * i], v1 = src[2 * i + 1];
    float f[8] = {v0.x, v0.y, v0.z, v0.w, v1.x, v1.y, v1.z, v1.w};
    unsigned h[8];
#pragma unroll
    for (int j = 0; j < 8; j++) h[j] = __bfloat16_as_ushort(__float2bfloat16(f[j]));
    g_xhi[i] = make_uint4(h[0] | (h[1] << 16), h[2] | (h[3] << 16),
                          h[4] | (h[5] << 16), h[6] | (h[7] << 16));
}
__global__ void k_split_e(const float4* __restrict__ src, int n8) {
    int i = blockIdx.x * blockDim.x + threadIdx.x;
    if (i >= n8) return;
    float4 v0 = src[2 * i], v1 = src[2 * i + 1];
    float f[8] = {v0.x, v0.y, v0.z, v0.w, v1.x, v1.y, v1.z, v1.w};
    uint4 hh, ll; split8(f, hh, ll);
    g_ehi[i] = hh; g_elo[i] = ll;
}

// ================= k_argmin: single-pass xh·eh, top-2/thread, global top-4 =================
// stage (16KB): AHI[8K] BHI[8K]; 2 stages; aux @32768
#define STG2     16384
#define S2_AHI   0
#define S2_BHI   8192
#define OFF_AUX2 32768
#define SMEM_ARG (32768 + 2048)

__device__ __forceinline__ void stage_load2(uint32_t sb, int abase_g, int bbase_g, int tid) {
#pragma unroll
    for (int rep = 0; rep < 2; rep++) {
        int id  = tid + rep * 256;
        int row = id >> 2, g = id & 3;
        uint32_t so = fold_off(row, g);
        cp16(sb + S2_AHI + so, g_xhi + abase_g + row * 32 + g);
        cp16(sb + S2_BHI + so, g_ehi + bbase_g + row * 32 + g);
    }
}

struct Frag {
    int aoff[4], akey[4], boff[2], bkey[2];
    int asub, bsub;
};
__device__ __forceinline__ void frag_init(Frag& f, int lane, int wm, int wn) {
    f.asub = lane >> 4;
    f.bsub = (lane >> 3) & 1;
#pragma unroll
    for (int ma = 0; ma < 4; ma++) {
        int row = wm * 64 + ma * 16 + ((lane >> 3) & 1) * 8 + (lane & 7);
        f.aoff[ma] = (row >> 1) * 128 + (row & 1) * 64;
        f.akey[ma] = (row >> 1) & 3;
    }
#pragma unroll
    for (int pr = 0; pr < 2; pr++) {
        int row = wn * 32 + pr * 16 + ((lane >> 4) & 1) * 8 + (lane & 7);
        f.boff[pr] = (row >> 1) * 128 + (row & 1) * 64;
        f.bkey[pr] = (row >> 1) & 3;
    }
}

// one 128x128x32 chunk: acc += xh*eh   (single pass)
__device__ __forceinline__ void chunk_compute(uint32_t sb, const Frag& f,
                                              float acc[4][4][4]) {
#pragma unroll
    for (int ks = 0; ks < 2; ks++) {
        int ga = ks * 2 + f.asub;
        int gb = ks * 2 + f.bsub;
        uint32_t ah[4][4], bh[4][2];
#pragma unroll
        for (int ma = 0; ma < 4; ma++)
            ldsm_x4(ah[ma][0], ah[ma][1], ah[ma][2], ah[ma][3],
                    sb + S2_AHI + f.aoff[ma] + (((ga ^ f.akey[ma]) & 3) << 4));
#pragma unroll
        for (int pr = 0; pr < 2; pr++) {
            uint32_t d0, d1, d2, d3;
            ldsm_x4(d0, d1, d2, d3,
                    sb + S2_BHI + f.boff[pr] + (((gb ^ f.bkey[pr]) & 3) << 4));
            bh[2*pr][0] = d0; bh[2*pr][1] = d1;
            bh[2*pr+1][0] = d2; bh[2*pr+1][1] = d3;
        }
#pragma unroll
        for (int ma = 0; ma < 4; ma++)
#pragma unroll
            for (int na = 0; na < 4; na++)
                mma_bf16(acc[ma][na], ah[ma], bh[na]);
    }
}

__global__ void __launch_bounds__(256, 2)
k_argmin_b1(int N, int K) {
    extern __shared__ char dsm[];
    uint32_t smb = smem_u32(dsm);
    int tid  = threadIdx.x;
    int lane = tid & 31;
    int wid  = tid >> 5;
    int wm   = wid >> 2;
    int wn   = wid & 3;
    int m0   = blockIdx.x * 128;

    Frag f; frag_init(f, lane, wm, wn);

    ull tb1[8], tb2[8];
#pragma unroll
    for (int i = 0; i < 8; i++) { tb1[i] = UMAX64; tb2[i] = UMAX64; }

    int NT = K / 128;
    int C  = NT * 8;

    stage_load2(smb, m0 * 32, 0, tid);
    CP_COMMIT();

    float acc[4][4][4];
#pragma unroll
    for (int ma = 0; ma < 4; ma++)
#pragma unroll
        for (int na = 0; na < 4; na++)
#pragma unroll
            for (int c = 0; c < 4; c++) acc[ma][na][c] = 0.f;

#pragma unroll 1
    for (int c = 0; c < C; c++) {
        int nt = c >> 3, dc = c & 7;
        uint32_t sb = smb + (c & 1) * STG2;

        CP_WAIT0();
        __syncthreads();

        if (c + 1 < C) {
            int nt1 = (c + 1) >> 3, dc1 = (c + 1) & 7;
            stage_load2(smb + ((c + 1) & 1) * STG2,
                        m0 * 32 + dc1 * 4, nt1 * 128 * 32 + dc1 * 4, tid);
            CP_COMMIT();
        } else {
            CP_COMMIT();
        }

        chunk_compute(sb, f, acc);

        if (dc == 7) {
#pragma unroll
            for (int ma = 0; ma < 4; ma++) {
                int m_r = m0 + wm * 64 + ma * 16 + (lane >> 2);
                float xq0 = g_xsq[m_r];
                float xq1 = g_xsq[m_r + 8];
#pragma unroll
                for (int na = 0; na < 4; na++) {
                    int n0c = nt * 128 + wn * 32 + na * 8 + 2 * (lane & 3);
                    float e0 = g_esq[n0c], e1 = g_esq[n0c + 1];
                    float d00 = __fsub_rn(__fadd_rn(xq0, e0), 2.0f * acc[ma][na][0]);
                    float d01 = __fsub_rn(__fadd_rn(xq0, e1), 2.0f * acc[ma][na][1]);
                    float d10 = __fsub_rn(__fadd_rn(xq1, e0), 2.0f * acc[ma][na][2]);
                    float d11 = __fsub_rn(__fadd_rn(xq1, e1), 2.0f * acc[ma][na][3]);
                    upd2(tb1[ma * 2],     tb2[ma * 2],
                         ((ull)__float_as_uint(d00) << 32) | (unsigned)n0c);
                    upd2(tb1[ma * 2],     tb2[ma * 2],
                         ((ull)__float_as_uint(d01) << 32) | (unsigned)(n0c + 1));
                    upd2(tb1[ma * 2 + 1], tb2[ma * 2 + 1],
                         ((ull)__float_as_uint(d10) << 32) | (unsigned)n0c);
                    upd2(tb1[ma * 2 + 1], tb2[ma * 2 + 1],
                         ((ull)__float_as_uint(d11) << 32) | (unsigned)(n0c + 1));
                    acc[ma][na][0] = 0.f; acc[ma][na][1] = 0.f;
                    acc[ma][na][2] = 0.f; acc[ma][na][3] = 0.f;
                }
            }
        }
    }

    // global top-4 merge: 4 rounds of atomicMin with exclusion
    ull* best = reinterpret_cast<ull*>(dsm + OFF_AUX2);
    ull wlast[8];
#pragma unroll
    for (int i = 0; i < 8; i++) wlast[i] = 0ULL;

#pragma unroll 1
    for (int r = 0; r < 4; r++) {
        __syncthreads();
        if (tid < 128) best[tid] = UMAX64;
        __syncthreads();
#pragma unroll
        for (int i = 0; i < 8; i++) {
            int ma = i >> 1;
            int mloc = wm * 64 + ma * 16 + (lane >> 2) + (i & 1) * 8;
            ull cand = (tb1[i] > wlast[i]) ? tb1[i]
                     : ((tb2[i] > wlast[i]) ? tb2[i] : UMAX64);
            if (cand != UMAX64) atomicMin(&best[mloc], cand);
        }
        __syncthreads();
#pragma unroll
        for (int i = 0; i < 8; i++) {
            int ma = i >> 1;
            int mloc = wm * 64 + ma * 16 + (lane >> 2) + (i & 1) * 8;
            wlast[i] = best[mloc];
        }
        if (tid < 128) g_cand[r * MAXN + m0 + tid] = (int)(best[tid] & 0xFFFFFFFFu);
    }
}

// ---------------- k_refine: exact fp32 rescore of the 4 candidates ----------------
__global__ void __launch_bounds__(256)
k_refine(const float* __restrict__ x, const float* __restrict__ e, int N) {
    int w    = (blockIdx.x * blockDim.x + threadIdx.x) >> 5;
    int lane = threadIdx.x & 31;
    if (w >= N) return;
    int cc[4];
#pragma unroll
    for (int r = 0; r < 4; r++) cc[r] = g_cand[r * MAXN + w];
    const float4* xr = reinterpret_cast<const float4*>(x + (size_t)w * D);
    float4 a = xr[lane], b = xr[32 + lane];
    float d[4];
#pragma unroll
    for (int r = 0; r < 4; r++) {
        const float4* er = reinterpret_cast<const float4*>(e + (size_t)cc[r] * D);
        float4 u = er[lane], v = er[32 + lane];
        d[r] = a.x*u.x + a.y*u.y + a.z*u.z + a.w*u.w
             + b.x*v.x + b.y*v.y + b.z*v.z + b.w*v.w;
    }
#pragma unroll
    for (int off = 16; off > 0; off >>= 1) {
#pragma unroll
        for (int r = 0; r < 4; r++) d[r] += __shfl_xor_sync(0xffffffffu, d[r], off);
    }
    if (lane == 0) {
        float xq = g_xsq[w];
        ull bestc = UMAX64;
#pragma unroll
        for (int r = 0; r < 4; r++) {
            float dist = __fsub_rn(__fadd_rn(xq, g_esq[cc[r]]), 2.0f * d[r]);
            ull c = ((ull)__float_as_uint(dist) << 32) | (unsigned)cc[r];
            if (c < bestc) bestc = c;
        }
        g_idx[w] = (int)(bestc & 0xFFFFFFFFu);
    }
}

// ================= k_sim (bf16x3, round-7 proven) =================
#define STG_SZ   32768
#define S_AHI    0
#define S_ALO    8192
#define S_BHI    16384
#define S_BLO    24576
#define OFF_AUX  65536
#define SMEM_SIM (65536 + 2048)

__device__ __forceinline__ void stage_load_sim(uint32_t sb,
                                               int abase_g, int bbase_g, int tid) {
#pragma unroll
    for (int rep = 0; rep < 2; rep++) {
        int id  = tid + rep * 256;
        int row = id >> 2, g = id & 3;
        uint32_t so = fold_off(row, g);
        int fa = abase_g + row * 32 + g;
        int fb = bbase_g + row * 32 + g;
        cp16(sb + S_AHI + so, g_ehi + fa);
        cp16(sb + S_ALO + so, g_elo + fa);
        cp16(sb + S_BHI + so, g_ehi + fb);
        cp16(sb + S_BLO + so, g_elo + fb);
    }
}

__device__ __forceinline__ void chunk_compute_sim(uint32_t sb, const Frag& f,
                                                  float acc[4][4][4]) {
#pragma unroll
    for (int ks = 0; ks < 2; ks++) {
        int ga = ks * 2 + f.asub;
        int gb = ks * 2 + f.bsub;
        uint32_t ah[4][4], al[4][4], bh[4][2], bl[4][2];
#pragma unroll
        for (int ma = 0; ma < 4; ma++)
            ldsm_x4(ah[ma][0], ah[ma][1], ah[ma][2], ah[ma][3],
                    sb + S_AHI + f.aoff[ma] + (((ga ^ f.akey[ma]) & 3) << 4));
#pragma unroll
        for (int pr = 0; pr < 2; pr++) {
            uint32_t d0, d1, d2, d3;
            ldsm_x4(d0, d1, d2, d3,
                    sb + S_BHI + f.boff[pr] + (((gb ^ f.bkey[pr]) & 3) << 4));
            bh[2*pr][0] = d0; bh[2*pr][1] = d1;
            bh[2*pr+1][0] = d2; bh[2*pr+1][1] = d3;
        }
#pragma unroll
        for (int ma = 0; ma < 4; ma++)
#pragma unroll
            for (int na = 0; na < 4; na++)
                mma_bf16(acc[ma][na], ah[ma], bh[na]);
#pragma unroll
        for (int pr = 0; pr < 2; pr++) {
            uint32_t d0, d1, d2, d3;
            ldsm_x4(d0, d1, d2, d3,
                    sb + S_BLO + f.boff[pr] + (((gb ^ f.bkey[pr]) & 3) << 4));
            bl[2*pr][0] = d0; bl[2*pr][1] = d1;
            bl[2*pr+1][0] = d2; bl[2*pr+1][1] = d3;
        }
#pragma unroll
        for (int ma = 0; ma < 4; ma++)
#pragma unroll
            for (int na = 0; na < 4; na++)
                mma_bf16(acc[ma][na], ah[ma], bl[na]);
#pragma unroll
        for (int ma = 0; ma < 4; ma++)
            ldsm_x4(al[ma][0], al[ma][1], al[ma][2], al[ma][3],
                    sb + S_ALO + f.aoff[ma] + (((ga ^ f.akey[ma]) & 3) << 4));
#pragma unroll
        for (int ma = 0; ma < 4; ma++)
#pragma unroll
            for (int na = 0; na < 4; na++)
                mma_bf16(acc[ma][na], al[ma], bh[na]);
    }
}

__global__ void __launch_bounds__(256, 2)
k_sim_mma(int K) {
    extern __shared__ char dsm[];
    uint32_t smb = smem_u32(dsm);
    int tid  = threadIdx.x;
    int lane = tid & 31;
    int wid  = tid >> 5;
    int wm   = wid >> 2;
    int wn   = wid & 3;

    int nt_blocks = K / 128;
    int b = blockIdx.x, by = 0;
    while (b >= nt_blocks - by) { b -= nt_blocks - by; by++; }
    int bx = by + b;
    int m0 = by * 128, n0 = bx * 128;
    float wgt = (by == bx) ? 1.0f : 2.0f;

    Frag f; frag_init(f, lane, wm, wn);

    float acc[4][4][4];
#pragma unroll
    for (int ma = 0; ma < 4; ma++)
#pragma unroll
        for (int na = 0; na < 4; na++)
#pragma unroll
            for (int c = 0; c < 4; c++) acc[ma][na][c] = 0.f;

    stage_load_sim(smb, m0 * 32, n0 * 32, tid);
    CP_COMMIT();

#pragma unroll 1
    for (int dc = 0; dc < 8; dc++) {
        uint32_t sb = smb + (dc & 1) * STG_SZ;
        CP_WAIT0();
        __syncthreads();
        if (dc + 1 < 8) {
            stage_load_sim(smb + ((dc + 1) & 1) * STG_SZ,
                           m0 * 32 + (dc + 1) * 4, n0 * 32 + (dc + 1) * 4, tid);
            CP_COMMIT();
        } else {
            CP_COMMIT();
        }
        chunk_compute_sim(sb, f, acc);
    }

    float s = 0.f;
#pragma unroll
    for (int ma = 0; ma < 4; ma++) {
        int m_r0 = m0 + wm * 64 + ma * 16 + (lane >> 2);
        float r0 = g_rninv[m_r0], r1 = g_rninv[m_r0 + 8];
#pragma unroll
        for (int na = 0; na < 4; na++) {
            int n0c = n0 + wn * 32 + na * 8 + 2 * (lane & 3);
            float q0 = g_rninv[n0c], q1 = g_rninv[n0c + 1];
            float s00 = fabsf(acc[ma][na][0] * r0 * q0);
            float s01 = fabsf(acc[ma][na][1] * r0 * q1);
            float s10 = fabsf(acc[ma][na][2] * r1 * q0);
            float s11 = fabsf(acc[ma][na][3] * r1 * q1);
            if (m_r0     == n0c)     s00 = 0.f;
            if (m_r0     == n0c + 1) s01 = 0.f;
            if (m_r0 + 8 == n0c)     s10 = 0.f;
            if (m_r0 + 8 == n0c + 1) s11 = 0.f;
            s += (s00 + s01) + (s10 + s11);
        }
    }
    s *= wgt;

    float* red = reinterpret_cast<float*>(dsm + OFF_AUX);
    __syncthreads();
    red[tid] = s; __syncthreads();
    for (int st = 128; st > 0; st >>= 1) { if (tid < st) red[tid] += red[tid + st]; __syncthreads(); }
    if (tid == 0) atomicAdd(&g_acc[1], red[0]);
}

// ---------------- k_gather ----------------
__global__ void __launch_bounds__(256)
k_gather(const float* __restrict__ x, const float* __restrict__ e,
         float* __restrict__ outq, float* __restrict__ outidx, int N) {
    __shared__ float red[256];
    int tid = threadIdx.x;
    int t   = blockIdx.x * 16 + (tid >> 4);
    int seg = tid & 15;
    int k = g_idx[t];
    const float4* er = reinterpret_cast<const float4*>(e + (size_t)k * D);
    const float4* xr = reinterpret_cast<const float4*>(x + (size_t)t * D);
    float4* qr = reinterpret_cast<float4*>(outq + (size_t)t * D);
    float s = 0.f;
#pragma unroll
    for (int j = 0; j < 4; j++) {
        int c = seg + j * 16;
        float4 q = er[c], xv = xr[c];
        qr[c] = q;
        float dx = q.x - xv.x, dy = q.y - xv.y, dz = q.z - xv.z, dw = q.w - xv.w;
        s += (dx * dx + dy * dy) + (dz * dz + dw * dw);
    }
    red[tid] = s; __syncthreads();
    for (int st = 128; st > 0; st >>= 1) { if (tid < st) red[tid] += red[tid + st]; __syncthreads(); }
    if (tid == 0) atomicAdd(&g_acc[0], red[0]);
    if (seg == 0) {
        outidx[t] = (float)k;
        atomicAdd(&g_counts[k], 1.0f);
    }
}

// ---------------- k_final ----------------
__global__ void k_final(float* __restrict__ out_loss, float* __restrict__ out_perp, int N, int K) {
    __shared__ float sA[256], sB[256], sC[256];
    int tid = threadIdx.x;

    float tot = 0.f;
    for (int k = tid; k < K; k += 256) tot += g_counts[k];
    sA[tid] = tot; __syncthreads();
    for (int st = 128; st > 0; st >>= 1) { if (tid < st) sA[tid] += sA[tid + st]; __syncthreads(); }
    float total = sA[0];
    __syncthreads();

    float tuni = 1.0f / (float)K;
    float kl = 0.f, pl = 0.f;
    for (int k = tid; k < K; k += 256) {
        float p = g_counts[k] / total;
        kl += (p + EPS_F) * logf((p + EPS_F) / (tuni + EPS_F));
        if (p > 0.f) pl += p * logf(p);
    }
    sB[tid] = kl; sC[tid] = pl; __syncthreads();
    for (int st = 128; st > 0; st >>= 1) {
        if (tid < st) { sB[tid] += sB[tid + st]; sC[tid] += sC[tid + st]; }
        __syncthreads();
    }
    if (tid == 0) {
        float klv = fminf(sB[0], 100.0f);
        float mse = g_acc[0] / ((float)N * (float)D);
        float vq  = mse + COMMIT_COST * mse;
        float l2  = fminf(g_acc[2] / (float)K, 10.0f);
        float orth = fminf(g_acc[1] / ((float)K * (float)K), 10.0f);
        float reg = l2 + orth;
        float loss = fminf(vq + DIV_GAMMA * klv + 0.01f * reg, 100.0f);
        *out_loss = loss;
        *out_perp = expf(-sC[0]);
    }
}

// ---------------- launch ----------------
extern "C" void kernel_launch(void* const* d_in, const int* in_sizes, int n_in,
                              void* d_out, int out_size) {
    const float* x = (const float*)d_in[0];
    const float* e = (const float*)d_in[1];
    float* out = (float*)d_out;

    int N = in_sizes[0] / D;   // 65536
    int K = in_sizes[1] / D;   // 2048
    if (N > MAXN) N = MAXN;
    if (K > MAXK) K = MAXK;

    float* out_q    = out;
    float* out_loss = out + (size_t)N * D;
    float* out_perp = out_loss + 1;
    float* out_idx  = out_perp + 1;

    cudaFuncSetAttribute(k_argmin_b1, cudaFuncAttributeMaxDynamicSharedMemorySize, SMEM_ARG);
    cudaFuncSetAttribute(k_sim_mma,   cudaFuncAttributeMaxDynamicSharedMemorySize, SMEM_SIM);

    int nx8 = N * (D / 8);
    int ne8 = K * (D / 8);
    int ntb = K / 128;
    int tri = ntb * (ntb + 1) / 2;

    k_init     <<<(K + 255) / 256, 256>>>(K);
    k_prep     <<<(K + 7) / 8, 256>>>(e, K);
    k_xsq      <<<(N + 7) / 8, 256>>>(x, N);
    k_split_x  <<<(nx8 + 255) / 256, 256>>>((const float4*)x, nx8);
    k_split_e  <<<(ne8 + 255) / 256, 256>>>((const float4*)e, ne8);
    k_argmin_b1<<<N / 128, 256, SMEM_ARG>>>(N, K);
    k_refine   <<<(N + 7) / 8, 256>>>(x, e, N);
    k_gather   <<<N / 16, 256>>>(x, e, out_q, out_idx, N);
    k_sim_mma  <<<tri, 256, SMEM_SIM>>>(K);
    k_final    <<<1, 256>>>(out_loss, out_perp, N, K);
}

// round 13
// speedup vs baseline: 3.7233x; 1.0454x over previous
#include <cuda_runtime.h>
#include <cuda_bf16.h>
#include <cstdint>

#define D    256
#define MAXK 2048
#define MAXN 65536

#define COMMIT_COST 0.25f
#define DIV_GAMMA   0.1f
#define EPS_F       1e-8f

typedef unsigned long long ull;
#define UMAX64 0xFFFFFFFFFFFFFFFFULL

// ---------------- device scratch ----------------
__device__ float g_esq[MAXK];
__device__ float g_rninv[MAXK];
__device__ float g_xsq[MAXN];
__device__ int   g_cand[4 * MAXN];
__device__ float g_counts[MAXK];
__device__ float g_acc[4];

// bf16 splits (16B granules of 8 bf16). x: hi only. e: hi + lo (lo for k_sim).
__device__ uint4 g_xhi[MAXN * D / 8];
__device__ uint4 g_ehi[MAXK * D / 8];
__device__ uint4 g_elo[MAXK * D / 8];

// ---------------- helpers ----------------
__device__ __forceinline__ uint32_t smem_u32(const void* p) {
    uint32_t a;
    asm("{ .reg .u64 t; cvta.to.shared.u64 t, %1; cvt.u32.u64 %0, t; }" : "=r"(a) : "l"(p));
    return a;
}
__device__ __forceinline__ void ldsm_x4(uint32_t& d0, uint32_t& d1, uint32_t& d2, uint32_t& d3,
                                        uint32_t addr) {
    asm volatile("ldmatrix.sync.aligned.m8n8.x4.shared.b16 {%0,%1,%2,%3}, [%4];"
        : "=r"(d0), "=r"(d1), "=r"(d2), "=r"(d3) : "r"(addr));
}
__device__ __forceinline__ void mma_bf16(float* c, const uint32_t* a, const uint32_t* b) {
    asm volatile(
        "mma.sync.aligned.m16n8k16.row.col.f32.bf16.bf16.f32 "
        "{%0,%1,%2,%3}, {%4,%5,%6,%7}, {%8,%9}, {%0,%1,%2,%3};"
        : "+f"(c[0]), "+f"(c[1]), "+f"(c[2]), "+f"(c[3])
        : "r"(a[0]), "r"(a[1]), "r"(a[2]), "r"(a[3]), "r"(b[0]), "r"(b[1]));
}
__device__ __forceinline__ void cp16(uint32_t dst, const void* src) {
    asm volatile("{ .reg .u64 g; cvta.to.global.u64 g, %1; "
                 "cp.async.cg.shared.global [%0], [g], 16; }"
                 :: "r"(dst), "l"(src) : "memory");
}
#define CP_COMMIT() asm volatile("cp.async.commit_group;" ::: "memory")
#define CP_WAIT0()  asm volatile("cp.async.wait_group 0;" ::: "memory")
#define CP_WAIT2()  asm volatile("cp.async.wait_group 2;" ::: "memory")

__device__ __forceinline__ uint32_t fold_off(int row, int g) {
    return (uint32_t)((row >> 1) * 128 + (row & 1) * 64 + ((g ^ ((row >> 1) & 3)) << 4));
}
__device__ __forceinline__ void upd2(ull& b1, ull& b2, ull c) {
    if (c < b1) { b2 = b1; b1 = c; }
    else if (c < b2) { b2 = c; }
}

// ---------------- k_init ----------------
__global__ void k_init(int K) {
    int i = blockIdx.x * blockDim.x + threadIdx.x;
    if (i < K) g_counts[i] = 0.f;
    if (i < 4) g_acc[i] = 0.f;
}

// ---------------- k_prep_e: esq, rninv, rn-sum, bf16 hi/lo split (warp per row) ----------------
__global__ void k_prep_e(const float4* __restrict__ e4, int K) {
    int w    = (blockIdx.x * blockDim.x + threadIdx.x) >> 5;
    int lane = threadIdx.x & 31;
    if (w >= K) return;
    const float4* er = e4 + (size_t)w * 64;
    float4 a = er[2 * lane], b = er[2 * lane + 1];
    float f[8] = {a.x, a.y, a.z, a.w, b.x, b.y, b.z, b.w};
    float s = 0.f;
#pragma unroll
    for (int j = 0; j < 8; j++) s += f[j] * f[j];
#pragma unroll
    for (int off = 16; off > 0; off >>= 1) s += __shfl_xor_sync(0xffffffffu, s, off);

    unsigned h[8], l[8];
#pragma unroll
    for (int j = 0; j < 8; j++) {
        __nv_bfloat16 hb = __float2bfloat16(f[j]);
        float hf = __bfloat162float(hb);
        h[j] = __bfloat16_as_ushort(hb);
        l[j] = __bfloat16_as_ushort(__float2bfloat16(f[j] - hf));
    }
    g_ehi[w * 32 + lane] = make_uint4(h[0] | (h[1] << 16), h[2] | (h[3] << 16),
                                      h[4] | (h[5] << 16), h[6] | (h[7] << 16));
    g_elo[w * 32 + lane] = make_uint4(l[0] | (l[1] << 16), l[2] | (l[3] << 16),
                                      l[4] | (l[5] << 16), l[6] | (l[7] << 16));
    if (lane == 0) {
        g_esq[w] = s;
        float rn = sqrtf(s);
        g_rninv[w] = 1.0f / fmaxf(rn, 1e-12f);
        atomicAdd(&g_acc[2], rn);
    }
}

// ---------------- k_prep_x: xsq + bf16 hi split (warp per row) ----------------
__global__ void k_prep_x(const float4* __restrict__ x4, int N) {
    int w    = (blockIdx.x * blockDim.x + threadIdx.x) >> 5;
    int lane = threadIdx.x & 31;
    if (w >= N) return;
    const float4* xr = x4 + (size_t)w * 64;
    float4 a = xr[2 * lane], b = xr[2 * lane + 1];
    float f[8] = {a.x, a.y, a.z, a.w, b.x, b.y, b.z, b.w};
    float s = 0.f;
#pragma unroll
    for (int j = 0; j < 8; j++) s += f[j] * f[j];
#pragma unroll
    for (int off = 16; off > 0; off >>= 1) s += __shfl_xor_sync(0xffffffffu, s, off);
    unsigned h[8];
#pragma unroll
    for (int j = 0; j < 8; j++) h[j] = __bfloat16_as_ushort(__float2bfloat16(f[j]));
    g_xhi[w * 32 + lane] = make_uint4(h[0] | (h[1] << 16), h[2] | (h[3] << 16),
                                      h[4] | (h[5] << 16), h[6] | (h[7] << 16));
    if (lane == 0) g_xsq[w] = s;
}

// ================= k_argmin: single-pass xh·eh, 4-stage pipeline, top-2/thread, top-4 =================
// stage (16KB): AHI[8K] BHI[8K]; 4 stages; aux @65536
#define STG2     16384
#define S2_AHI   0
#define S2_BHI   8192
#define OFF_AUX2 65536
#define SMEM_ARG (65536 + 2048)

__device__ __forceinline__ void stage_load2(uint32_t sb, int abase_g, int bbase_g, int tid) {
#pragma unroll
    for (int rep = 0; rep < 2; rep++) {
        int id  = tid + rep * 256;
        int row = id >> 2, g = id & 3;
        uint32_t so = fold_off(row, g);
        cp16(sb + S2_AHI + so, g_xhi + abase_g + row * 32 + g);
        cp16(sb + S2_BHI + so, g_ehi + bbase_g + row * 32 + g);
    }
}

struct Frag {
    int aoff[4], akey[4], boff[2], bkey[2];
    int asub, bsub;
};
__device__ __forceinline__ void frag_init(Frag& f, int lane, int wm, int wn) {
    f.asub = lane >> 4;
    f.bsub = (lane >> 3) & 1;
#pragma unroll
    for (int ma = 0; ma < 4; ma++) {
        int row = wm * 64 + ma * 16 + ((lane >> 3) & 1) * 8 + (lane & 7);
        f.aoff[ma] = (row >> 1) * 128 + (row & 1) * 64;
        f.akey[ma] = (row >> 1) & 3;
    }
#pragma unroll
    for (int pr = 0; pr < 2; pr++) {
        int row = wn * 32 + pr * 16 + ((lane >> 4) & 1) * 8 + (lane & 7);
        f.boff[pr] = (row >> 1) * 128 + (row & 1) * 64;
        f.bkey[pr] = (row >> 1) & 3;
    }
}

__device__ __forceinline__ void chunk_compute(uint32_t sb, const Frag& f,
                                              float acc[4][4][4]) {
#pragma unroll
    for (int ks = 0; ks < 2; ks++) {
        int ga = ks * 2 + f.asub;
        int gb = ks * 2 + f.bsub;
        uint32_t ah[4][4], bh[4][2];
#pragma unroll
        for (int ma = 0; ma < 4; ma++)
            ldsm_x4(ah[ma][0], ah[ma][1], ah[ma][2], ah[ma][3],
                    sb + S2_AHI + f.aoff[ma] + (((ga ^ f.akey[ma]) & 3) << 4));
#pragma unroll
        for (int pr = 0; pr < 2; pr++) {
            uint32_t d0, d1, d2, d3;
            ldsm_x4(d0, d1, d2, d3,
                    sb + S2_BHI + f.boff[pr] + (((gb ^ f.bkey[pr]) & 3) << 4));
            bh[2*pr][0] = d0; bh[2*pr][1] = d1;
            bh[2*pr+1][0] = d2; bh[2*pr+1][1] = d3;
        }
#pragma unroll
        for (int ma = 0; ma < 4; ma++)
#pragma unroll
            for (int na = 0; na < 4; na++)
                mma_bf16(acc[ma][na], ah[ma], bh[na]);
    }
}

__global__ void __launch_bounds__(256, 2)
k_argmin_b1(int N, int K) {
    extern __shared__ char dsm[];
    uint32_t smb = smem_u32(dsm);
    int tid  = threadIdx.x;
    int lane = tid & 31;
    int wid  = tid >> 5;
    int wm   = wid >> 2;
    int wn   = wid & 3;
    int m0   = blockIdx.x * 128;

    Frag f; frag_init(f, lane, wm, wn);

    ull tb1[8], tb2[8];
#pragma unroll
    for (int i = 0; i < 8; i++) { tb1[i] = UMAX64; tb2[i] = UMAX64; }

    int NT = K / 128;
    int C  = NT * 8;

    // prologue: 3 chunks in flight
#pragma unroll
    for (int p = 0; p < 3; p++) {
        int nt = p >> 3, dc = p & 7;
        stage_load2(smb + p * STG2, m0 * 32 + dc * 4, nt * 128 * 32 + dc * 4, tid);
        CP_COMMIT();
    }

    float acc[4][4][4];
#pragma unroll
    for (int ma = 0; ma < 4; ma++)
#pragma unroll
        for (int na = 0; na < 4; na++)
#pragma unroll
            for (int c = 0; c < 4; c++) acc[ma][na][c] = 0.f;

#pragma unroll 1
    for (int c = 0; c < C; c++) {
        int nt = c >> 3, dc = c & 7;
        uint32_t sb = smb + (c & 3) * STG2;

        CP_WAIT2();
        __syncthreads();

        if (c + 3 < C) {
            int c3 = c + 3;
            int nt3 = c3 >> 3, dc3 = c3 & 7;
            stage_load2(smb + (c3 & 3) * STG2,
                        m0 * 32 + dc3 * 4, nt3 * 128 * 32 + dc3 * 4, tid);
            CP_COMMIT();
        } else {
            CP_COMMIT();
        }

        chunk_compute(sb, f, acc);

        if (dc == 7) {
#pragma unroll
            for (int ma = 0; ma < 4; ma++) {
                int m_r = m0 + wm * 64 + ma * 16 + (lane >> 2);
                float xq0 = g_xsq[m_r];
                float xq1 = g_xsq[m_r + 8];
#pragma unroll
                for (int na = 0; na < 4; na++) {
                    int n0c = nt * 128 + wn * 32 + na * 8 + 2 * (lane & 3);
                    float e0 = g_esq[n0c], e1 = g_esq[n0c + 1];
                    float d00 = __fsub_rn(__fadd_rn(xq0, e0), 2.0f * acc[ma][na][0]);
                    float d01 = __fsub_rn(__fadd_rn(xq0, e1), 2.0f * acc[ma][na][1]);
                    float d10 = __fsub_rn(__fadd_rn(xq1, e0), 2.0f * acc[ma][na][2]);
                    float d11 = __fsub_rn(__fadd_rn(xq1, e1), 2.0f * acc[ma][na][3]);
                    upd2(tb1[ma * 2],     tb2[ma * 2],
                         ((ull)__float_as_uint(d00) << 32) | (unsigned)n0c);
                    upd2(tb1[ma * 2],     tb2[ma * 2],
                         ((ull)__float_as_uint(d01) << 32) | (unsigned)(n0c + 1));
                    upd2(tb1[ma * 2 + 1], tb2[ma * 2 + 1],
                         ((ull)__float_as_uint(d10) << 32) | (unsigned)n0c);
                    upd2(tb1[ma * 2 + 1], tb2[ma * 2 + 1],
                         ((ull)__float_as_uint(d11) << 32) | (unsigned)(n0c + 1));
                    acc[ma][na][0] = 0.f; acc[ma][na][1] = 0.f;
                    acc[ma][na][2] = 0.f; acc[ma][na][3] = 0.f;
                }
            }
        }
    }

    // global top-4 merge: 4 rounds of atomicMin with exclusion
    ull* best = reinterpret_cast<ull*>(dsm + OFF_AUX2);
    ull wlast[8];
#pragma unroll
    for (int i = 0; i < 8; i++) wlast[i] = 0ULL;

#pragma unroll 1
    for (int r = 0; r < 4; r++) {
        __syncthreads();
        if (tid < 128) best[tid] = UMAX64;
        __syncthreads();
#pragma unroll
        for (int i = 0; i < 8; i++) {
            int ma = i >> 1;
            int mloc = wm * 64 + ma * 16 + (lane >> 2) + (i & 1) * 8;
            ull cand = (tb1[i] > wlast[i]) ? tb1[i]
                     : ((tb2[i] > wlast[i]) ? tb2[i] : UMAX64);
            if (cand != UMAX64) atomicMin(&best[mloc], cand);
        }
        __syncthreads();
#pragma unroll
        for (int i = 0; i < 8; i++) {
            int ma = i >> 1;
            int mloc = wm * 64 + ma * 16 + (lane >> 2) + (i & 1) * 8;
            wlast[i] = best[mloc];
        }
        if (tid < 128) g_cand[r * MAXN + m0 + tid] = (int)(best[tid] & 0xFFFFFFFFu);
    }
}

// ---------------- k_finalize: exact rescore + quantized write + counts + MSE ----------------
__global__ void __launch_bounds__(256)
k_finalize(const float* __restrict__ x, const float* __restrict__ e,
           float* __restrict__ outq, float* __restrict__ outidx, int N) {
    __shared__ float smse[8];
    int wg   = threadIdx.x >> 5;
    int lane = threadIdx.x & 31;
    int w    = blockIdx.x * 8 + wg;

    int cc[4];
#pragma unroll
    for (int r = 0; r < 4; r++) cc[r] = g_cand[r * MAXN + w];

    const float4* xr = reinterpret_cast<const float4*>(x + (size_t)w * D);
    float4 a = xr[lane], b = xr[32 + lane];
    float4 u[4], v[4];
    float d[4];
#pragma unroll
    for (int r = 0; r < 4; r++) {
        const float4* er = reinterpret_cast<const float4*>(e + (size_t)cc[r] * D);
        u[r] = er[lane]; v[r] = er[32 + lane];
        d[r] = a.x*u[r].x + a.y*u[r].y + a.z*u[r].z + a.w*u[r].w
             + b.x*v[r].x + b.y*v[r].y + b.z*v[r].z + b.w*v[r].w;
    }
#pragma unroll
    for (int off = 16; off > 0; off >>= 1) {
#pragma unroll
        for (int r = 0; r < 4; r++) d[r] += __shfl_xor_sync(0xffffffffu, d[r], off);
    }

    float xq = g_xsq[w];
    ull bestc = UMAX64;
    int rwin = 0;
#pragma unroll
    for (int r = 0; r < 4; r++) {
        float dist = __fsub_rn(__fadd_rn(xq, g_esq[cc[r]]), 2.0f * d[r]);
        ull c = ((ull)__float_as_uint(dist) << 32) | (unsigned)cc[r];
        if (c < bestc) { bestc = c; rwin = r; }
    }
    int kwin = (int)(bestc & 0xFFFFFFFFu);

    // write quantized row from registers (uniform select across warp)
    float4 uw = u[0], vw = v[0];
    if (rwin == 1) { uw = u[1]; vw = v[1]; }
    if (rwin == 2) { uw = u[2]; vw = v[2]; }
    if (rwin == 3) { uw = u[3]; vw = v[3]; }
    float4* qr = reinterpret_cast<float4*>(outq + (size_t)w * D);
    qr[lane] = uw;
    qr[32 + lane] = vw;

    if (lane == 0) {
        outidx[w] = (float)kwin;
        atomicAdd(&g_counts[kwin], 1.0f);
        smse[wg] = __uint_as_float((unsigned)(bestc >> 32));   // winning distance = token MSE sum
    }
    __syncthreads();
    if (threadIdx.x == 0) {
        float s = 0.f;
#pragma unroll
        for (int i = 0; i < 8; i++) s += smse[i];
        atomicAdd(&g_acc[0], s);
    }
}

// ================= k_sim (bf16x3, proven) =================
#define STG_SZ   32768
#define S_AHI    0
#define S_ALO    8192
#define S_BHI    16384
#define S_BLO    24576
#define OFF_AUX  65536
#define SMEM_SIM (65536 + 2048)

__device__ __forceinline__ void stage_load_sim(uint32_t sb,
                                               int abase_g, int bbase_g, int tid) {
#pragma unroll
    for (int rep = 0; rep < 2; rep++) {
        int id  = tid + rep * 256;
        int row = id >> 2, g = id & 3;
        uint32_t so = fold_off(row, g);
        int fa = abase_g + row * 32 + g;
        int fb = bbase_g + row * 32 + g;
        cp16(sb + S_AHI + so, g_ehi + fa);
        cp16(sb + S_ALO + so, g_elo + fa);
        cp16(sb + S_BHI + so, g_ehi + fb);
        cp16(sb + S_BLO + so, g_elo + fb);
    }
}

__device__ __forceinline__ void chunk_compute_sim(uint32_t sb, const Frag& f,
                                                  float acc[4][4][4]) {
#pragma unroll
    for (int ks = 0; ks < 2; ks++) {
        int ga = ks * 2 + f.asub;
        int gb = ks * 2 + f.bsub;
        uint32_t ah[4][4], al[4][4], bh[4][2], bl[4][2];
#pragma unroll
        for (int ma = 0; ma < 4; ma++)
            ldsm_x4(ah[ma][0], ah[ma][1], ah[ma][2], ah[ma][3],
                    sb + S_AHI + f.aoff[ma] + (((ga ^ f.akey[ma]) & 3) << 4));
#pragma unroll
        for (int pr = 0; pr < 2; pr++) {
            uint32_t d0, d1, d2, d3;
            ldsm_x4(d0, d1, d2, d3,
                    sb + S_BHI + f.boff[pr] + (((gb ^ f.bkey[pr]) & 3) << 4));
            bh[2*pr][0] = d0; bh[2*pr][1] = d1;
            bh[2*pr+1][0] = d2; bh[2*pr+1][1] = d3;
        }
#pragma unroll
        for (int ma = 0; ma < 4; ma++)
#pragma unroll
            for (int na = 0; na < 4; na++)
                mma_bf16(acc[ma][na], ah[ma], bh[na]);
#pragma unroll
        for (int pr = 0; pr < 2; pr++) {
            uint32_t d0, d1, d2, d3;
            ldsm_x4(d0, d1, d2, d3,
                    sb + S_BLO + f.boff[pr] + (((gb ^ f.bkey[pr]) & 3) << 4));
            bl[2*pr][0] = d0; bl[2*pr][1] = d1;
            bl[2*pr+1][0] = d2; bl[2*pr+1][1] = d3;
        }
#pragma unroll
        for (int ma = 0; ma < 4; ma++)
#pragma unroll
            for (int na = 0; na < 4; na++)
                mma_bf16(acc[ma][na], ah[ma], bl[na]);
#pragma unroll
        for (int ma = 0; ma < 4; ma++)
            ldsm_x4(al[ma][0], al[ma][1], al[ma][2], al[ma][3],
                    sb + S_ALO + f.aoff[ma] + (((ga ^ f.akey[ma]) & 3) << 4));
#pragma unroll
        for (int ma = 0; ma < 4; ma++)
#pragma unroll
            for (int na = 0; na < 4; na++)
                mma_bf16(acc[ma][na], al[ma], bh[na]);
    }
}

__global__ void __launch_bounds__(256, 2)
k_sim_mma(int K) {
    extern __shared__ char dsm[];
    uint32_t smb = smem_u32(dsm);
    int tid  = threadIdx.x;
    int lane = tid & 31;
    int wid  = tid >> 5;
    int wm   = wid >> 2;
    int wn   = wid & 3;

    int nt_blocks = K / 128;
    int b = blockIdx.x, by = 0;
    while (b >= nt_blocks - by) { b -= nt_blocks - by; by++; }
    int bx = by + b;
    int m0 = by * 128, n0 = bx * 128;
    float wgt = (by == bx) ? 1.0f : 2.0f;

    Frag f; frag_init(f, lane, wm, wn);

    float acc[4][4][4];
#pragma unroll
    for (int ma = 0; ma < 4; ma++)
#pragma unroll
        for (int na = 0; na < 4; na++)
#pragma unroll
            for (int c = 0; c < 4; c++) acc[ma][na][c] = 0.f;

    stage_load_sim(smb, m0 * 32, n0 * 32, tid);
    CP_COMMIT();

#pragma unroll 1
    for (int dc = 0; dc < 8; dc++) {
        uint32_t sb = smb + (dc & 1) * STG_SZ;
        CP_WAIT0();
        __syncthreads();
        if (dc + 1 < 8) {
            stage_load_sim(smb + ((dc + 1) & 1) * STG_SZ,
                           m0 * 32 + (dc + 1) * 4, n0 * 32 + (dc + 1) * 4, tid);
            CP_COMMIT();
        } else {
            CP_COMMIT();
        }
        chunk_compute_sim(sb, f, acc);
    }

    float s = 0.f;
#pragma unroll
    for (int ma = 0; ma < 4; ma++) {
        int m_r0 = m0 + wm * 64 + ma * 16 + (lane >> 2);
        float r0 = g_rninv[m_r0], r1 = g_rninv[m_r0 + 8];
#pragma unroll
        for (int na = 0; na < 4; na++) {
            int n0c = n0 + wn * 32 + na * 8 + 2 * (lane & 3);
            float q0 = g_rninv[n0c], q1 = g_rninv[n0c + 1];
            float s00 = fabsf(acc[ma][na][0] * r0 * q0);
            float s01 = fabsf(acc[ma][na][1] * r0 * q1);
            float s10 = fabsf(acc[ma][na][2] * r1 * q0);
            float s11 = fabsf(acc[ma][na][3] * r1 * q1);
            if (m_r0     == n0c)     s00 = 0.f;
            if (m_r0     == n0c + 1) s01 = 0.f;
            if (m_r0 + 8 == n0c)     s10 = 0.f;
            if (m_r0 + 8 == n0c + 1) s11 = 0.f;
            s += (s00 + s01) + (s10 + s11);
        }
    }
    s *= wgt;

    float* red = reinterpret_cast<float*>(dsm + OFF_AUX);
    __syncthreads();
    red[tid] = s; __syncthreads();
    for (int st = 128; st > 0; st >>= 1) { if (tid < st) red[tid] += red[tid + st]; __syncthreads(); }
    if (tid == 0) atomicAdd(&g_acc[1], red[0]);
}

// ---------------- k_final ----------------
__global__ void k_final(float* __restrict__ out_loss, float* __restrict__ out_perp, int N, int K) {
    __shared__ float sA[256], sB[256], sC[256];
    int tid = threadIdx.x;

    float tot = 0.f;
    for (int k = tid; k < K; k += 256) tot += g_counts[k];
    sA[tid] = tot; __syncthreads();
    for (int st = 128; st > 0; st >>= 1) { if (tid < st) sA[tid] += sA[tid + st]; __syncthreads(); }
    float total = sA[0];
    __syncthreads();

    float tuni = 1.0f / (float)K;
    float kl = 0.f, pl = 0.f;
    for (int k = tid; k < K; k += 256) {
        float p = g_counts[k] / total;
        kl += (p + EPS_F) * logf((p + EPS_F) / (tuni + EPS_F));
        if (p > 0.f) pl += p * logf(p);
    }
    sB[tid] = kl; sC[tid] = pl; __syncthreads();
    for (int st = 128; st > 0; st >>= 1) {
        if (tid < st) { sB[tid] += sB[tid + st]; sC[tid] += sC[tid + st]; }
        __syncthreads();
    }
    if (tid == 0) {
        float klv = fminf(sB[0], 100.0f);
        float mse = g_acc[0] / ((float)N * (float)D);
        float vq  = mse + COMMIT_COST * mse;
        float l2  = fminf(g_acc[2] / (float)K, 10.0f);
        float orth = fminf(g_acc[1] / ((float)K * (float)K), 10.0f);
        float reg = l2 + orth;
        float loss = fminf(vq + DIV_GAMMA * klv + 0.01f * reg, 100.0f);
        *out_loss = loss;
        *out_perp = expf(-sC[0]);
    }
}

// ---------------- launch ----------------
extern "C" void kernel_launch(void* const* d_in, const int* in_sizes, int n_in,
                              void* d_out, int out_size) {
    const float* x = (const float*)d_in[0];
    const float* e = (const float*)d_in[1];
    float* out = (float*)d_out;

    int N = in_sizes[0] / D;   // 65536
    int K = in_sizes[1] / D;   // 2048
    if (N > MAXN) N = MAXN;
    if (K > MAXK) K = MAXK;

    float* out_q    = out;
    float* out_loss = out + (size_t)N * D;
    float* out_perp = out_loss + 1;
    float* out_idx  = out_perp + 1;

    cudaFuncSetAttribute(k_argmin_b1, cudaFuncAttributeMaxDynamicSharedMemorySize, SMEM_ARG);
    cudaFuncSetAttribute(k_sim_mma,   cudaFuncAttributeMaxDynamicSharedMemorySize, SMEM_SIM);

    int ntb = K / 128;
    int tri = ntb * (ntb + 1) / 2;

    k_init     <<<(K + 255) / 256, 256>>>(K);
    k_prep_e   <<<(K + 7) / 8, 256>>>((const float4*)e, K);
    k_prep_x   <<<(N + 7) / 8, 256>>>((const float4*)x, N);
    k_argmin_b1<<<N / 128, 256, SMEM_ARG>>>(N, K);
    k_finalize <<<N / 8, 256>>>(x, e, out_q, out_idx, N);
    k_sim_mma  <<<tri, 256, SMEM_SIM>>>(K);
    k_final    <<<1, 256>>>(out_loss, out_perp, N, K);
}

// round 14
// speedup vs baseline: 3.9000x; 1.0474x over previous
#include <cuda_runtime.h>
#include <cuda_bf16.h>
#include <cstdint>

#define D    256
#define MAXK 2048
#define MAXN 65536

#define COMMIT_COST 0.25f
#define DIV_GAMMA   0.1f
#define EPS_F       1e-8f

typedef unsigned long long ull;
#define UMAX64 0xFFFFFFFFFFFFFFFFULL

// ---------------- device scratch ----------------
__device__ float g_esq[MAXK];
__device__ float g_rninv[MAXK];
__device__ float g_xsq[MAXN];
__device__ int   g_cand[4 * MAXN];
__device__ float g_counts[MAXK];
__device__ float g_acc[4];

// bf16 splits (16B granules of 8 bf16). x: hi only. e: hi + lo (lo for k_sim).
__device__ uint4 g_xhi[MAXN * D / 8];
__device__ uint4 g_ehi[MAXK * D / 8];
__device__ uint4 g_elo[MAXK * D / 8];

// ---------------- helpers ----------------
__device__ __forceinline__ uint32_t smem_u32(const void* p) {
    uint32_t a;
    asm("{ .reg .u64 t; cvta.to.shared.u64 t, %1; cvt.u32.u64 %0, t; }" : "=r"(a) : "l"(p));
    return a;
}
__device__ __forceinline__ void ldsm_x4(uint32_t& d0, uint32_t& d1, uint32_t& d2, uint32_t& d3,
                                        uint32_t addr) {
    asm volatile("ldmatrix.sync.aligned.m8n8.x4.shared.b16 {%0,%1,%2,%3}, [%4];"
        : "=r"(d0), "=r"(d1), "=r"(d2), "=r"(d3) : "r"(addr));
}
__device__ __forceinline__ void mma_bf16(float* c, const uint32_t* a, const uint32_t* b) {
    asm volatile(
        "mma.sync.aligned.m16n8k16.row.col.f32.bf16.bf16.f32 "
        "{%0,%1,%2,%3}, {%4,%5,%6,%7}, {%8,%9}, {%0,%1,%2,%3};"
        : "+f"(c[0]), "+f"(c[1]), "+f"(c[2]), "+f"(c[3])
        : "r"(a[0]), "r"(a[1]), "r"(a[2]), "r"(a[3]), "r"(b[0]), "r"(b[1]));
}
__device__ __forceinline__ void cp16(uint32_t dst, const void* src) {
    asm volatile("{ .reg .u64 g; cvta.to.global.u64 g, %1; "
                 "cp.async.cg.shared.global [%0], [g], 16; }"
                 :: "r"(dst), "l"(src) : "memory");
}
#define CP_COMMIT() asm volatile("cp.async.commit_group;" ::: "memory")
#define CP_WAIT0()  asm volatile("cp.async.wait_group 0;" ::: "memory")
#define CP_WAIT1()  asm volatile("cp.async.wait_group 1;" ::: "memory")

__device__ __forceinline__ uint32_t fold_off(int row, int g) {
    return (uint32_t)((row >> 1) * 128 + (row & 1) * 64 + ((g ^ ((row >> 1) & 3)) << 4));
}
__device__ __forceinline__ void upd2(ull& b1, ull& b2, ull c) {
    if (c < b1) { b2 = b1; b1 = c; }
    else if (c < b2) { b2 = c; }
}

// ---------------- k_init ----------------
__global__ void k_init(int K) {
    int i = blockIdx.x * blockDim.x + threadIdx.x;
    if (i < K) g_counts[i] = 0.f;
    if (i < 4) g_acc[i] = 0.f;
}

// ---------------- k_prep_e: esq, rninv, rn-sum, bf16 hi/lo split ----------------
__global__ void k_prep_e(const float4* __restrict__ e4, int K) {
    int w    = (blockIdx.x * blockDim.x + threadIdx.x) >> 5;
    int lane = threadIdx.x & 31;
    if (w >= K) return;
    const float4* er = e4 + (size_t)w * 64;
    float4 a = er[2 * lane], b = er[2 * lane + 1];
    float f[8] = {a.x, a.y, a.z, a.w, b.x, b.y, b.z, b.w};
    float s = 0.f;
#pragma unroll
    for (int j = 0; j < 8; j++) s += f[j] * f[j];
#pragma unroll
    for (int off = 16; off > 0; off >>= 1) s += __shfl_xor_sync(0xffffffffu, s, off);

    unsigned h[8], l[8];
#pragma unroll
    for (int j = 0; j < 8; j++) {
        __nv_bfloat16 hb = __float2bfloat16(f[j]);
        float hf = __bfloat162float(hb);
        h[j] = __bfloat16_as_ushort(hb);
        l[j] = __bfloat16_as_ushort(__float2bfloat16(f[j] - hf));
    }
    g_ehi[w * 32 + lane] = make_uint4(h[0] | (h[1] << 16), h[2] | (h[3] << 16),
                                      h[4] | (h[5] << 16), h[6] | (h[7] << 16));
    g_elo[w * 32 + lane] = make_uint4(l[0] | (l[1] << 16), l[2] | (l[3] << 16),
                                      l[4] | (l[5] << 16), l[6] | (l[7] << 16));
    if (lane == 0) {
        g_esq[w] = s;
        float rn = sqrtf(s);
        g_rninv[w] = 1.0f / fmaxf(rn, 1e-12f);
        atomicAdd(&g_acc[2], rn);
    }
}

// ---------------- k_prep_x: xsq + bf16 hi split ----------------
__global__ void k_prep_x(const float4* __restrict__ x4, int N) {
    int w    = (blockIdx.x * blockDim.x + threadIdx.x) >> 5;
    int lane = threadIdx.x & 31;
    if (w >= N) return;
    const float4* xr = x4 + (size_t)w * 64;
    float4 a = xr[2 * lane], b = xr[2 * lane + 1];
    float f[8] = {a.x, a.y, a.z, a.w, b.x, b.y, b.z, b.w};
    float s = 0.f;
#pragma unroll
    for (int j = 0; j < 8; j++) s += f[j] * f[j];
#pragma unroll
    for (int off = 16; off > 0; off >>= 1) s += __shfl_xor_sync(0xffffffffu, s, off);
    unsigned h[8];
#pragma unroll
    for (int j = 0; j < 8; j++) h[j] = __bfloat16_as_ushort(__float2bfloat16(f[j]));
    g_xhi[w * 32 + lane] = make_uint4(h[0] | (h[1] << 16), h[2] | (h[3] << 16),
                                      h[4] | (h[5] << 16), h[6] | (h[7] << 16));
    if (lane == 0) g_xsq[w] = s;
}

// ================= k_argmin: single-pass xh·eh, k64 chunks, 3-stage pipeline =================
// stage (32KB): AHI[16K: 128r x 128B] BHI[16K]; 3 stages; aux @98304
// row layout: 128B rows, granule swizzle g ^ (row & 7)
#define STG64    32768
#define S64_B    16384
#define OFF_AUX2 98304
#define SMEM_ARG (98304 + 2048)

struct Frag2 {
    int aoff[4], akey[4], boff[2], bkey[2];
    int asub, bsub;
};
__device__ __forceinline__ void frag_init2(Frag2& f, int lane, int wm, int wn) {
    f.asub = lane >> 4;
    f.bsub = (lane >> 3) & 1;
#pragma unroll
    for (int ma = 0; ma < 4; ma++) {
        int row = wm * 64 + ma * 16 + ((lane >> 3) & 1) * 8 + (lane & 7);
        f.aoff[ma] = row * 128;
        f.akey[ma] = row & 7;
    }
#pragma unroll
    for (int pr = 0; pr < 2; pr++) {
        int row = wn * 32 + pr * 16 + ((lane >> 4) & 1) * 8 + (lane & 7);
        f.boff[pr] = S64_B + row * 128;
        f.bkey[pr] = row & 7;
    }
}

// one 128x128x64 chunk per call: 64 MMAs/warp
__device__ __forceinline__ void chunk_compute64(uint32_t sb, const Frag2& f,
                                                float acc[4][4][4]) {
#pragma unroll
    for (int ks = 0; ks < 4; ks++) {
        int ga = ks * 2 + f.asub;
        int gb = ks * 2 + f.bsub;
        uint32_t ah[4][4], bh[4][2];
#pragma unroll
        for (int ma = 0; ma < 4; ma++)
            ldsm_x4(ah[ma][0], ah[ma][1], ah[ma][2], ah[ma][3],
                    sb + f.aoff[ma] + (((ga ^ f.akey[ma]) & 7) << 4));
#pragma unroll
        for (int pr = 0; pr < 2; pr++) {
            uint32_t d0, d1, d2, d3;
            ldsm_x4(d0, d1, d2, d3,
                    sb + f.boff[pr] + (((gb ^ f.bkey[pr]) & 7) << 4));
            bh[2*pr][0] = d0; bh[2*pr][1] = d1;
            bh[2*pr+1][0] = d2; bh[2*pr+1][1] = d3;
        }
#pragma unroll
        for (int ma = 0; ma < 4; ma++)
#pragma unroll
            for (int na = 0; na < 4; na++)
                mma_bf16(acc[ma][na], ah[ma], bh[na]);
    }
}

__global__ void __launch_bounds__(256, 2)
k_argmin_b1(int N, int K) {
    extern __shared__ char dsm[];
    uint32_t smb = smem_u32(dsm);
    int tid  = threadIdx.x;
    int lane = tid & 31;
    int wid  = tid >> 5;
    int wm   = wid >> 2;
    int wn   = wid & 3;
    int m0   = blockIdx.x * 128;

    Frag2 f; frag_init2(f, lane, wm, wn);

    // hoisted loader addressing: 4 (row,granule) assignments, chunk-invariant
    uint32_t lso[4];
    int      lgo[4];
#pragma unroll
    for (int r = 0; r < 4; r++) {
        int id  = tid + r * 256;       // 0..1023
        int row = id >> 3, g = id & 7;
        lso[r] = (uint32_t)(row * 128 + ((g ^ (row & 7)) << 4));
        lgo[r] = row * 32 + g;
    }

    ull tb1[8], tb2[8];
#pragma unroll
    for (int i = 0; i < 8; i++) { tb1[i] = UMAX64; tb2[i] = UMAX64; }

    int NT = K / 128;     // 16
    int C  = NT * 4;      // 64 chunks of k64
    int am0 = m0 * 32;

    // prologue: 2 chunks in flight
#pragma unroll
    for (int p = 0; p < 2; p++) {
        uint32_t sb = smb + p * STG64;
        int ab = am0 + p * 8;          // nt=0, dc=p
        int bb = p * 8;
#pragma unroll
        for (int r = 0; r < 4; r++) {
            cp16(sb + lso[r],         g_xhi + ab + lgo[r]);
            cp16(sb + S64_B + lso[r], g_ehi + bb + lgo[r]);
        }
        CP_COMMIT();
    }

    float acc[4][4][4];
#pragma unroll
    for (int ma = 0; ma < 4; ma++)
#pragma unroll
        for (int na = 0; na < 4; na++)
#pragma unroll
            for (int c = 0; c < 4; c++) acc[ma][na][c] = 0.f;

#pragma unroll 1
    for (int c = 0; c < C; c++) {
        int nt = c >> 2, dc = c & 3;
        uint32_t sb = smb + (c % 3) * STG64;

        CP_WAIT1();
        __syncthreads();

        if (c + 2 < C) {
            int c2 = c + 2;
            int nt2 = c2 >> 2, dc2 = c2 & 3;
            uint32_t sb2 = smb + (c2 % 3) * STG64;
            int ab = am0 + dc2 * 8;
            int bb = nt2 * 4096 + dc2 * 8;
#pragma unroll
            for (int r = 0; r < 4; r++) {
                cp16(sb2 + lso[r],         g_xhi + ab + lgo[r]);
                cp16(sb2 + S64_B + lso[r], g_ehi + bb + lgo[r]);
            }
            CP_COMMIT();
        } else {
            CP_COMMIT();
        }

        chunk_compute64(sb, f, acc);

        if (dc == 3) {
#pragma unroll
            for (int ma = 0; ma < 4; ma++) {
                int m_r = m0 + wm * 64 + ma * 16 + (lane >> 2);
                float xq0 = g_xsq[m_r];
                float xq1 = g_xsq[m_r + 8];
#pragma unroll
                for (int na = 0; na < 4; na++) {
                    int n0c = nt * 128 + wn * 32 + na * 8 + 2 * (lane & 3);
                    float e0 = g_esq[n0c], e1 = g_esq[n0c + 1];
                    float d00 = __fsub_rn(__fadd_rn(xq0, e0), 2.0f * acc[ma][na][0]);
                    float d01 = __fsub_rn(__fadd_rn(xq0, e1), 2.0f * acc[ma][na][1]);
                    float d10 = __fsub_rn(__fadd_rn(xq1, e0), 2.0f * acc[ma][na][2]);
                    float d11 = __fsub_rn(__fadd_rn(xq1, e1), 2.0f * acc[ma][na][3]);
                    upd2(tb1[ma * 2],     tb2[ma * 2],
                         ((ull)__float_as_uint(d00) << 32) | (unsigned)n0c);
                    upd2(tb1[ma * 2],     tb2[ma * 2],
                         ((ull)__float_as_uint(d01) << 32) | (unsigned)(n0c + 1));
                    upd2(tb1[ma * 2 + 1], tb2[ma * 2 + 1],
                         ((ull)__float_as_uint(d10) << 32) | (unsigned)n0c);
                    upd2(tb1[ma * 2 + 1], tb2[ma * 2 + 1],
                         ((ull)__float_as_uint(d11) << 32) | (unsigned)(n0c + 1));
                    acc[ma][na][0] = 0.f; acc[ma][na][1] = 0.f;
                    acc[ma][na][2] = 0.f; acc[ma][na][3] = 0.f;
                }
            }
        }
    }

    // global top-4 merge: 4 rounds of atomicMin with exclusion
    ull* best = reinterpret_cast<ull*>(dsm + OFF_AUX2);
    ull wlast[8];
#pragma unroll
    for (int i = 0; i < 8; i++) wlast[i] = 0ULL;

#pragma unroll 1
    for (int r = 0; r < 4; r++) {
        __syncthreads();
        if (tid < 128) best[tid] = UMAX64;
        __syncthreads();
#pragma unroll
        for (int i = 0; i < 8; i++) {
            int ma = i >> 1;
            int mloc = wm * 64 + ma * 16 + (lane >> 2) + (i & 1) * 8;
            ull cand = (tb1[i] > wlast[i]) ? tb1[i]
                     : ((tb2[i] > wlast[i]) ? tb2[i] : UMAX64);
            if (cand != UMAX64) atomicMin(&best[mloc], cand);
        }
        __syncthreads();
#pragma unroll
        for (int i = 0; i < 8; i++) {
            int ma = i >> 1;
            int mloc = wm * 64 + ma * 16 + (lane >> 2) + (i & 1) * 8;
            wlast[i] = best[mloc];
        }
        if (tid < 128) g_cand[r * MAXN + m0 + tid] = (int)(best[tid] & 0xFFFFFFFFu);
    }
}

// ---------------- k_finalize: exact rescore + quantized write + counts + MSE ----------------
__global__ void __launch_bounds__(256)
k_finalize(const float* __restrict__ x, const float* __restrict__ e,
           float* __restrict__ outq, float* __restrict__ outidx, int N) {
    __shared__ float smse[8];
    int wg   = threadIdx.x >> 5;
    int lane = threadIdx.x & 31;
    int w    = blockIdx.x * 8 + wg;

    int cc[4];
#pragma unroll
    for (int r = 0; r < 4; r++) cc[r] = g_cand[r * MAXN + w];

    const float4* xr = reinterpret_cast<const float4*>(x + (size_t)w * D);
    float4 a = xr[lane], b = xr[32 + lane];
    float4 u[4], v[4];
    float d[4];
#pragma unroll
    for (int r = 0; r < 4; r++) {
        const float4* er = reinterpret_cast<const float4*>(e + (size_t)cc[r] * D);
        u[r] = er[lane]; v[r] = er[32 + lane];
        d[r] = a.x*u[r].x + a.y*u[r].y + a.z*u[r].z + a.w*u[r].w
             + b.x*v[r].x + b.y*v[r].y + b.z*v[r].z + b.w*v[r].w;
    }
#pragma unroll
    for (int off = 16; off > 0; off >>= 1) {
#pragma unroll
        for (int r = 0; r < 4; r++) d[r] += __shfl_xor_sync(0xffffffffu, d[r], off);
    }

    float xq = g_xsq[w];
    ull bestc = UMAX64;
    int rwin = 0;
#pragma unroll
    for (int r = 0; r < 4; r++) {
        float dist = __fsub_rn(__fadd_rn(xq, g_esq[cc[r]]), 2.0f * d[r]);
        ull c = ((ull)__float_as_uint(dist) << 32) | (unsigned)cc[r];
        if (c < bestc) { bestc = c; rwin = r; }
    }
    int kwin = (int)(bestc & 0xFFFFFFFFu);

    float4 uw = u[0], vw = v[0];
    if (rwin == 1) { uw = u[1]; vw = v[1]; }
    if (rwin == 2) { uw = u[2]; vw = v[2]; }
    if (rwin == 3) { uw = u[3]; vw = v[3]; }
    float4* qr = reinterpret_cast<float4*>(outq + (size_t)w * D);
    qr[lane] = uw;
    qr[32 + lane] = vw;

    if (lane == 0) {
        outidx[w] = (float)kwin;
        atomicAdd(&g_counts[kwin], 1.0f);
        smse[wg] = __uint_as_float((unsigned)(bestc >> 32));
    }
    __syncthreads();
    if (threadIdx.x == 0) {
        float s = 0.f;
#pragma unroll
        for (int i = 0; i < 8; i++) s += smse[i];
        atomicAdd(&g_acc[0], s);
    }
}

// ================= k_sim (bf16x3, proven) =================
#define STG_SZ   32768
#define S_AHI    0
#define S_ALO    8192
#define S_BHI    16384
#define S_BLO    24576
#define OFF_AUX  65536
#define SMEM_SIM (65536 + 2048)

struct Frag {
    int aoff[4], akey[4], boff[2], bkey[2];
    int asub, bsub;
};
__device__ __forceinline__ void frag_init(Frag& f, int lane, int wm, int wn) {
    f.asub = lane >> 4;
    f.bsub = (lane >> 3) & 1;
#pragma unroll
    for (int ma = 0; ma < 4; ma++) {
        int row = wm * 64 + ma * 16 + ((lane >> 3) & 1) * 8 + (lane & 7);
        f.aoff[ma] = (row >> 1) * 128 + (row & 1) * 64;
        f.akey[ma] = (row >> 1) & 3;
    }
#pragma unroll
    for (int pr = 0; pr < 2; pr++) {
        int row = wn * 32 + pr * 16 + ((lane >> 4) & 1) * 8 + (lane & 7);
        f.boff[pr] = (row >> 1) * 128 + (row & 1) * 64;
        f.bkey[pr] = (row >> 1) & 3;
    }
}

__device__ __forceinline__ void stage_load_sim(uint32_t sb,
                                               int abase_g, int bbase_g, int tid) {
#pragma unroll
    for (int rep = 0; rep < 2; rep++) {
        int id  = tid + rep * 256;
        int row = id >> 2, g = id & 3;
        uint32_t so = fold_off(row, g);
        int fa = abase_g + row * 32 + g;
        int fb = bbase_g + row * 32 + g;
        cp16(sb + S_AHI + so, g_ehi + fa);
        cp16(sb + S_ALO + so, g_elo + fa);
        cp16(sb + S_BHI + so, g_ehi + fb);
        cp16(sb + S_BLO + so, g_elo + fb);
    }
}

__device__ __forceinline__ void chunk_compute_sim(uint32_t sb, const Frag& f,
                                                  float acc[4][4][4]) {
#pragma unroll
    for (int ks = 0; ks < 2; ks++) {
        int ga = ks * 2 + f.asub;
        int gb = ks * 2 + f.bsub;
        uint32_t ah[4][4], al[4][4], bh[4][2], bl[4][2];
#pragma unroll
        for (int ma = 0; ma < 4; ma++)
            ldsm_x4(ah[ma][0], ah[ma][1], ah[ma][2], ah[ma][3],
                    sb + S_AHI + f.aoff[ma] + (((ga ^ f.akey[ma]) & 3) << 4));
#pragma unroll
        for (int pr = 0; pr < 2; pr++) {
            uint32_t d0, d1, d2, d3;
            ldsm_x4(d0, d1, d2, d3,
                    sb + S_BHI + f.boff[pr] + (((gb ^ f.bkey[pr]) & 3) << 4));
            bh[2*pr][0] = d0; bh[2*pr][1] = d1;
            bh[2*pr+1][0] = d2; bh[2*pr+1][1] = d3;
        }
#pragma unroll
        for (int ma = 0; ma < 4; ma++)
#pragma unroll
            for (int na = 0; na < 4; na++)
                mma_bf16(acc[ma][na], ah[ma], bh[na]);
#pragma unroll
        for (int pr = 0; pr < 2; pr++) {
            uint32_t d0, d1, d2, d3;
            ldsm_x4(d0, d1, d2, d3,
                    sb + S_BLO + f.boff[pr] + (((gb ^ f.bkey[pr]) & 3) << 4));
            bl[2*pr][0] = d0; bl[2*pr][1] = d1;
            bl[2*pr+1][0] = d2; bl[2*pr+1][1] = d3;
        }
#pragma unroll
        for (int ma = 0; ma < 4; ma++)
#pragma unroll
            for (int na = 0; na < 4; na++)
                mma_bf16(acc[ma][na], ah[ma], bl[na]);
#pragma unroll
        for (int ma = 0; ma < 4; ma++)
            ldsm_x4(al[ma][0], al[ma][1], al[ma][2], al[ma][3],
                    sb + S_ALO + f.aoff[ma] + (((ga ^ f.akey[ma]) & 3) << 4));
#pragma unroll
        for (int ma = 0; ma < 4; ma++)
#pragma unroll
            for (int na = 0; na < 4; na++)
                mma_bf16(acc[ma][na], al[ma], bh[na]);
    }
}

__global__ void __launch_bounds__(256, 2)
k_sim_mma(int K) {
    extern __shared__ char dsm[];
    uint32_t smb = smem_u32(dsm);
    int tid  = threadIdx.x;
    int lane = tid & 31;
    int wid  = tid >> 5;
    int wm   = wid >> 2;
    int wn   = wid & 3;

    int nt_blocks = K / 128;
    int b = blockIdx.x, by = 0;
    while (b >= nt_blocks - by) { b -= nt_blocks - by; by++; }
    int bx = by + b;
    int m0 = by * 128, n0 = bx * 128;
    float wgt = (by == bx) ? 1.0f : 2.0f;

    Frag f; frag_init(f, lane, wm, wn);

    float acc[4][4][4];
#pragma unroll
    for (int ma = 0; ma < 4; ma++)
#pragma unroll
        for (int na = 0; na < 4; na++)
#pragma unroll
            for (int c = 0; c < 4; c++) acc[ma][na][c] = 0.f;

    stage_load_sim(smb, m0 * 32, n0 * 32, tid);
    CP_COMMIT();

#pragma unroll 1
    for (int dc = 0; dc < 8; dc++) {
        uint32_t sb = smb + (dc & 1) * STG_SZ;
        CP_WAIT0();
        __syncthreads();
        if (dc + 1 < 8) {
            stage_load_sim(smb + ((dc + 1) & 1) * STG_SZ,
                           m0 * 32 + (dc + 1) * 4, n0 * 32 + (dc + 1) * 4, tid);
            CP_COMMIT();
        } else {
            CP_COMMIT();
        }
        chunk_compute_sim(sb, f, acc);
    }

    float s = 0.f;
#pragma unroll
    for (int ma = 0; ma < 4; ma++) {
        int m_r0 = m0 + wm * 64 + ma * 16 + (lane >> 2);
        float r0 = g_rninv[m_r0], r1 = g_rninv[m_r0 + 8];
#pragma unroll
        for (int na = 0; na < 4; na++) {
            int n0c = n0 + wn * 32 + na * 8 + 2 * (lane & 3);
            float q0 = g_rninv[n0c], q1 = g_rninv[n0c + 1];
            float s00 = fabsf(acc[ma][na][0] * r0 * q0);
            float s01 = fabsf(acc[ma][na][1] * r0 * q1);
            float s10 = fabsf(acc[ma][na][2] * r1 * q0);
            float s11 = fabsf(acc[ma][na][3] * r1 * q1);
            if (m_r0     == n0c)     s00 = 0.f;
            if (m_r0     == n0c + 1) s01 = 0.f;
            if (m_r0 + 8 == n0c)     s10 = 0.f;
            if (m_r0 + 8 == n0c + 1) s11 = 0.f;
            s += (s00 + s01) + (s10 + s11);
        }
    }
    s *= wgt;

    float* red = reinterpret_cast<float*>(dsm + OFF_AUX);
    __syncthreads();
    red[tid] = s; __syncthreads();
    for (int st = 128; st > 0; st >>= 1) { if (tid < st) red[tid] += red[tid + st]; __syncthreads(); }
    if (tid == 0) atomicAdd(&g_acc[1], red[0]);
}

// ---------------- k_final ----------------
__global__ void k_final(float* __restrict__ out_loss, float* __restrict__ out_perp, int N, int K) {
    __shared__ float sA[256], sB[256], sC[256];
    int tid = threadIdx.x;

    float tot = 0.f;
    for (int k = tid; k < K; k += 256) tot += g_counts[k];
    sA[tid] = tot; __syncthreads();
    for (int st = 128; st > 0; st >>= 1) { if (tid < st) sA[tid] += sA[tid + st]; __syncthreads(); }
    float total = sA[0];
    __syncthreads();

    float tuni = 1.0f / (float)K;
    float kl = 0.f, pl = 0.f;
    for (int k = tid; k < K; k += 256) {
        float p = g_counts[k] / total;
        kl += (p + EPS_F) * logf((p + EPS_F) / (tuni + EPS_F));
        if (p > 0.f) pl += p * logf(p);
    }
    sB[tid] = kl; sC[tid] = pl; __syncthreads();
    for (int st = 128; st > 0; st >>= 1) {
        if (tid < st) { sB[tid] += sB[tid + st]; sC[tid] += sC[tid + st]; }
        __syncthreads();
    }
    if (tid == 0) {
        float klv = fminf(sB[0], 100.0f);
        float mse = g_acc[0] / ((float)N * (float)D);
        float vq  = mse + COMMIT_COST * mse;
        float l2  = fminf(g_acc[2] / (float)K, 10.0f);
        float orth = fminf(g_acc[1] / ((float)K * (float)K), 10.0f);
        float reg = l2 + orth;
        float loss = fminf(vq + DIV_GAMMA * klv + 0.01f * reg, 100.0f);
        *out_loss = loss;
        *out_perp = expf(-sC[0]);
    }
}

// ---------------- launch ----------------
extern "C" void kernel_launch(void* const* d_in, const int* in_sizes, int n_in,
                              void* d_out, int out_size) {
    const float* x = (const float*)d_in[0];
    const float* e = (const float*)d_in[1];
    float* out = (float*)d_out;

    int N = in_sizes[0] / D;   // 65536
    int K = in_sizes[1] / D;   // 2048
    if (N > MAXN) N = MAXN;
    if (K > MAXK) K = MAXK;

    float* out_q    = out;
    float* out_loss = out + (size_t)N * D;
    float* out_perp = out_loss + 1;
    float* out_idx  = out_perp + 1;

    cudaFuncSetAttribute(k_argmin_b1, cudaFuncAttributeMaxDynamicSharedMemorySize, SMEM_ARG);
    cudaFuncSetAttribute(k_sim_mma,   cudaFuncAttributeMaxDynamicSharedMemorySize, SMEM_SIM);

    int ntb = K / 128;
    int tri = ntb * (ntb + 1) / 2;

    k_init     <<<(K + 255) / 256, 256>>>(K);
    k_prep_e   <<<(K + 7) / 8, 256>>>((const float4*)e, K);
    k_prep_x   <<<(N + 7) / 8, 256>>>((const float4*)x, N);
    k_argmin_b1<<<N / 128, 256, SMEM_ARG>>>(N, K);
    k_finalize <<<N / 8, 256>>>(x, e, out_q, out_idx, N);
    k_sim_mma  <<<tri, 256, SMEM_SIM>>>(K);
    k_final    <<<1, 256>>>(out_loss, out_perp, N, K);
}

// round 15
// speedup vs baseline: 4.6550x; 1.1936x over previous
#include <cuda_runtime.h>
#include <cuda_bf16.h>
#include <cstdint>

#define D    256
#define MAXK 2048
#define MAXN 65536

#define COMMIT_COST 0.25f
#define DIV_GAMMA   0.1f
#define EPS_F       1e-8f

typedef unsigned long long ull;
#define UMAX64 0xFFFFFFFFFFFFFFFFULL

// ---------------- device scratch ----------------
__device__ float g_esq[MAXK];
__device__ float g_esqh[MAXK];     // 0.5 * esq (for m-form filter compare)
__device__ float g_rninv[MAXK];
__device__ float g_xsq[MAXN];
__device__ int   g_cand[4 * MAXN];
__device__ float g_counts[MAXK];
__device__ float g_acc[4];

// bf16 splits (16B granules of 8 bf16). x: hi only. e: hi + lo (lo for k_sim).
__device__ uint4 g_xhi[MAXN * D / 8];
__device__ uint4 g_ehi[MAXK * D / 8];
__device__ uint4 g_elo[MAXK * D / 8];

// ---------------- helpers ----------------
__device__ __forceinline__ uint32_t smem_u32(const void* p) {
    uint32_t a;
    asm("{ .reg .u64 t; cvta.to.shared.u64 t, %1; cvt.u32.u64 %0, t; }" : "=r"(a) : "l"(p));
    return a;
}
__device__ __forceinline__ void ldsm_x4(uint32_t& d0, uint32_t& d1, uint32_t& d2, uint32_t& d3,
                                        uint32_t addr) {
    asm volatile("ldmatrix.sync.aligned.m8n8.x4.shared.b16 {%0,%1,%2,%3}, [%4];"
        : "=r"(d0), "=r"(d1), "=r"(d2), "=r"(d3) : "r"(addr));
}
__device__ __forceinline__ void mma_bf16(float* c, const uint32_t* a, const uint32_t* b) {
    asm volatile(
        "mma.sync.aligned.m16n8k16.row.col.f32.bf16.bf16.f32 "
        "{%0,%1,%2,%3}, {%4,%5,%6,%7}, {%8,%9}, {%0,%1,%2,%3};"
        : "+f"(c[0]), "+f"(c[1]), "+f"(c[2]), "+f"(c[3])
        : "r"(a[0]), "r"(a[1]), "r"(a[2]), "r"(a[3]), "r"(b[0]), "r"(b[1]));
}
__device__ __forceinline__ void cp16(uint32_t dst, const void* src) {
    asm volatile("{ .reg .u64 g; cvta.to.global.u64 g, %1; "
                 "cp.async.cg.shared.global [%0], [g], 16; }"
                 :: "r"(dst), "l"(src) : "memory");
}
#define CP_COMMIT() asm volatile("cp.async.commit_group;" ::: "memory")
#define CP_WAIT0()  asm volatile("cp.async.wait_group 0;" ::: "memory")
#define CP_WAIT1()  asm volatile("cp.async.wait_group 1;" ::: "memory")

__device__ __forceinline__ uint32_t fold_off(int row, int g) {
    return (uint32_t)((row >> 1) * 128 + (row & 1) * 64 + ((g ^ ((row >> 1) & 3)) << 4));
}
// sortable-float: monotone unsigned image of float ordering
__device__ __forceinline__ unsigned sortf(float m) {
    unsigned b = __float_as_uint(m);
    return b ^ (unsigned)(((int)b >> 31) | 0x80000000);
}
// u32 top-2 update: 2 umin + setp + sel
__device__ __forceinline__ void upd2u(unsigned& b1, unsigned& b2, unsigned c) {
    unsigned t = umin(c, b2);
    b2 = (c < b1) ? b1 : t;
    b1 = umin(c, b1);
}

// ---------------- k_init ----------------
__global__ void k_init(int K) {
    int i = blockIdx.x * blockDim.x + threadIdx.x;
    if (i < K) g_counts[i] = 0.f;
    if (i < 4) g_acc[i] = 0.f;
}

// ---------------- k_prep_e: esq, esq/2, rninv, rn-sum, bf16 hi/lo split ----------------
__global__ void k_prep_e(const float4* __restrict__ e4, int K) {
    int w    = (blockIdx.x * blockDim.x + threadIdx.x) >> 5;
    int lane = threadIdx.x & 31;
    if (w >= K) return;
    const float4* er = e4 + (size_t)w * 64;
    float4 a = er[2 * lane], b = er[2 * lane + 1];
    float f[8] = {a.x, a.y, a.z, a.w, b.x, b.y, b.z, b.w};
    float s = 0.f;
#pragma unroll
    for (int j = 0; j < 8; j++) s += f[j] * f[j];
#pragma unroll
    for (int off = 16; off > 0; off >>= 1) s += __shfl_xor_sync(0xffffffffu, s, off);

    unsigned h[8], l[8];
#pragma unroll
    for (int j = 0; j < 8; j++) {
        __nv_bfloat16 hb = __float2bfloat16(f[j]);
        float hf = __bfloat162float(hb);
        h[j] = __bfloat16_as_ushort(hb);
        l[j] = __bfloat16_as_ushort(__float2bfloat16(f[j] - hf));
    }
    g_ehi[w * 32 + lane] = make_uint4(h[0] | (h[1] << 16), h[2] | (h[3] << 16),
                                      h[4] | (h[5] << 16), h[6] | (h[7] << 16));
    g_elo[w * 32 + lane] = make_uint4(l[0] | (l[1] << 16), l[2] | (l[3] << 16),
                                      l[4] | (l[5] << 16), l[6] | (l[7] << 16));
    if (lane == 0) {
        g_esq[w]  = s;
        g_esqh[w] = 0.5f * s;
        float rn = sqrtf(s);
        g_rninv[w] = 1.0f / fmaxf(rn, 1e-12f);
        atomicAdd(&g_acc[2], rn);
    }
}

// ---------------- k_prep_x: xsq + bf16 hi split ----------------
__global__ void k_prep_x(const float4* __restrict__ x4, int N) {
    int w    = (blockIdx.x * blockDim.x + threadIdx.x) >> 5;
    int lane = threadIdx.x & 31;
    if (w >= N) return;
    const float4* xr = x4 + (size_t)w * 64;
    float4 a = xr[2 * lane], b = xr[2 * lane + 1];
    float f[8] = {a.x, a.y, a.z, a.w, b.x, b.y, b.z, b.w};
    float s = 0.f;
#pragma unroll
    for (int j = 0; j < 8; j++) s += f[j] * f[j];
#pragma unroll
    for (int off = 16; off > 0; off >>= 1) s += __shfl_xor_sync(0xffffffffu, s, off);
    unsigned h[8];
#pragma unroll
    for (int j = 0; j < 8; j++) h[j] = __bfloat16_as_ushort(__float2bfloat16(f[j]));
    g_xhi[w * 32 + lane] = make_uint4(h[0] | (h[1] << 16), h[2] | (h[3] << 16),
                                      h[4] | (h[5] << 16), h[6] | (h[7] << 16));
    if (lane == 0) g_xsq[w] = s;
}

// ================= k_argmin: single-pass xh·eh, k64 chunks, u32 top-2 filter =================
#define STG64    32768
#define S64_B    16384
#define OFF_AUX2 98304
#define SMEM_ARG (98304 + 2048)

struct Frag2 {
    int aoff[4], akey[4], boff[2], bkey[2];
    int asub, bsub;
};
__device__ __forceinline__ void frag_init2(Frag2& f, int lane, int wm, int wn) {
    f.asub = lane >> 4;
    f.bsub = (lane >> 3) & 1;
#pragma unroll
    for (int ma = 0; ma < 4; ma++) {
        int row = wm * 64 + ma * 16 + ((lane >> 3) & 1) * 8 + (lane & 7);
        f.aoff[ma] = row * 128;
        f.akey[ma] = row & 7;
    }
#pragma unroll
    for (int pr = 0; pr < 2; pr++) {
        int row = wn * 32 + pr * 16 + ((lane >> 4) & 1) * 8 + (lane & 7);
        f.boff[pr] = S64_B + row * 128;
        f.bkey[pr] = row & 7;
    }
}

__device__ __forceinline__ void chunk_compute64(uint32_t sb, const Frag2& f,
                                                float acc[4][4][4]) {
#pragma unroll
    for (int ks = 0; ks < 4; ks++) {
        int ga = ks * 2 + f.asub;
        int gb = ks * 2 + f.bsub;
        uint32_t ah[4][4], bh[4][2];
#pragma unroll
        for (int ma = 0; ma < 4; ma++)
            ldsm_x4(ah[ma][0], ah[ma][1], ah[ma][2], ah[ma][3],
                    sb + f.aoff[ma] + (((ga ^ f.akey[ma]) & 7) << 4));
#pragma unroll
        for (int pr = 0; pr < 2; pr++) {
            uint32_t d0, d1, d2, d3;
            ldsm_x4(d0, d1, d2, d3,
                    sb + f.boff[pr] + (((gb ^ f.bkey[pr]) & 7) << 4));
            bh[2*pr][0] = d0; bh[2*pr][1] = d1;
            bh[2*pr+1][0] = d2; bh[2*pr+1][1] = d3;
        }
#pragma unroll
        for (int ma = 0; ma < 4; ma++)
#pragma unroll
            for (int na = 0; na < 4; na++)
                mma_bf16(acc[ma][na], ah[ma], bh[na]);
    }
}

__global__ void __launch_bounds__(256, 2)
k_argmin_b1(int N, int K) {
    extern __shared__ char dsm[];
    uint32_t smb = smem_u32(dsm);
    int tid  = threadIdx.x;
    int lane = tid & 31;
    int wid  = tid >> 5;
    int wm   = wid >> 2;
    int wn   = wid & 3;
    int m0   = blockIdx.x * 128;

    Frag2 f; frag_init2(f, lane, wm, wn);

    // hoisted loader addressing
    uint32_t lso[4];
    int      lgo[4];
#pragma unroll
    for (int r = 0; r < 4; r++) {
        int id  = tid + r * 256;
        int row = id >> 3, g = id & 7;
        lso[r] = (uint32_t)(row * 128 + ((g ^ (row & 7)) << 4));
        lgo[r] = row * 32 + g;
    }

    unsigned tb1[8], tb2[8];
#pragma unroll
    for (int i = 0; i < 8; i++) { tb1[i] = 0xFFFFFFFFu; tb2[i] = 0xFFFFFFFFu; }

    int NT = K / 128;
    int C  = NT * 4;
    int am0 = m0 * 32;

#pragma unroll
    for (int p = 0; p < 2; p++) {
        uint32_t sb = smb + p * STG64;
        int ab = am0 + p * 8;
        int bb = p * 8;
#pragma unroll
        for (int r = 0; r < 4; r++) {
            cp16(sb + lso[r],         g_xhi + ab + lgo[r]);
            cp16(sb + S64_B + lso[r], g_ehi + bb + lgo[r]);
        }
        CP_COMMIT();
    }

    float acc[4][4][4];
#pragma unroll
    for (int ma = 0; ma < 4; ma++)
#pragma unroll
        for (int na = 0; na < 4; na++)
#pragma unroll
            for (int c = 0; c < 4; c++) acc[ma][na][c] = 0.f;

#pragma unroll 1
    for (int c = 0; c < C; c++) {
        int nt = c >> 2, dc = c & 3;
        uint32_t sb = smb + (c % 3) * STG64;

        CP_WAIT1();
        __syncthreads();

        if (c + 2 < C) {
            int c2 = c + 2;
            int nt2 = c2 >> 2, dc2 = c2 & 3;
            uint32_t sb2 = smb + (c2 % 3) * STG64;
            int ab = am0 + dc2 * 8;
            int bb = nt2 * 4096 + dc2 * 8;
#pragma unroll
            for (int r = 0; r < 4; r++) {
                cp16(sb2 + lso[r],         g_xhi + ab + lgo[r]);
                cp16(sb2 + S64_B + lso[r], g_ehi + bb + lgo[r]);
            }
            CP_COMMIT();
        } else {
            CP_COMMIT();
        }

        chunk_compute64(sb, f, acc);

        if (dc == 3) {
            // m-form epilogue: minimize m = esq/2 - dot (ordering == dist ordering per token)
            int base = nt * 128 + wn * 32 + 2 * (lane & 3);
            unsigned nt8 = (unsigned)(nt << 3);
#pragma unroll
            for (int na = 0; na < 4; na++) {
                int n0c = base + na * 8;
                float he0 = g_esqh[n0c], he1 = g_esqh[n0c + 1];
                unsigned id0 = nt8 + 2 * na;
                unsigned id1 = id0 + 1;
#pragma unroll
                for (int ma = 0; ma < 4; ma++) {
                    unsigned p00 = (sortf(he0 - acc[ma][na][0]) & 0xFFFFFF80u) | id0;
                    unsigned p01 = (sortf(he1 - acc[ma][na][1]) & 0xFFFFFF80u) | id1;
                    unsigned p10 = (sortf(he0 - acc[ma][na][2]) & 0xFFFFFF80u) | id0;
                    unsigned p11 = (sortf(he1 - acc[ma][na][3]) & 0xFFFFFF80u) | id1;
                    upd2u(tb1[ma * 2],     tb2[ma * 2],     p00);
                    upd2u(tb1[ma * 2],     tb2[ma * 2],     p01);
                    upd2u(tb1[ma * 2 + 1], tb2[ma * 2 + 1], p10);
                    upd2u(tb1[ma * 2 + 1], tb2[ma * 2 + 1], p11);
                    acc[ma][na][0] = 0.f; acc[ma][na][1] = 0.f;
                    acc[ma][na][2] = 0.f; acc[ma][na][3] = 0.f;
                }
            }
        }
    }

    // decode thread-local candidates -> u64 (sortable_m | global idx)
    unsigned nbase = (unsigned)(wn * 32 + 2 * (lane & 3));
    ull c1[8], c2[8];
#pragma unroll
    for (int i = 0; i < 8; i++) {
        unsigned ida = tb1[i] & 127u;
        unsigned idb = tb2[i] & 127u;
        unsigned ga = ((ida >> 3) << 7) + nbase + (((ida >> 1) & 3u) << 3) + (ida & 1u);
        unsigned gb = ((idb >> 3) << 7) + nbase + (((idb >> 1) & 3u) << 3) + (idb & 1u);
        c1[i] = ((ull)(tb1[i] & 0xFFFFFF80u) << 32) | ga;
        c2[i] = ((ull)(tb2[i] & 0xFFFFFF80u) << 32) | gb;
    }

    // global top-4 merge: 4 rounds of atomicMin with exclusion
    ull* best = reinterpret_cast<ull*>(dsm + OFF_AUX2);
    ull wlast[8];
#pragma unroll
    for (int i = 0; i < 8; i++) wlast[i] = 0ULL;

#pragma unroll 1
    for (int r = 0; r < 4; r++) {
        __syncthreads();
        if (tid < 128) best[tid] = UMAX64;
        __syncthreads();
#pragma unroll
        for (int i = 0; i < 8; i++) {
            int ma = i >> 1;
            int mloc = wm * 64 + ma * 16 + (lane >> 2) + (i & 1) * 8;
            ull cand = (c1[i] > wlast[i]) ? c1[i]
                     : ((c2[i] > wlast[i]) ? c2[i] : UMAX64);
            if (cand != UMAX64) atomicMin(&best[mloc], cand);
        }
        __syncthreads();
#pragma unroll
        for (int i = 0; i < 8; i++) {
            int ma = i >> 1;
            int mloc = wm * 64 + ma * 16 + (lane >> 2) + (i & 1) * 8;
            wlast[i] = best[mloc];
        }
        if (tid < 128) g_cand[r * MAXN + m0 + tid] = (int)(best[tid] & 0xFFFFFFFFu);
    }
}

// ---------------- k_finalize: exact rescore + quantized write + counts + MSE ----------------
__global__ void __launch_bounds__(256)
k_finalize(const float* __restrict__ x, const float* __restrict__ e,
           float* __restrict__ outq, float* __restrict__ outidx, int N) {
    __shared__ float smse[8];
    int wg   = threadIdx.x >> 5;
    int lane = threadIdx.x & 31;
    int w    = blockIdx.x * 8 + wg;

    int cc[4];
#pragma unroll
    for (int r = 0; r < 4; r++) cc[r] = g_cand[r * MAXN + w];

    const float4* xr = reinterpret_cast<const float4*>(x + (size_t)w * D);
    float4 a = xr[lane], b = xr[32 + lane];
    float4 u[4], v[4];
    float d[4];
#pragma unroll
    for (int r = 0; r < 4; r++) {
        const float4* er = reinterpret_cast<const float4*>(e + (size_t)cc[r] * D);
        u[r] = er[lane]; v[r] = er[32 + lane];
        d[r] = a.x*u[r].x + a.y*u[r].y + a.z*u[r].z + a.w*u[r].w
             + b.x*v[r].x + b.y*v[r].y + b.z*v[r].z + b.w*v[r].w;
    }
#pragma unroll
    for (int off = 16; off > 0; off >>= 1) {
#pragma unroll
        for (int r = 0; r < 4; r++) d[r] += __shfl_xor_sync(0xffffffffu, d[r], off);
    }

    float xq = g_xsq[w];
    ull bestc = UMAX64;
    int rwin = 0;
#pragma unroll
    for (int r = 0; r < 4; r++) {
        float dist = __fsub_rn(__fadd_rn(xq, g_esq[cc[r]]), 2.0f * d[r]);
        ull c = ((ull)__float_as_uint(dist) << 32) | (unsigned)cc[r];
        if (c < bestc) { bestc = c; rwin = r; }
    }
    int kwin = (int)(bestc & 0xFFFFFFFFu);

    float4 uw = u[0], vw = v[0];
    if (rwin == 1) { uw = u[1]; vw = v[1]; }
    if (rwin == 2) { uw = u[2]; vw = v[2]; }
    if (rwin == 3) { uw = u[3]; vw = v[3]; }
    float4* qr = reinterpret_cast<float4*>(outq + (size_t)w * D);
    qr[lane] = uw;
    qr[32 + lane] = vw;

    if (lane == 0) {
        outidx[w] = (float)kwin;
        atomicAdd(&g_counts[kwin], 1.0f);
        smse[wg] = __uint_as_float((unsigned)(bestc >> 32));
    }
    __syncthreads();
    if (threadIdx.x == 0) {
        float s = 0.f;
#pragma unroll
        for (int i = 0; i < 8; i++) s += smse[i];
        atomicAdd(&g_acc[0], s);
    }
}

// ================= k_sim (bf16x3, proven) =================
#define STG_SZ   32768
#define S_AHI    0
#define S_ALO    8192
#define S_BHI    16384
#define S_BLO    24576
#define OFF_AUX  65536
#define SMEM_SIM (65536 + 2048)

struct Frag {
    int aoff[4], akey[4], boff[2], bkey[2];
    int asub, bsub;
};
__device__ __forceinline__ void frag_init(Frag& f, int lane, int wm, int wn) {
    f.asub = lane >> 4;
    f.bsub = (lane >> 3) & 1;
#pragma unroll
    for (int ma = 0; ma < 4; ma++) {
        int row = wm * 64 + ma * 16 + ((lane >> 3) & 1) * 8 + (lane & 7);
        f.aoff[ma] = (row >> 1) * 128 + (row & 1) * 64;
        f.akey[ma] = (row >> 1) & 3;
    }
#pragma unroll
    for (int pr = 0; pr < 2; pr++) {
        int row = wn * 32 + pr * 16 + ((lane >> 4) & 1) * 8 + (lane & 7);
        f.boff[pr] = (row >> 1) * 128 + (row & 1) * 64;
        f.bkey[pr] = (row >> 1) & 3;
    }
}

__device__ __forceinline__ void stage_load_sim(uint32_t sb,
                                               int abase_g, int bbase_g, int tid) {
#pragma unroll
    for (int rep = 0; rep < 2; rep++) {
        int id  = tid + rep * 256;
        int row = id >> 2, g = id & 3;
        uint32_t so = fold_off(row, g);
        int fa = abase_g + row * 32 + g;
        int fb = bbase_g + row * 32 + g;
        cp16(sb + S_AHI + so, g_ehi + fa);
        cp16(sb + S_ALO + so, g_elo + fa);
        cp16(sb + S_BHI + so, g_ehi + fb);
        cp16(sb + S_BLO + so, g_elo + fb);
    }
}

__device__ __forceinline__ void chunk_compute_sim(uint32_t sb, const Frag& f,
                                                  float acc[4][4][4]) {
#pragma unroll
    for (int ks = 0; ks < 2; ks++) {
        int ga = ks * 2 + f.asub;
        int gb = ks * 2 + f.bsub;
        uint32_t ah[4][4], al[4][4], bh[4][2], bl[4][2];
#pragma unroll
        for (int ma = 0; ma < 4; ma++)
            ldsm_x4(ah[ma][0], ah[ma][1], ah[ma][2], ah[ma][3],
                    sb + S_AHI + f.aoff[ma] + (((ga ^ f.akey[ma]) & 3) << 4));
#pragma unroll
        for (int pr = 0; pr < 2; pr++) {
            uint32_t d0, d1, d2, d3;
            ldsm_x4(d0, d1, d2, d3,
                    sb + S_BHI + f.boff[pr] + (((gb ^ f.bkey[pr]) & 3) << 4));
            bh[2*pr][0] = d0; bh[2*pr][1] = d1;
            bh[2*pr+1][0] = d2; bh[2*pr+1][1] = d3;
        }
#pragma unroll
        for (int ma = 0; ma < 4; ma++)
#pragma unroll
            for (int na = 0; na < 4; na++)
                mma_bf16(acc[ma][na], ah[ma], bh[na]);
#pragma unroll
        for (int pr = 0; pr < 2; pr++) {
            uint32_t d0, d1, d2, d3;
            ldsm_x4(d0, d1, d2, d3,
                    sb + S_BLO + f.boff[pr] + (((gb ^ f.bkey[pr]) & 3) << 4));
            bl[2*pr][0] = d0; bl[2*pr][1] = d1;
            bl[2*pr+1][0] = d2; bl[2*pr+1][1] = d3;
        }
#pragma unroll
        for (int ma = 0; ma < 4; ma++)
#pragma unroll
            for (int na = 0; na < 4; na++)
                mma_bf16(acc[ma][na], ah[ma], bl[na]);
#pragma unroll
        for (int ma = 0; ma < 4; ma++)
            ldsm_x4(al[ma][0], al[ma][1], al[ma][2], al[ma][3],
                    sb + S_ALO + f.aoff[ma] + (((ga ^ f.akey[ma]) & 3) << 4));
#pragma unroll
        for (int ma = 0; ma < 4; ma++)
#pragma unroll
            for (int na = 0; na < 4; na++)
                mma_bf16(acc[ma][na], al[ma], bh[na]);
    }
}

__global__ void __launch_bounds__(256, 2)
k_sim_mma(int K) {
    extern __shared__ char dsm[];
    uint32_t smb = smem_u32(dsm);
    int tid  = threadIdx.x;
    int lane = tid & 31;
    int wid  = tid >> 5;
    int wm   = wid >> 2;
    int wn   = wid & 3;

    int nt_blocks = K / 128;
    int b = blockIdx.x, by = 0;
    while (b >= nt_blocks - by) { b -= nt_blocks - by; by++; }
    int bx = by + b;
    int m0 = by * 128, n0 = bx * 128;
    float wgt = (by == bx) ? 1.0f : 2.0f;

    Frag f; frag_init(f, lane, wm, wn);

    float acc[4][4][4];
#pragma unroll
    for (int ma = 0; ma < 4; ma++)
#pragma unroll
        for (int na = 0; na < 4; na++)
#pragma unroll
            for (int c = 0; c < 4; c++) acc[ma][na][c] = 0.f;

    stage_load_sim(smb, m0 * 32, n0 * 32, tid);
    CP_COMMIT();

#pragma unroll 1
    for (int dc = 0; dc < 8; dc++) {
        uint32_t sb = smb + (dc & 1) * STG_SZ;
        CP_WAIT0();
        __syncthreads();
        if (dc + 1 < 8) {
            stage_load_sim(smb + ((dc + 1) & 1) * STG_SZ,
                           m0 * 32 + (dc + 1) * 4, n0 * 32 + (dc + 1) * 4, tid);
            CP_COMMIT();
        } else {
            CP_COMMIT();
        }
        chunk_compute_sim(sb, f, acc);
    }

    float s = 0.f;
#pragma unroll
    for (int ma = 0; ma < 4; ma++) {
        int m_r0 = m0 + wm * 64 + ma * 16 + (lane >> 2);
        float r0 = g_rninv[m_r0], r1 = g_rninv[m_r0 + 8];
#pragma unroll
        for (int na = 0; na < 4; na++) {
            int n0c = n0 + wn * 32 + na * 8 + 2 * (lane & 3);
            float q0 = g_rninv[n0c], q1 = g_rninv[n0c + 1];
            float s00 = fabsf(acc[ma][na][0] * r0 * q0);
            float s01 = fabsf(acc[ma][na][1] * r0 * q1);
            float s10 = fabsf(acc[ma][na][2] * r1 * q0);
            float s11 = fabsf(acc[ma][na][3] * r1 * q1);
            if (m_r0     == n0c)     s00 = 0.f;
            if (m_r0     == n0c + 1) s01 = 0.f;
            if (m_r0 + 8 == n0c)     s10 = 0.f;
            if (m_r0 + 8 == n0c + 1) s11 = 0.f;
            s += (s00 + s01) + (s10 + s11);
        }
    }
    s *= wgt;

    float* red = reinterpret_cast<float*>(dsm + OFF_AUX);
    __syncthreads();
    red[tid] = s; __syncthreads();
    for (int st = 128; st > 0; st >>= 1) { if (tid < st) red[tid] += red[tid + st]; __syncthreads(); }
    if (tid == 0) atomicAdd(&g_acc[1], red[0]);
}

// ---------------- k_final ----------------
__global__ void k_final(float* __restrict__ out_loss, float* __restrict__ out_perp, int N, int K) {
    __shared__ float sA[256], sB[256], sC[256];
    int tid = threadIdx.x;

    float tot = 0.f;
    for (int k = tid; k < K; k += 256) tot += g_counts[k];
    sA[tid] = tot; __syncthreads();
    for (int st = 128; st > 0; st >>= 1) { if (tid < st) sA[tid] += sA[tid + st]; __syncthreads(); }
    float total = sA[0];
    __syncthreads();

    float tuni = 1.0f / (float)K;
    float kl = 0.f, pl = 0.f;
    for (int k = tid; k < K; k += 256) {
        float p = g_counts[k] / total;
        kl += (p + EPS_F) * logf((p + EPS_F) / (tuni + EPS_F));
        if (p > 0.f) pl += p * logf(p);
    }
    sB[tid] = kl; sC[tid] = pl; __syncthreads();
    for (int st = 128; st > 0; st >>= 1) {
        if (tid < st) { sB[tid] += sB[tid + st]; sC[tid] += sC[tid + st]; }
        __syncthreads();
    }
    if (tid == 0) {
        float klv = fminf(sB[0], 100.0f);
        float mse = g_acc[0] / ((float)N * (float)D);
        float vq  = mse + COMMIT_COST * mse;
        float l2  = fminf(g_acc[2] / (float)K, 10.0f);
        float orth = fminf(g_acc[1] / ((float)K * (float)K), 10.0f);
        float reg = l2 + orth;
        float loss = fminf(vq + DIV_GAMMA * klv + 0.01f * reg, 100.0f);
        *out_loss = loss;
        *out_perp = expf(-sC[0]);
    }
}

// ---------------- launch ----------------
extern "C" void kernel_launch(void* const* d_in, const int* in_sizes, int n_in,
                              void* d_out, int out_size) {
    const float* x = (const float*)d_in[0];
    const float* e = (const float*)d_in[1];
    float* out = (float*)d_out;

    int N = in_sizes[0] / D;   // 65536
    int K = in_sizes[1] / D;   // 2048
    if (N > MAXN) N = MAXN;
    if (K > MAXK) K = MAXK;

    float* out_q    = out;
    float* out_loss = out + (size_t)N * D;
    float* out_perp = out_loss + 1;
    float* out_idx  = out_perp + 1;

    cudaFuncSetAttribute(k_argmin_b1, cudaFuncAttributeMaxDynamicSharedMemorySize, SMEM_ARG);
    cudaFuncSetAttribute(k_sim_mma,   cudaFuncAttributeMaxDynamicSharedMemorySize, SMEM_SIM);

    int ntb = K / 128;
    int tri = ntb * (ntb + 1) / 2;

    k_init     <<<(K + 255) / 256, 256>>>(K);
    k_prep_e   <<<(K + 7) / 8, 256>>>((const float4*)e, K);
    k_prep_x   <<<(N + 7) / 8, 256>>>((const float4*)x, N);
    k_argmin_b1<<<N / 128, 256, SMEM_ARG>>>(N, K);
    k_finalize <<<N / 8, 256>>>(x, e, out_q, out_idx, N);
    k_sim_mma  <<<tri, 256, SMEM_SIM>>>(K);
    k_final    <<<1, 256>>>(out_loss, out_perp, N, K);
}

// round 16
// speedup vs baseline: 4.7444x; 1.0192x over previous
#include <cuda_runtime.h>
#include <cuda_bf16.h>
#include <cstdint>

#define D    256
#define MAXK 2048
#define MAXN 65536

#define COMMIT_COST 0.25f
#define DIV_GAMMA   0.1f
#define EPS_F       1e-8f

typedef unsigned long long ull;
#define UMAX64 0xFFFFFFFFFFFFFFFFULL

// ---------------- device scratch ----------------
__device__ float g_esq[MAXK];
__device__ float g_esqh[MAXK];     // 0.5 * esq (m-form filter compare)
__device__ float g_rninv[MAXK];
__device__ float g_xsq[MAXN];
__device__ int   g_cand[4 * MAXN];
__device__ float g_counts[MAXK];
__device__ float g_acc[4];

// bf16 splits (16B granules of 8 bf16). x: hi only. e: hi + lo (lo for k_sim).
__device__ uint4 g_xhi[MAXN * D / 8];
__device__ uint4 g_ehi[MAXK * D / 8];
__device__ uint4 g_elo[MAXK * D / 8];

// ---------------- helpers ----------------
__device__ __forceinline__ uint32_t smem_u32(const void* p) {
    uint32_t a;
    asm("{ .reg .u64 t; cvta.to.shared.u64 t, %1; cvt.u32.u64 %0, t; }" : "=r"(a) : "l"(p));
    return a;
}
__device__ __forceinline__ void ldsm_x4(uint32_t& d0, uint32_t& d1, uint32_t& d2, uint32_t& d3,
                                        uint32_t addr) {
    asm volatile("ldmatrix.sync.aligned.m8n8.x4.shared.b16 {%0,%1,%2,%3}, [%4];"
        : "=r"(d0), "=r"(d1), "=r"(d2), "=r"(d3) : "r"(addr));
}
__device__ __forceinline__ void mma_bf16(float* c, const uint32_t* a, const uint32_t* b) {
    asm volatile(
        "mma.sync.aligned.m16n8k16.row.col.f32.bf16.bf16.f32 "
        "{%0,%1,%2,%3}, {%4,%5,%6,%7}, {%8,%9}, {%0,%1,%2,%3};"
        : "+f"(c[0]), "+f"(c[1]), "+f"(c[2]), "+f"(c[3])
        : "r"(a[0]), "r"(a[1]), "r"(a[2]), "r"(a[3]), "r"(b[0]), "r"(b[1]));
}
// D = A*B + 0   (starts a fresh accumulation without zeroing registers)
__device__ __forceinline__ void mma_bf16_z(float* c, const uint32_t* a, const uint32_t* b) {
    asm volatile(
        "mma.sync.aligned.m16n8k16.row.col.f32.bf16.bf16.f32 "
        "{%0,%1,%2,%3}, {%4,%5,%6,%7}, {%8,%9}, {%10,%11,%12,%13};"
        : "=f"(c[0]), "=f"(c[1]), "=f"(c[2]), "=f"(c[3])
        : "r"(a[0]), "r"(a[1]), "r"(a[2]), "r"(a[3]), "r"(b[0]), "r"(b[1]),
          "f"(0.f), "f"(0.f), "f"(0.f), "f"(0.f));
}
__device__ __forceinline__ void cp16(uint32_t dst, const void* src) {
    asm volatile("{ .reg .u64 g; cvta.to.global.u64 g, %1; "
                 "cp.async.cg.shared.global [%0], [g], 16; }"
                 :: "r"(dst), "l"(src) : "memory");
}
#define CP_COMMIT() asm volatile("cp.async.commit_group;" ::: "memory")
#define CP_WAIT0()  asm volatile("cp.async.wait_group 0;" ::: "memory")
#define CP_WAIT1()  asm volatile("cp.async.wait_group 1;" ::: "memory")

__device__ __forceinline__ uint32_t fold_off(int row, int g) {
    return (uint32_t)((row >> 1) * 128 + (row & 1) * 64 + ((g ^ ((row >> 1) & 3)) << 4));
}
__device__ __forceinline__ unsigned sortf(float m) {
    unsigned b = __float_as_uint(m);
    return b ^ (unsigned)(((int)b >> 31) | 0x80000000);
}
// 3-op top-2 update (b1 <= b2 invariant)
__device__ __forceinline__ void upd2u(unsigned& b1, unsigned& b2, unsigned c) {
    unsigned hi = umax(c, b1);
    b1 = umin(c, b1);
    b2 = umin(b2, hi);
}

// ---------------- k_init ----------------
__global__ void k_init(int K) {
    int i = blockIdx.x * blockDim.x + threadIdx.x;
    if (i < K) g_counts[i] = 0.f;
    if (i < 4) g_acc[i] = 0.f;
}

// ---------------- k_prep_e ----------------
__global__ void k_prep_e(const float4* __restrict__ e4, int K) {
    int w    = (blockIdx.x * blockDim.x + threadIdx.x) >> 5;
    int lane = threadIdx.x & 31;
    if (w >= K) return;
    const float4* er = e4 + (size_t)w * 64;
    float4 a = er[2 * lane], b = er[2 * lane + 1];
    float f[8] = {a.x, a.y, a.z, a.w, b.x, b.y, b.z, b.w};
    float s = 0.f;
#pragma unroll
    for (int j = 0; j < 8; j++) s += f[j] * f[j];
#pragma unroll
    for (int off = 16; off > 0; off >>= 1) s += __shfl_xor_sync(0xffffffffu, s, off);

    unsigned h[8], l[8];
#pragma unroll
    for (int j = 0; j < 8; j++) {
        __nv_bfloat16 hb = __float2bfloat16(f[j]);
        float hf = __bfloat162float(hb);
        h[j] = __bfloat16_as_ushort(hb);
        l[j] = __bfloat16_as_ushort(__float2bfloat16(f[j] - hf));
    }
    g_ehi[w * 32 + lane] = make_uint4(h[0] | (h[1] << 16), h[2] | (h[3] << 16),
                                      h[4] | (h[5] << 16), h[6] | (h[7] << 16));
    g_elo[w * 32 + lane] = make_uint4(l[0] | (l[1] << 16), l[2] | (l[3] << 16),
                                      l[4] | (l[5] << 16), l[6] | (l[7] << 16));
    if (lane == 0) {
        g_esq[w]  = s;
        g_esqh[w] = 0.5f * s;
        float rn = sqrtf(s);
        g_rninv[w] = 1.0f / fmaxf(rn, 1e-12f);
        atomicAdd(&g_acc[2], rn);
    }
}

// ---------------- k_prep_x ----------------
__global__ void k_prep_x(const float4* __restrict__ x4, int N) {
    int w    = (blockIdx.x * blockDim.x + threadIdx.x) >> 5;
    int lane = threadIdx.x & 31;
    if (w >= N) return;
    const float4* xr = x4 + (size_t)w * 64;
    float4 a = xr[2 * lane], b = xr[2 * lane + 1];
    float f[8] = {a.x, a.y, a.z, a.w, b.x, b.y, b.z, b.w};
    float s = 0.f;
#pragma unroll
    for (int j = 0; j < 8; j++) s += f[j] * f[j];
#pragma unroll
    for (int off = 16; off > 0; off >>= 1) s += __shfl_xor_sync(0xffffffffu, s, off);
    unsigned h[8];
#pragma unroll
    for (int j = 0; j < 8; j++) h[j] = __bfloat16_as_ushort(__float2bfloat16(f[j]));
    g_xhi[w * 32 + lane] = make_uint4(h[0] | (h[1] << 16), h[2] | (h[3] << 16),
                                      h[4] | (h[5] << 16), h[6] | (h[7] << 16));
    if (lane == 0) g_xsq[w] = s;
}

// ================= k_argmin =================
#define STG64    32768
#define S64_B    16384
#define OFF_AUX2 98304
#define SMEM_ARG (98304 + 2048)

struct Frag2 {
    int aoff[4], akey[4], boff[2], bkey[2];
    int asub, bsub;
};
__device__ __forceinline__ void frag_init2(Frag2& f, int lane, int wm, int wn) {
    f.asub = lane >> 4;
    f.bsub = (lane >> 3) & 1;
#pragma unroll
    for (int ma = 0; ma < 4; ma++) {
        int row = wm * 64 + ma * 16 + ((lane >> 3) & 1) * 8 + (lane & 7);
        f.aoff[ma] = row * 128;
        f.akey[ma] = row & 7;
    }
#pragma unroll
    for (int pr = 0; pr < 2; pr++) {
        int row = wn * 32 + pr * 16 + ((lane >> 4) & 1) * 8 + (lane & 7);
        f.boff[pr] = S64_B + row * 128;
        f.bkey[pr] = row & 7;
    }
}

// one 128x128x64 chunk; FIRST: ks==0 starts a fresh accumulation (D = A*B + 0)
template <bool FIRST>
__device__ __forceinline__ void chunk_compute64(uint32_t sb, const Frag2& f,
                                                float acc[4][4][4]) {
#pragma unroll
    for (int ks = 0; ks < 4; ks++) {
        int ga = ks * 2 + f.asub;
        int gb = ks * 2 + f.bsub;
        uint32_t ah[4][4], bh[4][2];
#pragma unroll
        for (int ma = 0; ma < 4; ma++)
            ldsm_x4(ah[ma][0], ah[ma][1], ah[ma][2], ah[ma][3],
                    sb + f.aoff[ma] + (((ga ^ f.akey[ma]) & 7) << 4));
#pragma unroll
        for (int pr = 0; pr < 2; pr++) {
            uint32_t d0, d1, d2, d3;
            ldsm_x4(d0, d1, d2, d3,
                    sb + f.boff[pr] + (((gb ^ f.bkey[pr]) & 7) << 4));
            bh[2*pr][0] = d0; bh[2*pr][1] = d1;
            bh[2*pr+1][0] = d2; bh[2*pr+1][1] = d3;
        }
        if (FIRST && ks == 0) {
#pragma unroll
            for (int ma = 0; ma < 4; ma++)
#pragma unroll
                for (int na = 0; na < 4; na++)
                    mma_bf16_z(acc[ma][na], ah[ma], bh[na]);
        } else {
#pragma unroll
            for (int ma = 0; ma < 4; ma++)
#pragma unroll
                for (int na = 0; na < 4; na++)
                    mma_bf16(acc[ma][na], ah[ma], bh[na]);
        }
    }
}

__global__ void __launch_bounds__(256, 2)
k_argmin_b1(int N, int K) {
    extern __shared__ char dsm[];
    uint32_t smb = smem_u32(dsm);
    int tid  = threadIdx.x;
    int lane = tid & 31;
    int wid  = tid >> 5;
    int wm   = wid >> 2;
    int wn   = wid & 3;
    int m0   = blockIdx.x * 128;

    Frag2 f; frag_init2(f, lane, wm, wn);

    uint32_t lso[4];
    int      lgo[4];
#pragma unroll
    for (int r = 0; r < 4; r++) {
        int id  = tid + r * 256;
        int row = id >> 3, g = id & 7;
        lso[r] = (uint32_t)(row * 128 + ((g ^ (row & 7)) << 4));
        lgo[r] = row * 32 + g;
    }

    unsigned tb1[8], tb2[8];
#pragma unroll
    for (int i = 0; i < 8; i++) { tb1[i] = 0xFFFFFFFFu; tb2[i] = 0xFFFFFFFFu; }

    int NT = K / 128;
    int C  = NT * 4;
    int am0 = m0 * 32;

#pragma unroll
    for (int p = 0; p < 2; p++) {
        uint32_t sb = smb + p * STG64;
        int ab = am0 + p * 8;
        int bb = p * 8;
#pragma unroll
        for (int r = 0; r < 4; r++) {
            cp16(sb + lso[r],         g_xhi + ab + lgo[r]);
            cp16(sb + S64_B + lso[r], g_ehi + bb + lgo[r]);
        }
        CP_COMMIT();
    }

    float acc[4][4][4];   // written by mma_bf16_z on each n-tile's first slice

#pragma unroll 1
    for (int c = 0; c < C; c++) {
        int nt = c >> 2, dc = c & 3;
        uint32_t sb = smb + (c % 3) * STG64;

        CP_WAIT1();
        __syncthreads();

        if (c + 2 < C) {
            int c2 = c + 2;
            int nt2 = c2 >> 2, dc2 = c2 & 3;
            uint32_t sb2 = smb + (c2 % 3) * STG64;
            int ab = am0 + dc2 * 8;
            int bb = nt2 * 4096 + dc2 * 8;
#pragma unroll
            for (int r = 0; r < 4; r++) {
                cp16(sb2 + lso[r],         g_xhi + ab + lgo[r]);
                cp16(sb2 + S64_B + lso[r], g_ehi + bb + lgo[r]);
            }
            CP_COMMIT();
        } else {
            CP_COMMIT();
        }

        if (dc == 0) chunk_compute64<true >(sb, f, acc);
        else         chunk_compute64<false>(sb, f, acc);

        if (dc == 3) {
            // m-form epilogue: minimize m = esq/2 - dot
            int base = nt * 128 + wn * 32 + 2 * (lane & 3);
            unsigned nt8 = (unsigned)(nt << 3);
#pragma unroll
            for (int na = 0; na < 4; na++) {
                int n0c = base + na * 8;
                float he0 = g_esqh[n0c], he1 = g_esqh[n0c + 1];
                unsigned id0 = nt8 + 2 * na;
                unsigned id1 = id0 + 1;
#pragma unroll
                for (int ma = 0; ma < 4; ma++) {
                    unsigned p00 = (sortf(he0 - acc[ma][na][0]) & 0xFFFFFF80u) | id0;
                    unsigned p01 = (sortf(he1 - acc[ma][na][1]) & 0xFFFFFF80u) | id1;
                    unsigned p10 = (sortf(he0 - acc[ma][na][2]) & 0xFFFFFF80u) | id0;
                    unsigned p11 = (sortf(he1 - acc[ma][na][3]) & 0xFFFFFF80u) | id1;
                    upd2u(tb1[ma * 2],     tb2[ma * 2],     p00);
                    upd2u(tb1[ma * 2],     tb2[ma * 2],     p01);
                    upd2u(tb1[ma * 2 + 1], tb2[ma * 2 + 1], p10);
                    upd2u(tb1[ma * 2 + 1], tb2[ma * 2 + 1], p11);
                }
            }
        }
    }

    // decode thread-local candidates -> u64 (sortable_m | global idx)
    unsigned nbase = (unsigned)(wn * 32 + 2 * (lane & 3));
    ull c1[8], c2[8];
#pragma unroll
    for (int i = 0; i < 8; i++) {
        unsigned ida = tb1[i] & 127u;
        unsigned idb = tb2[i] & 127u;
        unsigned ga = ((ida >> 3) << 7) + nbase + (((ida >> 1) & 3u) << 3) + (ida & 1u);
        unsigned gb = ((idb >> 3) << 7) + nbase + (((idb >> 1) & 3u) << 3) + (idb & 1u);
        c1[i] = ((ull)(tb1[i] & 0xFFFFFF80u) << 32) | ga;
        c2[i] = ((ull)(tb2[i] & 0xFFFFFF80u) << 32) | gb;
    }

    // global top-4 merge
    ull* best = reinterpret_cast<ull*>(dsm + OFF_AUX2);
    ull wlast[8];
#pragma unroll
    for (int i = 0; i < 8; i++) wlast[i] = 0ULL;

#pragma unroll 1
    for (int r = 0; r < 4; r++) {
        __syncthreads();
        if (tid < 128) best[tid] = UMAX64;
        __syncthreads();
#pragma unroll
        for (int i = 0; i < 8; i++) {
            int ma = i >> 1;
            int mloc = wm * 64 + ma * 16 + (lane >> 2) + (i & 1) * 8;
            ull cand = (c1[i] > wlast[i]) ? c1[i]
                     : ((c2[i] > wlast[i]) ? c2[i] : UMAX64);
            if (cand != UMAX64) atomicMin(&best[mloc], cand);
        }
        __syncthreads();
#pragma unroll
        for (int i = 0; i < 8; i++) {
            int ma = i >> 1;
            int mloc = wm * 64 + ma * 16 + (lane >> 2) + (i & 1) * 8;
            wlast[i] = best[mloc];
        }
        if (tid < 128) g_cand[r * MAXN + m0 + tid] = (int)(best[tid] & 0xFFFFFFFFu);
    }
}

// ---------------- k_finalize ----------------
__global__ void __launch_bounds__(256)
k_finalize(const float* __restrict__ x, const float* __restrict__ e,
           float* __restrict__ outq, float* __restrict__ outidx, int N) {
    __shared__ float smse[8];
    int wg   = threadIdx.x >> 5;
    int lane = threadIdx.x & 31;
    int w    = blockIdx.x * 8 + wg;

    int cc[4];
#pragma unroll
    for (int r = 0; r < 4; r++) cc[r] = g_cand[r * MAXN + w];

    const float4* xr = reinterpret_cast<const float4*>(x + (size_t)w * D);
    float4 a = xr[lane], b = xr[32 + lane];
    float4 u[4], v[4];
    float d[4];
#pragma unroll
    for (int r = 0; r < 4; r++) {
        const float4* er = reinterpret_cast<const float4*>(e + (size_t)cc[r] * D);
        u[r] = er[lane]; v[r] = er[32 + lane];
        d[r] = a.x*u[r].x + a.y*u[r].y + a.z*u[r].z + a.w*u[r].w
             + b.x*v[r].x + b.y*v[r].y + b.z*v[r].z + b.w*v[r].w;
    }
#pragma unroll
    for (int off = 16; off > 0; off >>= 1) {
#pragma unroll
        for (int r = 0; r < 4; r++) d[r] += __shfl_xor_sync(0xffffffffu, d[r], off);
    }

    float xq = g_xsq[w];
    ull bestc = UMAX64;
    int rwin = 0;
#pragma unroll
    for (int r = 0; r < 4; r++) {
        float dist = __fsub_rn(__fadd_rn(xq, g_esq[cc[r]]), 2.0f * d[r]);
        ull c = ((ull)__float_as_uint(dist) << 32) | (unsigned)cc[r];
        if (c < bestc) { bestc = c; rwin = r; }
    }
    int kwin = (int)(bestc & 0xFFFFFFFFu);

    float4 uw = u[0], vw = v[0];
    if (rwin == 1) { uw = u[1]; vw = v[1]; }
    if (rwin == 2) { uw = u[2]; vw = v[2]; }
    if (rwin == 3) { uw = u[3]; vw = v[3]; }
    float4* qr = reinterpret_cast<float4*>(outq + (size_t)w * D);
    qr[lane] = uw;
    qr[32 + lane] = vw;

    if (lane == 0) {
        outidx[w] = (float)kwin;
        atomicAdd(&g_counts[kwin], 1.0f);
        smse[wg] = __uint_as_float((unsigned)(bestc >> 32));
    }
    __syncthreads();
    if (threadIdx.x == 0) {
        float s = 0.f;
#pragma unroll
        for (int i = 0; i < 8; i++) s += smse[i];
        atomicAdd(&g_acc[0], s);
    }
}

// ================= k_sim (bf16x3, proven) =================
#define STG_SZ   32768
#define S_AHI    0
#define S_ALO    8192
#define S_BHI    16384
#define S_BLO    24576
#define OFF_AUX  65536
#define SMEM_SIM (65536 + 2048)

struct Frag {
    int aoff[4], akey[4], boff[2], bkey[2];
    int asub, bsub;
};
__device__ __forceinline__ void frag_init(Frag& f, int lane, int wm, int wn) {
    f.asub = lane >> 4;
    f.bsub = (lane >> 3) & 1;
#pragma unroll
    for (int ma = 0; ma < 4; ma++) {
        int row = wm * 64 + ma * 16 + ((lane >> 3) & 1) * 8 + (lane & 7);
        f.aoff[ma] = (row >> 1) * 128 + (row & 1) * 64;
        f.akey[ma] = (row >> 1) & 3;
    }
#pragma unroll
    for (int pr = 0; pr < 2; pr++) {
        int row = wn * 32 + pr * 16 + ((lane >> 4) & 1) * 8 + (lane & 7);
        f.boff[pr] = (row >> 1) * 128 + (row & 1) * 64;
        f.bkey[pr] = (row >> 1) & 3;
    }
}

__device__ __forceinline__ void stage_load_sim(uint32_t sb,
                                               int abase_g, int bbase_g, int tid) {
#pragma unroll
    for (int rep = 0; rep < 2; rep++) {
        int id  = tid + rep * 256;
        int row = id >> 2, g = id & 3;
        uint32_t so = fold_off(row, g);
        int fa = abase_g + row * 32 + g;
        int fb = bbase_g + row * 32 + g;
        cp16(sb + S_AHI + so, g_ehi + fa);
        cp16(sb + S_ALO + so, g_elo + fa);
        cp16(sb + S_BHI + so, g_ehi + fb);
        cp16(sb + S_BLO + so, g_elo + fb);
    }
}

__device__ __forceinline__ void chunk_compute_sim(uint32_t sb, const Frag& f,
                                                  float acc[4][4][4]) {
#pragma unroll
    for (int ks = 0; ks < 2; ks++) {
        int ga = ks * 2 + f.asub;
        int gb = ks * 2 + f.bsub;
        uint32_t ah[4][4], al[4][4], bh[4][2], bl[4][2];
#pragma unroll
        for (int ma = 0; ma < 4; ma++)
            ldsm_x4(ah[ma][0], ah[ma][1], ah[ma][2], ah[ma][3],
                    sb + S_AHI + f.aoff[ma] + (((ga ^ f.akey[ma]) & 3) << 4));
#pragma unroll
        for (int pr = 0; pr < 2; pr++) {
            uint32_t d0, d1, d2, d3;
            ldsm_x4(d0, d1, d2, d3,
                    sb + S_BHI + f.boff[pr] + (((gb ^ f.bkey[pr]) & 3) << 4));
            bh[2*pr][0] = d0; bh[2*pr][1] = d1;
            bh[2*pr+1][0] = d2; bh[2*pr+1][1] = d3;
        }
#pragma unroll
        for (int ma = 0; ma < 4; ma++)
#pragma unroll
            for (int na = 0; na < 4; na++)
                mma_bf16(acc[ma][na], ah[ma], bh[na]);
#pragma unroll
        for (int pr = 0; pr < 2; pr++) {
            uint32_t d0, d1, d2, d3;
            ldsm_x4(d0, d1, d2, d3,
                    sb + S_BLO + f.boff[pr] + (((gb ^ f.bkey[pr]) & 3) << 4));
            bl[2*pr][0] = d0; bl[2*pr][1] = d1;
            bl[2*pr+1][0] = d2; bl[2*pr+1][1] = d3;
        }
#pragma unroll
        for (int ma = 0; ma < 4; ma++)
#pragma unroll
            for (int na = 0; na < 4; na++)
                mma_bf16(acc[ma][na], ah[ma], bl[na]);
#pragma unroll
        for (int ma = 0; ma < 4; ma++)
            ldsm_x4(al[ma][0], al[ma][1], al[ma][2], al[ma][3],
                    sb + S_ALO + f.aoff[ma] + (((ga ^ f.akey[ma]) & 3) << 4));
#pragma unroll
        for (int ma = 0; ma < 4; ma++)
#pragma unroll
            for (int na = 0; na < 4; na++)
                mma_bf16(acc[ma][na], al[ma], bh[na]);
    }
}

__global__ void __launch_bounds__(256, 2)
k_sim_mma(int K) {
    extern __shared__ char dsm[];
    uint32_t smb = smem_u32(dsm);
    int tid  = threadIdx.x;
    int lane = tid & 31;
    int wid  = tid >> 5;
    int wm   = wid >> 2;
    int wn   = wid & 3;

    int nt_blocks = K / 128;
    int b = blockIdx.x, by = 0;
    while (b >= nt_blocks - by) { b -= nt_blocks - by; by++; }
    int bx = by + b;
    int m0 = by * 128, n0 = bx * 128;
    float wgt = (by == bx) ? 1.0f : 2.0f;

    Frag f; frag_init(f, lane, wm, wn);

    float acc[4][4][4];
#pragma unroll
    for (int ma = 0; ma < 4; ma++)
#pragma unroll
        for (int na = 0; na < 4; na++)
#pragma unroll
            for (int c = 0; c < 4; c++) acc[ma][na][c] = 0.f;

    stage_load_sim(smb, m0 * 32, n0 * 32, tid);
    CP_COMMIT();

#pragma unroll 1
    for (int dc = 0; dc < 8; dc++) {
        uint32_t sb = smb + (dc & 1) * STG_SZ;
        CP_WAIT0();
        __syncthreads();
        if (dc + 1 < 8) {
            stage_load_sim(smb + ((dc + 1) & 1) * STG_SZ,
                           m0 * 32 + (dc + 1) * 4, n0 * 32 + (dc + 1) * 4, tid);
            CP_COMMIT();
        } else {
            CP_COMMIT();
        }
        chunk_compute_sim(sb, f, acc);
    }

    float s = 0.f;
#pragma unroll
    for (int ma = 0; ma < 4; ma++) {
        int m_r0 = m0 + wm * 64 + ma * 16 + (lane >> 2);
        float r0 = g_rninv[m_r0], r1 = g_rninv[m_r0 + 8];
#pragma unroll
        for (int na = 0; na < 4; na++) {
            int n0c = n0 + wn * 32 + na * 8 + 2 * (lane & 3);
            float q0 = g_rninv[n0c], q1 = g_rninv[n0c + 1];
            float s00 = fabsf(acc[ma][na][0] * r0 * q0);
            float s01 = fabsf(acc[ma][na][1] * r0 * q1);
            float s10 = fabsf(acc[ma][na][2] * r1 * q0);
            float s11 = fabsf(acc[ma][na][3] * r1 * q1);
            if (m_r0     == n0c)     s00 = 0.f;
            if (m_r0     == n0c + 1) s01 = 0.f;
            if (m_r0 + 8 == n0c)     s10 = 0.f;
            if (m_r0 + 8 == n0c + 1) s11 = 0.f;
            s += (s00 + s01) + (s10 + s11);
        }
    }
    s *= wgt;

    float* red = reinterpret_cast<float*>(dsm + OFF_AUX);
    __syncthreads();
    red[tid] = s; __syncthreads();
    for (int st = 128; st > 0; st >>= 1) { if (tid < st) red[tid] += red[tid + st]; __syncthreads(); }
    if (tid == 0) atomicAdd(&g_acc[1], red[0]);
}

// ---------------- k_final ----------------
__global__ void k_final(float* __restrict__ out_loss, float* __restrict__ out_perp, int N, int K) {
    __shared__ float sA[256], sB[256], sC[256];
    int tid = threadIdx.x;

    float tot = 0.f;
    for (int k = tid; k < K; k += 256) tot += g_counts[k];
    sA[tid] = tot; __syncthreads();
    for (int st = 128; st > 0; st >>= 1) { if (tid < st) sA[tid] += sA[tid + st]; __syncthreads(); }
    float total = sA[0];
    __syncthreads();

    float tuni = 1.0f / (float)K;
    float kl = 0.f, pl = 0.f;
    for (int k = tid; k < K; k += 256) {
        float p = g_counts[k] / total;
        kl += (p + EPS_F) * logf((p + EPS_F) / (tuni + EPS_F));
        if (p > 0.f) pl += p * logf(p);
    }
    sB[tid] = kl; sC[tid] = pl; __syncthreads();
    for (int st = 128; st > 0; st >>= 1) {
        if (tid < st) { sB[tid] += sB[tid + st]; sC[tid] += sC[tid + st]; }
        __syncthreads();
    }
    if (tid == 0) {
        float klv = fminf(sB[0], 100.0f);
        float mse = g_acc[0] / ((float)N * (float)D);
        float vq  = mse + COMMIT_COST * mse;
        float l2  = fminf(g_acc[2] / (float)K, 10.0f);
        float orth = fminf(g_acc[1] / ((float)K * (float)K), 10.0f);
        float reg = l2 + orth;
        float loss = fminf(vq + DIV_GAMMA * klv + 0.01f * reg, 100.0f);
        *out_loss = loss;
        *out_perp = expf(-sC[0]);
    }
}

// ---------------- launch ----------------
extern "C" void kernel_launch(void* const* d_in, const int* in_sizes, int n_in,
                              void* d_out, int out_size) {
    const float* x = (const float*)d_in[0];
    const float* e = (const float*)d_in[1];
    float* out = (float*)d_out;

    int N = in_sizes[0] / D;   // 65536
    int K = in_sizes[1] / D;   // 2048
    if (N > MAXN) N = MAXN;
    if (K > MAXK) K = MAXK;

    float* out_q    = out;
    float* out_loss = out + (size_t)N * D;
    float* out_perp = out_loss + 1;
    float* out_idx  = out_perp + 1;

    cudaFuncSetAttribute(k_argmin_b1, cudaFuncAttributeMaxDynamicSharedMemorySize, SMEM_ARG);
    cudaFuncSetAttribute(k_sim_mma,   cudaFuncAttributeMaxDynamicSharedMemorySize, SMEM_SIM);

    int ntb = K / 128;
    int tri = ntb * (ntb + 1) / 2;

    k_init     <<<(K + 255) / 256, 256>>>(K);
    k_prep_e   <<<(K + 7) / 8, 256>>>((const float4*)e, K);
    k_prep_x   <<<(N + 7) / 8, 256>>>((const float4*)x, N);
    k_argmin_b1<<<N / 128, 256, SMEM_ARG>>>(N, K);
    k_finalize <<<N / 8, 256>>>(x, e, out_q, out_idx, N);
    k_sim_mma  <<<tri, 256, SMEM_SIM>>>(K);
    k_final    <<<1, 256>>>(out_loss, out_perp, N, K);
}

// round 17
// speedup vs baseline: 5.0381x; 1.0619x over previous
#include <cuda_runtime.h>
#include <cuda_bf16.h>
#include <cstdint>

#define D    256
#define MAXK 2048
#define MAXN 65536

#define COMMIT_COST 0.25f
#define DIV_GAMMA   0.1f
#define EPS_F       1e-8f

typedef unsigned long long ull;
#define UMAX64 0xFFFFFFFFFFFFFFFFULL

// ---------------- device scratch ----------------
__device__ float g_esq[MAXK];
__device__ float g_esqhB[MAXK];    // 0.5*esq + 16 (positive-bias m-form filter key)
__device__ float g_rninv[MAXK];
__device__ float g_xsq[MAXN];
__device__ int   g_cand[4 * MAXN];
__device__ float g_counts[MAXK];
__device__ float g_acc[4];

// bf16 splits (16B granules of 8 bf16). x: hi only. e: hi + lo (lo for k_sim).
__device__ uint4 g_xhi[MAXN * D / 8];
__device__ uint4 g_ehi[MAXK * D / 8];
__device__ uint4 g_elo[MAXK * D / 8];

// ---------------- helpers ----------------
__device__ __forceinline__ uint32_t smem_u32(const void* p) {
    uint32_t a;
    asm("{ .reg .u64 t; cvta.to.shared.u64 t, %1; cvt.u32.u64 %0, t; }" : "=r"(a) : "l"(p));
    return a;
}
__device__ __forceinline__ void ldsm_x4(uint32_t& d0, uint32_t& d1, uint32_t& d2, uint32_t& d3,
                                        uint32_t addr) {
    asm volatile("ldmatrix.sync.aligned.m8n8.x4.shared.b16 {%0,%1,%2,%3}, [%4];"
        : "=r"(d0), "=r"(d1), "=r"(d2), "=r"(d3) : "r"(addr));
}
__device__ __forceinline__ void mma_bf16(float* c, const uint32_t* a, const uint32_t* b) {
    asm volatile(
        "mma.sync.aligned.m16n8k16.row.col.f32.bf16.bf16.f32 "
        "{%0,%1,%2,%3}, {%4,%5,%6,%7}, {%8,%9}, {%0,%1,%2,%3};"
        : "+f"(c[0]), "+f"(c[1]), "+f"(c[2]), "+f"(c[3])
        : "r"(a[0]), "r"(a[1]), "r"(a[2]), "r"(a[3]), "r"(b[0]), "r"(b[1]));
}
__device__ __forceinline__ void mma_bf16_z(float* c, const uint32_t* a, const uint32_t* b) {
    asm volatile(
        "mma.sync.aligned.m16n8k16.row.col.f32.bf16.bf16.f32 "
        "{%0,%1,%2,%3}, {%4,%5,%6,%7}, {%8,%9}, {%10,%11,%12,%13};"
        : "=f"(c[0]), "=f"(c[1]), "=f"(c[2]), "=f"(c[3])
        : "r"(a[0]), "r"(a[1]), "r"(a[2]), "r"(a[3]), "r"(b[0]), "r"(b[1]),
          "f"(0.f), "f"(0.f), "f"(0.f), "f"(0.f));
}
__device__ __forceinline__ void cp16(uint32_t dst, const void* src) {
    asm volatile("{ .reg .u64 g; cvta.to.global.u64 g, %1; "
                 "cp.async.cg.shared.global [%0], [g], 16; }"
                 :: "r"(dst), "l"(src) : "memory");
}
#define CP_COMMIT() asm volatile("cp.async.commit_group;" ::: "memory")
#define CP_WAIT0()  asm volatile("cp.async.wait_group 0;" ::: "memory")
#define CP_WAIT1()  asm volatile("cp.async.wait_group 1;" ::: "memory")

__device__ __forceinline__ uint32_t fold_off(int row, int g) {
    return (uint32_t)((row >> 1) * 128 + (row & 1) * 64 + ((g ^ ((row >> 1) & 3)) << 4));
}
// 3-op top-2 update (b1 <= b2 invariant)
__device__ __forceinline__ void upd2u(unsigned& b1, unsigned& b2, unsigned c) {
    unsigned hi = umax(c, b1);
    b1 = umin(c, b1);
    b2 = umin(b2, hi);
}
// positive-float filter key: bits of (heB - dot) are sort-monotone; low 7 bits carry id
__device__ __forceinline__ unsigned fkey(float heB, float dot, unsigned id) {
    return (__float_as_uint(heB - dot) & 0xFFFFFF80u) | id;
}

// ---------------- k_init ----------------
__global__ void k_init(int K) {
    int i = blockIdx.x * blockDim.x + threadIdx.x;
    if (i < K) g_counts[i] = 0.f;
    if (i < 4) g_acc[i] = 0.f;
}

// ---------------- k_prep: fused e-prep (w < K) and x-prep (w >= K) ----------------
__global__ void k_prep(const float4* __restrict__ e4, const float4* __restrict__ x4,
                       int K, int N) {
    int w    = (blockIdx.x * blockDim.x + threadIdx.x) >> 5;
    int lane = threadIdx.x & 31;
    if (w < K) {
        const float4* er = e4 + (size_t)w * 64;
        float4 a = er[2 * lane], b = er[2 * lane + 1];
        float f[8] = {a.x, a.y, a.z, a.w, b.x, b.y, b.z, b.w};
        float s = 0.f;
#pragma unroll
        for (int j = 0; j < 8; j++) s += f[j] * f[j];
#pragma unroll
        for (int off = 16; off > 0; off >>= 1) s += __shfl_xor_sync(0xffffffffu, s, off);
        unsigned h[8], l[8];
#pragma unroll
        for (int j = 0; j < 8; j++) {
            __nv_bfloat16 hb = __float2bfloat16(f[j]);
            float hf = __bfloat162float(hb);
            h[j] = __bfloat16_as_ushort(hb);
            l[j] = __bfloat16_as_ushort(__float2bfloat16(f[j] - hf));
        }
        g_ehi[w * 32 + lane] = make_uint4(h[0] | (h[1] << 16), h[2] | (h[3] << 16),
                                          h[4] | (h[5] << 16), h[6] | (h[7] << 16));
        g_elo[w * 32 + lane] = make_uint4(l[0] | (l[1] << 16), l[2] | (l[3] << 16),
                                          l[4] | (l[5] << 16), l[6] | (l[7] << 16));
        if (lane == 0) {
            g_esq[w]   = s;
            g_esqhB[w] = 0.5f * s + 16.0f;
            float rn = sqrtf(s);
            g_rninv[w] = 1.0f / fmaxf(rn, 1e-12f);
            atomicAdd(&g_acc[2], rn);
        }
    } else {
        int t = w - K;
        if (t >= N) return;
        const float4* xr = x4 + (size_t)t * 64;
        float4 a = xr[2 * lane], b = xr[2 * lane + 1];
        float f[8] = {a.x, a.y, a.z, a.w, b.x, b.y, b.z, b.w};
        float s = 0.f;
#pragma unroll
        for (int j = 0; j < 8; j++) s += f[j] * f[j];
#pragma unroll
        for (int off = 16; off > 0; off >>= 1) s += __shfl_xor_sync(0xffffffffu, s, off);
        unsigned h[8];
#pragma unroll
        for (int j = 0; j < 8; j++) h[j] = __bfloat16_as_ushort(__float2bfloat16(f[j]));
        g_xhi[t * 32 + lane] = make_uint4(h[0] | (h[1] << 16), h[2] | (h[3] << 16),
                                          h[4] | (h[5] << 16), h[6] | (h[7] << 16));
        if (lane == 0) g_xsq[t] = s;
    }
}

// ================= k_argmin =================
#define STG64    32768
#define S64_B    16384
#define OFF_AUX2 98304
#define SMEM_ARG (98304 + 2048)

struct Frag2 {
    int aoff[4], akey[4], boff[2], bkey[2];
    int asub, bsub;
};
__device__ __forceinline__ void frag_init2(Frag2& f, int lane, int wm, int wn) {
    f.asub = lane >> 4;
    f.bsub = (lane >> 3) & 1;
#pragma unroll
    for (int ma = 0; ma < 4; ma++) {
        int row = wm * 64 + ma * 16 + ((lane >> 3) & 1) * 8 + (lane & 7);
        f.aoff[ma] = row * 128;
        f.akey[ma] = row & 7;
    }
#pragma unroll
    for (int pr = 0; pr < 2; pr++) {
        int row = wn * 32 + pr * 16 + ((lane >> 4) & 1) * 8 + (lane & 7);
        f.boff[pr] = S64_B + row * 128;
        f.bkey[pr] = row & 7;
    }
}

template <bool FIRST>
__device__ __forceinline__ void chunk_compute64(uint32_t sb, const Frag2& f,
                                                float acc[4][4][4]) {
#pragma unroll
    for (int ks = 0; ks < 4; ks++) {
        int ga = ks * 2 + f.asub;
        int gb = ks * 2 + f.bsub;
        uint32_t ah[4][4], bh[4][2];
#pragma unroll
        for (int ma = 0; ma < 4; ma++)
            ldsm_x4(ah[ma][0], ah[ma][1], ah[ma][2], ah[ma][3],
                    sb + f.aoff[ma] + (((ga ^ f.akey[ma]) & 7) << 4));
#pragma unroll
        for (int pr = 0; pr < 2; pr++) {
            uint32_t d0, d1, d2, d3;
            ldsm_x4(d0, d1, d2, d3,
                    sb + f.boff[pr] + (((gb ^ f.bkey[pr]) & 7) << 4));
            bh[2*pr][0] = d0; bh[2*pr][1] = d1;
            bh[2*pr+1][0] = d2; bh[2*pr+1][1] = d3;
        }
        if (FIRST && ks == 0) {
#pragma unroll
            for (int ma = 0; ma < 4; ma++)
#pragma unroll
                for (int na = 0; na < 4; na++)
                    mma_bf16_z(acc[ma][na], ah[ma], bh[na]);
        } else {
#pragma unroll
            for (int ma = 0; ma < 4; ma++)
#pragma unroll
                for (int na = 0; na < 4; na++)
                    mma_bf16(acc[ma][na], ah[ma], bh[na]);
        }
    }
}

__global__ void __launch_bounds__(256, 2)
k_argmin_b1(int N, int K) {
    extern __shared__ char dsm[];
    uint32_t smb = smem_u32(dsm);
    int tid  = threadIdx.x;
    int lane = tid & 31;
    int wid  = tid >> 5;
    int wm   = wid >> 2;
    int wn   = wid & 3;
    int m0   = blockIdx.x * 128;

    Frag2 f; frag_init2(f, lane, wm, wn);

    uint32_t lso[4];
    int      lgo[4];
#pragma unroll
    for (int r = 0; r < 4; r++) {
        int id  = tid + r * 256;
        int row = id >> 3, g = id & 7;
        lso[r] = (uint32_t)(row * 128 + ((g ^ (row & 7)) << 4));
        lgo[r] = row * 32 + g;
    }

    unsigned tb1[8], tb2[8];
#pragma unroll
    for (int i = 0; i < 8; i++) { tb1[i] = 0xFFFFFFFFu; tb2[i] = 0xFFFFFFFFu; }

    int NT = K / 128;
    int C  = NT * 4;
    int am0 = m0 * 32;

#pragma unroll
    for (int p = 0; p < 2; p++) {
        uint32_t sb = smb + p * STG64;
        int ab = am0 + p * 8;
        int bb = p * 8;
#pragma unroll
        for (int r = 0; r < 4; r++) {
            cp16(sb + lso[r],         g_xhi + ab + lgo[r]);
            cp16(sb + S64_B + lso[r], g_ehi + bb + lgo[r]);
        }
        CP_COMMIT();
    }

    float acc[4][4][4];

#pragma unroll 1
    for (int c = 0; c < C; c++) {
        int nt = c >> 2, dc = c & 3;
        uint32_t sb = smb + (c % 3) * STG64;

        CP_WAIT1();
        __syncthreads();

        if (c + 2 < C) {
            int c2 = c + 2;
            int nt2 = c2 >> 2, dc2 = c2 & 3;
            uint32_t sb2 = smb + (c2 % 3) * STG64;
            int ab = am0 + dc2 * 8;
            int bb = nt2 * 4096 + dc2 * 8;
#pragma unroll
            for (int r = 0; r < 4; r++) {
                cp16(sb2 + lso[r],         g_xhi + ab + lgo[r]);
                cp16(sb2 + S64_B + lso[r], g_ehi + bb + lgo[r]);
            }
            CP_COMMIT();
        } else {
            CP_COMMIT();
        }

        if (dc == 0) chunk_compute64<true >(sb, f, acc);
        else         chunk_compute64<false>(sb, f, acc);

        if (dc == 3) {
            // positive-bias m-form epilogue: key bits of (esqh + 16 - dot)
            int base = nt * 128 + wn * 32 + 2 * (lane & 3);
            unsigned nt8 = (unsigned)(nt << 3);
#pragma unroll
            for (int na = 0; na < 4; na++) {
                int n0c = base + na * 8;
                float he0 = g_esqhB[n0c], he1 = g_esqhB[n0c + 1];
                unsigned id0 = nt8 + 2 * na;
                unsigned id1 = id0 + 1;
#pragma unroll
                for (int ma = 0; ma < 4; ma++) {
                    upd2u(tb1[ma * 2],     tb2[ma * 2],     fkey(he0, acc[ma][na][0], id0));
                    upd2u(tb1[ma * 2],     tb2[ma * 2],     fkey(he1, acc[ma][na][1], id1));
                    upd2u(tb1[ma * 2 + 1], tb2[ma * 2 + 1], fkey(he0, acc[ma][na][2], id0));
                    upd2u(tb1[ma * 2 + 1], tb2[ma * 2 + 1], fkey(he1, acc[ma][na][3], id1));
                }
            }
        }
    }

    // decode thread-local candidates -> u64 (key | global idx)
    unsigned nbase = (unsigned)(wn * 32 + 2 * (lane & 3));
    ull c1[8], c2[8];
#pragma unroll
    for (int i = 0; i < 8; i++) {
        unsigned ida = tb1[i] & 127u;
        unsigned idb = tb2[i] & 127u;
        unsigned ga = ((ida >> 3) << 7) + nbase + (((ida >> 1) & 3u) << 3) + (ida & 1u);
        unsigned gb = ((idb >> 3) << 7) + nbase + (((idb >> 1) & 3u) << 3) + (idb & 1u);
        c1[i] = ((ull)(tb1[i] & 0xFFFFFF80u) << 32) | ga;
        c2[i] = ((ull)(tb2[i] & 0xFFFFFF80u) << 32) | gb;
    }

    // global top-4 merge
    ull* best = reinterpret_cast<ull*>(dsm + OFF_AUX2);
    ull wlast[8];
#pragma unroll
    for (int i = 0; i < 8; i++) wlast[i] = 0ULL;

#pragma unroll 1
    for (int r = 0; r < 4; r++) {
        __syncthreads();
        if (tid < 128) best[tid] = UMAX64;
        __syncthreads();
#pragma unroll
        for (int i = 0; i < 8; i++) {
            int ma = i >> 1;
            int mloc = wm * 64 + ma * 16 + (lane >> 2) + (i & 1) * 8;
            ull cand = (c1[i] > wlast[i]) ? c1[i]
                     : ((c2[i] > wlast[i]) ? c2[i] : UMAX64);
            if (cand != UMAX64) atomicMin(&best[mloc], cand);
        }
        __syncthreads();
#pragma unroll
        for (int i = 0; i < 8; i++) {
            int ma = i >> 1;
            int mloc = wm * 64 + ma * 16 + (lane >> 2) + (i & 1) * 8;
            wlast[i] = best[mloc];
        }
        if (tid < 128) g_cand[r * MAXN + m0 + tid] = (int)(best[tid] & 0xFFFFFFFFu);
    }
}

// ---------------- k_finalize ----------------
__global__ void __launch_bounds__(256)
k_finalize(const float* __restrict__ x, const float* __restrict__ e,
           float* __restrict__ outq, float* __restrict__ outidx, int N) {
    __shared__ float smse[8];
    int wg   = threadIdx.x >> 5;
    int lane = threadIdx.x & 31;
    int w    = blockIdx.x * 8 + wg;

    int cc[4];
#pragma unroll
    for (int r = 0; r < 4; r++) cc[r] = g_cand[r * MAXN + w];

    const float4* xr = reinterpret_cast<const float4*>(x + (size_t)w * D);
    float4 a = xr[lane], b = xr[32 + lane];
    float4 u[4], v[4];
    float d[4];
#pragma unroll
    for (int r = 0; r < 4; r++) {
        const float4* er = reinterpret_cast<const float4*>(e + (size_t)cc[r] * D);
        u[r] = er[lane]; v[r] = er[32 + lane];
        d[r] = a.x*u[r].x + a.y*u[r].y + a.z*u[r].z + a.w*u[r].w
             + b.x*v[r].x + b.y*v[r].y + b.z*v[r].z + b.w*v[r].w;
    }
#pragma unroll
    for (int off = 16; off > 0; off >>= 1) {
#pragma unroll
        for (int r = 0; r < 4; r++) d[r] += __shfl_xor_sync(0xffffffffu, d[r], off);
    }

    float xq = g_xsq[w];
    ull bestc = UMAX64;
    int rwin = 0;
#pragma unroll
    for (int r = 0; r < 4; r++) {
        float dist = __fsub_rn(__fadd_rn(xq, g_esq[cc[r]]), 2.0f * d[r]);
        ull c = ((ull)__float_as_uint(dist) << 32) | (unsigned)cc[r];
        if (c < bestc) { bestc = c; rwin = r; }
    }
    int kwin = (int)(bestc & 0xFFFFFFFFu);

    float4 uw = u[0], vw = v[0];
    if (rwin == 1) { uw = u[1]; vw = v[1]; }
    if (rwin == 2) { uw = u[2]; vw = v[2]; }
    if (rwin == 3) { uw = u[3]; vw = v[3]; }
    float4* qr = reinterpret_cast<float4*>(outq + (size_t)w * D);
    qr[lane] = uw;
    qr[32 + lane] = vw;

    if (lane == 0) {
        outidx[w] = (float)kwin;
        atomicAdd(&g_counts[kwin], 1.0f);
        smse[wg] = __uint_as_float((unsigned)(bestc >> 32));
    }
    __syncthreads();
    if (threadIdx.x == 0) {
        float s = 0.f;
#pragma unroll
        for (int i = 0; i < 8; i++) s += smse[i];
        atomicAdd(&g_acc[0], s);
    }
}

// ================= k_sim (bf16x3, proven) =================
#define STG_SZ   32768
#define S_AHI    0
#define S_ALO    8192
#define S_BHI    16384
#define S_BLO    24576
#define OFF_AUX  65536
#define SMEM_SIM (65536 + 2048)

struct Frag {
    int aoff[4], akey[4], boff[2], bkey[2];
    int asub, bsub;
};
__device__ __forceinline__ void frag_init(Frag& f, int lane, int wm, int wn) {
    f.asub = lane >> 4;
    f.bsub = (lane >> 3) & 1;
#pragma unroll
    for (int ma = 0; ma < 4; ma++) {
        int row = wm * 64 + ma * 16 + ((lane >> 3) & 1) * 8 + (lane & 7);
        f.aoff[ma] = (row >> 1) * 128 + (row & 1) * 64;
        f.akey[ma] = (row >> 1) & 3;
    }
#pragma unroll
    for (int pr = 0; pr < 2; pr++) {
        int row = wn * 32 + pr * 16 + ((lane >> 4) & 1) * 8 + (lane & 7);
        f.boff[pr] = (row >> 1) * 128 + (row & 1) * 64;
        f.bkey[pr] = (row >> 1) & 3;
    }
}

__device__ __forceinline__ void stage_load_sim(uint32_t sb,
                                               int abase_g, int bbase_g, int tid) {
#pragma unroll
    for (int rep = 0; rep < 2; rep++) {
        int id  = tid + rep * 256;
        int row = id >> 2, g = id & 3;
        uint32_t so = fold_off(row, g);
        int fa = abase_g + row * 32 + g;
        int fb = bbase_g + row * 32 + g;
        cp16(sb + S_AHI + so, g_ehi + fa);
        cp16(sb + S_ALO + so, g_elo + fa);
        cp16(sb + S_BHI + so, g_ehi + fb);
        cp16(sb + S_BLO + so, g_elo + fb);
    }
}

__device__ __forceinline__ void chunk_compute_sim(uint32_t sb, const Frag& f,
                                                  float acc[4][4][4]) {
#pragma unroll
    for (int ks = 0; ks < 2; ks++) {
        int ga = ks * 2 + f.asub;
        int gb = ks * 2 + f.bsub;
        uint32_t ah[4][4], al[4][4], bh[4][2], bl[4][2];
#pragma unroll
        for (int ma = 0; ma < 4; ma++)
            ldsm_x4(ah[ma][0], ah[ma][1], ah[ma][2], ah[ma][3],
                    sb + S_AHI + f.aoff[ma] + (((ga ^ f.akey[ma]) & 3) << 4));
#pragma unroll
        for (int pr = 0; pr < 2; pr++) {
            uint32_t d0, d1, d2, d3;
            ldsm_x4(d0, d1, d2, d3,
                    sb + S_BHI + f.boff[pr] + (((gb ^ f.bkey[pr]) & 3) << 4));
            bh[2*pr][0] = d0; bh[2*pr][1] = d1;
            bh[2*pr+1][0] = d2; bh[2*pr+1][1] = d3;
        }
#pragma unroll
        for (int ma = 0; ma < 4; ma++)
#pragma unroll
            for (int na = 0; na < 4; na++)
                mma_bf16(acc[ma][na], ah[ma], bh[na]);
#pragma unroll
        for (int pr = 0; pr < 2; pr++) {
            uint32_t d0, d1, d2, d3;
            ldsm_x4(d0, d1, d2, d3,
                    sb + S_BLO + f.boff[pr] + (((gb ^ f.bkey[pr]) & 3) << 4));
            bl[2*pr][0] = d0; bl[2*pr][1] = d1;
            bl[2*pr+1][0] = d2; bl[2*pr+1][1] = d3;
        }
#pragma unroll
        for (int ma = 0; ma < 4; ma++)
#pragma unroll
            for (int na = 0; na < 4; na++)
                mma_bf16(acc[ma][na], ah[ma], bl[na]);
#pragma unroll
        for (int ma = 0; ma < 4; ma++)
            ldsm_x4(al[ma][0], al[ma][1], al[ma][2], al[ma][3],
                    sb + S_ALO + f.aoff[ma] + (((ga ^ f.akey[ma]) & 3) << 4));
#pragma unroll
        for (int ma = 0; ma < 4; ma++)
#pragma unroll
            for (int na = 0; na < 4; na++)
                mma_bf16(acc[ma][na], al[ma], bh[na]);
    }
}

__global__ void __launch_bounds__(256, 2)
k_sim_mma(int K) {
    extern __shared__ char dsm[];
    uint32_t smb = smem_u32(dsm);
    int tid  = threadIdx.x;
    int lane = tid & 31;
    int wid  = tid >> 5;
    int wm   = wid >> 2;
    int wn   = wid & 3;

    int nt_blocks = K / 128;
    int b = blockIdx.x, by = 0;
    while (b >= nt_blocks - by) { b -= nt_blocks - by; by++; }
    int bx = by + b;
    int m0 = by * 128, n0 = bx * 128;
    float wgt = (by == bx) ? 1.0f : 2.0f;

    Frag f; frag_init(f, lane, wm, wn);

    float acc[4][4][4];
#pragma unroll
    for (int ma = 0; ma < 4; ma++)
#pragma unroll
        for (int na = 0; na < 4; na++)
#pragma unroll
            for (int c = 0; c < 4; c++) acc[ma][na][c] = 0.f;

    stage_load_sim(smb, m0 * 32, n0 * 32, tid);
    CP_COMMIT();

#pragma unroll 1
    for (int dc = 0; dc < 8; dc++) {
        uint32_t sb = smb + (dc & 1) * STG_SZ;
        CP_WAIT0();
        __syncthreads();
        if (dc + 1 < 8) {
            stage_load_sim(smb + ((dc + 1) & 1) * STG_SZ,
                           m0 * 32 + (dc + 1) * 4, n0 * 32 + (dc + 1) * 4, tid);
            CP_COMMIT();
        } else {
            CP_COMMIT();
        }
        chunk_compute_sim(sb, f, acc);
    }

    float s = 0.f;
#pragma unroll
    for (int ma = 0; ma < 4; ma++) {
        int m_r0 = m0 + wm * 64 + ma * 16 + (lane >> 2);
        float r0 = g_rninv[m_r0], r1 = g_rninv[m_r0 + 8];
#pragma unroll
        for (int na = 0; na < 4; na++) {
            int n0c = n0 + wn * 32 + na * 8 + 2 * (lane & 3);
            float q0 = g_rninv[n0c], q1 = g_rninv[n0c + 1];
            float s00 = fabsf(acc[ma][na][0] * r0 * q0);
            float s01 = fabsf(acc[ma][na][1] * r0 * q1);
            float s10 = fabsf(acc[ma][na][2] * r1 * q0);
            float s11 = fabsf(acc[ma][na][3] * r1 * q1);
            if (m_r0     == n0c)     s00 = 0.f;
            if (m_r0     == n0c + 1) s01 = 0.f;
            if (m_r0 + 8 == n0c)     s10 = 0.f;
            if (m_r0 + 8 == n0c + 1) s11 = 0.f;
            s += (s00 + s01) + (s10 + s11);
        }
    }
    s *= wgt;

    float* red = reinterpret_cast<float*>(dsm + OFF_AUX);
    __syncthreads();
    red[tid] = s; __syncthreads();
    for (int st = 128; st > 0; st >>= 1) { if (tid < st) red[tid] += red[tid + st]; __syncthreads(); }
    if (tid == 0) atomicAdd(&g_acc[1], red[0]);
}

// ---------------- k_final ----------------
__global__ void k_final(float* __restrict__ out_loss, float* __restrict__ out_perp, int N, int K) {
    __shared__ float sA[256], sB[256], sC[256];
    int tid = threadIdx.x;

    float tot = 0.f;
    for (int k = tid; k < K; k += 256) tot += g_counts[k];
    sA[tid] = tot; __syncthreads();
    for (int st = 128; st > 0; st >>= 1) { if (tid < st) sA[tid] += sA[tid + st]; __syncthreads(); }
    float total = sA[0];
    __syncthreads();

    float tuni = 1.0f / (float)K;
    float kl = 0.f, pl = 0.f;
    for (int k = tid; k < K; k += 256) {
        float p = g_counts[k] / total;
        kl += (p + EPS_F) * logf((p + EPS_F) / (tuni + EPS_F));
        if (p > 0.f) pl += p * logf(p);
    }
    sB[tid] = kl; sC[tid] = pl; __syncthreads();
    for (int st = 128; st > 0; st >>= 1) {
        if (tid < st) { sB[tid] += sB[tid + st]; sC[tid] += sC[tid + st]; }
        __syncthreads();
    }
    if (tid == 0) {
        float klv = fminf(sB[0], 100.0f);
        float mse = g_acc[0] / ((float)N * (float)D);
        float vq  = mse + COMMIT_COST * mse;
        float l2  = fminf(g_acc[2] / (float)K, 10.0f);
        float orth = fminf(g_acc[1] / ((float)K * (float)K), 10.0f);
        float reg = l2 + orth;
        float loss = fminf(vq + DIV_GAMMA * klv + 0.01f * reg, 100.0f);
        *out_loss = loss;
        *out_perp = expf(-sC[0]);
    }
}

// ---------------- launch ----------------
extern "C" void kernel_launch(void* const* d_in, const int* in_sizes, int n_in,
                              void* d_out, int out_size) {
    const float* x = (const float*)d_in[0];
    const float* e = (const float*)d_in[1];
    float* out = (float*)d_out;

    int N = in_sizes[0] / D;   // 65536
    int K = in_sizes[1] / D;   // 2048
    if (N > MAXN) N = MAXN;
    if (K > MAXK) K = MAXK;

    float* out_q    = out;
    float* out_loss = out + (size_t)N * D;
    float* out_perp = out_loss + 1;
    float* out_idx  = out_perp + 1;

    cudaFuncSetAttribute(k_argmin_b1, cudaFuncAttributeMaxDynamicSharedMemorySize, SMEM_ARG);
    cudaFuncSetAttribute(k_sim_mma,   cudaFuncAttributeMaxDynamicSharedMemorySize, SMEM_SIM);

    int ntb = K / 128;
    int tri = ntb * (ntb + 1) / 2;
    int prep_warps = K + N;

    k_init     <<<(K + 255) / 256, 256>>>(K);
    k_prep     <<<(prep_warps + 7) / 8, 256>>>((const float4*)e, (const float4*)x, K, N);
    k_argmin_b1<<<N / 128, 256, SMEM_ARG>>>(N, K);
    k_finalize <<<N / 8, 256>>>(x, e, out_q, out_idx, N);
    k_sim_mma  <<<tri, 256, SMEM_SIM>>>(K);
    k_final    <<<1, 256>>>(out_loss, out_perp, N, K);
}